// round 2
// baseline (speedup 1.0000x reference)
#include <cuda_runtime.h>
#include <cstdint>

#define B_   2
#define T_   4096
#define D_   2048
#define H_   16
#define HD_  128
#define CH_  256
#define NCH_ 16
#define BT_  (B_*T_)
#define SCALE_ 0.08838834764831845f

__device__ float g_q[(size_t)BT_*D_];
__device__ float g_k[(size_t)BT_*D_];
__device__ float g_v[(size_t)BT_*D_];
__device__ float g_g[(size_t)BT_*D_];
__device__ float g_o[(size_t)BT_*D_];
__device__ float g_gt[B_*H_*T_];
__device__ float g_gc[B_*H_*T_];
__device__ float g_sinbuf [(size_t)B_*H_*NCH_*HD_*HD_];
__device__ float g_sprebuf[(size_t)B_*H_*NCH_*HD_*HD_];

__device__ __forceinline__ float log_sigmoidf(float z) {
    return (z >= 0.f) ? -log1pf(expf(-z)) : (z - log1pf(expf(z)));
}

// ---------- fp32 SGEMM: C[M,N] = A[M,K] @ B[K,N]; 128x128 tile, BK=16 ----------
__global__ __launch_bounds__(256) void sgemm_kernel(
    const float* __restrict__ A, const float* __restrict__ Bm, float* __restrict__ C,
    int M, int N, int K)
{
    __shared__ __align__(16) float As[16][128];
    __shared__ __align__(16) float Bs[16][128];
    int tid  = threadIdx.x;
    int trow = tid >> 4, tcol = tid & 15;
    int m0 = blockIdx.y * 128, n0 = blockIdx.x * 128;

    float acc[8][8];
#pragma unroll
    for (int i = 0; i < 8; i++)
#pragma unroll
        for (int j = 0; j < 8; j++) acc[i][j] = 0.f;

    for (int k0 = 0; k0 < K; k0 += 16) {
#pragma unroll
        for (int i = 0; i < 2; i++) {
            int li = tid + i * 256;
            int m = li >> 2, kq = (li & 3) << 2;
            float4 va = *(const float4*)&A[(size_t)(m0 + m) * K + k0 + kq];
            As[kq + 0][m] = va.x; As[kq + 1][m] = va.y;
            As[kq + 2][m] = va.z; As[kq + 3][m] = va.w;
        }
#pragma unroll
        for (int i = 0; i < 2; i++) {
            int li = tid + i * 256;
            int r = li >> 5, c4 = (li & 31) << 2;
            *(float4*)&Bs[r][c4] = *(const float4*)&Bm[(size_t)(k0 + r) * N + n0 + c4];
        }
        __syncthreads();
#pragma unroll
        for (int kk = 0; kk < 16; kk++) {
            float4 a0 = *(float4*)&As[kk][trow * 8];
            float4 a1 = *(float4*)&As[kk][trow * 8 + 4];
            float4 b0 = *(float4*)&Bs[kk][tcol * 8];
            float4 b1 = *(float4*)&Bs[kk][tcol * 8 + 4];
            float a[8] = {a0.x, a0.y, a0.z, a0.w, a1.x, a1.y, a1.z, a1.w};
            float b[8] = {b0.x, b0.y, b0.z, b0.w, b1.x, b1.y, b1.z, b1.w};
#pragma unroll
            for (int i = 0; i < 8; i++)
#pragma unroll
                for (int j = 0; j < 8; j++) acc[i][j] += a[i] * b[j];
        }
        __syncthreads();
    }
#pragma unroll
    for (int i = 0; i < 8; i++) {
        size_t ci = (size_t)(m0 + trow * 8 + i) * N + n0 + tcol * 8;
        *(float4*)&C[ci]     = make_float4(acc[i][0], acc[i][1], acc[i][2], acc[i][3]);
        *(float4*)&C[ci + 4] = make_float4(acc[i][4], acc[i][5], acc[i][6], acc[i][7]);
    }
}

// ---------- gt = log_sigmoid(x @ Wgt)/GLN, stored [B,H,T] ----------
__global__ __launch_bounds__(128) void gt_kernel(
    const float* __restrict__ x, const float* __restrict__ Wgt, float* __restrict__ gt)
{
    int row = blockIdx.x;
    int tid = threadIdx.x;
    const float* xr = x + (size_t)row * D_;
    float acc[16];
#pragma unroll
    for (int h = 0; h < 16; h++) acc[h] = 0.f;
    for (int kk = tid; kk < D_; kk += 128) {
        float xv = xr[kk];
        const float4* w4 = (const float4*)(Wgt + (size_t)kk * 16);
        float4 w0 = w4[0], w1 = w4[1], w2 = w4[2], w3 = w4[3];
        acc[0]  += xv * w0.x; acc[1]  += xv * w0.y; acc[2]  += xv * w0.z; acc[3]  += xv * w0.w;
        acc[4]  += xv * w1.x; acc[5]  += xv * w1.y; acc[6]  += xv * w1.z; acc[7]  += xv * w1.w;
        acc[8]  += xv * w2.x; acc[9]  += xv * w2.y; acc[10] += xv * w2.z; acc[11] += xv * w2.w;
        acc[12] += xv * w3.x; acc[13] += xv * w3.y; acc[14] += xv * w3.z; acc[15] += xv * w3.w;
    }
#pragma unroll
    for (int h = 0; h < 16; h++)
#pragma unroll
        for (int off = 16; off > 0; off >>= 1)
            acc[h] += __shfl_down_sync(0xffffffffu, acc[h], off);
    __shared__ float part[4][16];
    int warp = tid >> 5, lane = tid & 31;
    if (lane == 0)
#pragma unroll
        for (int h = 0; h < 16; h++) part[warp][h] = acc[h];
    __syncthreads();
    if (tid < 16) {
        float s = part[0][tid] + part[1][tid] + part[2][tid] + part[3][tid];
        int b = row >> 12, t = row & 4095;
        gt[((size_t)(b * H_ + tid)) * T_ + t] = log_sigmoidf(s) * (1.f / 16.f);
    }
}

// ---------- per-chunk inclusive cumsum of gt -> gc ----------
__global__ __launch_bounds__(256) void cumsum_kernel(
    const float* __restrict__ gt, float* __restrict__ gc)
{
    int bh = blockIdx.x >> 4;
    int n  = blockIdx.x & 15;
    int tid = threadIdx.x, lane = tid & 31, warp = tid >> 5;
    size_t idx = (size_t)bh * T_ + n * CH_ + tid;
    float v = gt[idx];
#pragma unroll
    for (int off = 1; off < 32; off <<= 1) {
        float y = __shfl_up_sync(0xffffffffu, v, off);
        if (lane >= off) v += y;
    }
    __shared__ float ws[8];
    if (lane == 31) ws[warp] = v;
    __syncthreads();
    if (tid == 0) {
        float s = 0.f;
#pragma unroll
        for (int w = 0; w < 8; w++) { float t = ws[w]; ws[w] = s; s += t; }
    }
    __syncthreads();
    gc[idx] = v + ws[warp];
}

// ---------- interleaved RoPE on q,k in-place ----------
__global__ __launch_bounds__(256) void rope_kernel(
    float* __restrict__ q, float* __restrict__ k,
    const float* __restrict__ cb, const float* __restrict__ sb)
{
    int p = blockIdx.x * 256 + threadIdx.x;
    int i = p & 63;
    int h = (p >> 6) & 15;
    int t = (p >> 10) & 4095;
    int b = p >> 22;
    float c = cb[t * 64 + i], s = sb[t * 64 + i];
    size_t base = ((size_t)(b * T_ + t)) * D_ + h * HD_ + 2 * i;
    float2 qv = *(float2*)&q[base];
    float2 kv = *(float2*)&k[base];
    float2 qo, ko;
    qo.x = qv.x * c - qv.y * s;  qo.y = qv.x * s + qv.y * c;
    ko.x = kv.x * c - kv.y * s;  ko.y = kv.x * s + kv.y * c;
    *(float2*)&q[base] = qo;
    *(float2*)&k[base] = ko;
}

// ---------- S_in[b,h,n] = (k*kdec*scale)^T @ v  (128x128, K=256) ----------
__global__ __launch_bounds__(256) void sin_kernel(
    const float* __restrict__ k, const float* __restrict__ v,
    const float* __restrict__ gc, float* __restrict__ Sin)
{
    __shared__ __align__(16) float Ks[32 * 128];
    __shared__ __align__(16) float Vs[32 * 128];
    __shared__ float kd[32];
    int blk = blockIdx.x;                        // b*256 + h*16 + n
    int n = blk & 15, h = (blk >> 4) & 15, b = blk >> 8;
    int tid = threadIdx.x;
    int trow = tid >> 4, tcol = tid & 15;
    const float* gcc = gc + ((size_t)(b * H_ + h)) * T_ + n * CH_;
    float gtot = gcc[CH_ - 1];

    float acc[8][8];
#pragma unroll
    for (int i = 0; i < 8; i++)
#pragma unroll
        for (int j = 0; j < 8; j++) acc[i][j] = 0.f;

    for (int s0 = 0; s0 < CH_; s0 += 32) {
        __syncthreads();
        if (tid < 32) kd[tid] = expf(gtot - gcc[s0 + tid]) * SCALE_;
        __syncthreads();
#pragma unroll
        for (int l = 0; l < 4; l++) {
            int li = tid + l * 256;
            int c = li >> 5, gcol = (li & 31) << 2;
            size_t gi = ((size_t)(b * T_ + n * CH_ + s0 + c)) * D_ + h * HD_ + gcol;
            float4 kv4 = *(const float4*)&k[gi];
            float sc = kd[c];
            kv4.x *= sc; kv4.y *= sc; kv4.z *= sc; kv4.w *= sc;
            *(float4*)&Ks[c * 128 + gcol] = kv4;
            *(float4*)&Vs[c * 128 + gcol] = *(const float4*)&v[gi];
        }
        __syncthreads();
#pragma unroll
        for (int c = 0; c < 32; c++) {
            float4 a0 = *(float4*)&Ks[c * 128 + trow * 8];
            float4 a1 = *(float4*)&Ks[c * 128 + trow * 8 + 4];
            float4 b0 = *(float4*)&Vs[c * 128 + tcol * 8];
            float4 b1 = *(float4*)&Vs[c * 128 + tcol * 8 + 4];
            float a[8] = {a0.x, a0.y, a0.z, a0.w, a1.x, a1.y, a1.z, a1.w};
            float bb[8] = {b0.x, b0.y, b0.z, b0.w, b1.x, b1.y, b1.z, b1.w};
#pragma unroll
            for (int i = 0; i < 8; i++)
#pragma unroll
                for (int j = 0; j < 8; j++) acc[i][j] += a[i] * bb[j];
        }
    }
    size_t base = (size_t)blk * (HD_ * HD_);
#pragma unroll
    for (int i = 0; i < 8; i++) {
        size_t oi = base + (size_t)(trow * 8 + i) * HD_ + tcol * 8;
        *(float4*)&Sin[oi]     = make_float4(acc[i][0], acc[i][1], acc[i][2], acc[i][3]);
        *(float4*)&Sin[oi + 4] = make_float4(acc[i][4], acc[i][5], acc[i][6], acc[i][7]);
    }
}

// ---------- serial state scan over chunks: Spre[n] = S; S = S*cd + Sin[n] ----------
__global__ __launch_bounds__(256) void scan_kernel(
    const float* __restrict__ Sin, const float* __restrict__ gc, float* __restrict__ Spre)
{
    int bh = blockIdx.x;
    float S[64];
#pragma unroll
    for (int l = 0; l < 64; l++) S[l] = 0.f;
    for (int n = 0; n < NCH_; n++) {
        float cd = expf(gc[(size_t)bh * T_ + n * CH_ + (CH_ - 1)]);
        size_t base = ((size_t)(bh * NCH_ + n)) * (HD_ * HD_);
#pragma unroll
        for (int l = 0; l < 64; l++) {
            int idx = threadIdx.x + l * 256;
            Spre[base + idx] = S[l];
            S[l] = S[l] * cd + Sin[base + idx];
        }
    }
}

// ---------- fused: scores+decay, o_inner, o_cross, RMSNorm, SiLU gate ----------
#define QS_OFF  0
#define BS_OFF  8192
#define SS_OFF  16384
#define GQ_OFF  20736
#define GK_OFF  20800
#define RED_OFF 20864
#define SMF_TOT 21888

__global__ __launch_bounds__(256) void out_kernel(
    const float* __restrict__ q, const float* __restrict__ k,
    const float* __restrict__ v, const float* __restrict__ g,
    const float* __restrict__ gc, const float* __restrict__ Spre,
    float* __restrict__ o)
{
    extern __shared__ __align__(16) float sm[];
    float* Qs  = sm + QS_OFF;
    float* Bs  = sm + BS_OFF;
    float* Ss  = sm + SS_OFF;
    float* gq  = sm + GQ_OFF;
    float* gk  = sm + GK_OFF;
    float* red = sm + RED_OFF;

    int blk = blockIdx.x;
    int rt = blk & 3, n = (blk >> 2) & 15, h = (blk >> 6) & 15, b = blk >> 10;
    int tid = threadIdx.x, trow = tid >> 4, tcol = tid & 15;
    int trow4 = trow * 4;
    const float* gcc = gc + ((size_t)(b * H_ + h)) * T_ + n * CH_;
    int c0 = rt * 64;
    int rowbase = b * T_ + n * CH_;

#pragma unroll
    for (int l = 0; l < 8; l++) {
        int li = tid + l * 256;
        int c = li >> 5, gcol = (li & 31) << 2;
        size_t gi = ((size_t)(rowbase + c0 + c)) * D_ + h * HD_ + gcol;
        *(float4*)&Qs[c * 128 + gcol] = *(const float4*)&q[gi];
    }
    if (tid < 64) gq[tid] = gcc[c0 + tid];

    float oacc[4][8];
#pragma unroll
    for (int i = 0; i < 4; i++)
#pragma unroll
        for (int j = 0; j < 8; j++) oacc[i][j] = 0.f;
    __syncthreads();

    for (int st = 0; st <= rt; st++) {
        int s0 = st * 64;
#pragma unroll
        for (int l = 0; l < 8; l++) {
            int li = tid + l * 256;
            int c = li >> 5, gr = li & 31;
            size_t gi = ((size_t)(rowbase + s0 + c)) * D_ + h * HD_ + (gr << 2);
            *(float4*)&Bs[c * 128 + ((gr ^ (c & 7)) << 2)] = *(const float4*)&k[gi];
        }
        if (tid < 64) gk[tid] = gcc[s0 + tid];
        __syncthreads();

        float sacc[4][4];
#pragma unroll
        for (int i = 0; i < 4; i++)
#pragma unroll
            for (int j = 0; j < 4; j++) sacc[i][j] = 0.f;
#pragma unroll
        for (int gr = 0; gr < 32; gr++) {
            float4 a[4];
#pragma unroll
            for (int i = 0; i < 4; i++) a[i] = *(float4*)&Qs[(trow4 + i) * 128 + (gr << 2)];
#pragma unroll
            for (int j = 0; j < 4; j++) {
                int s = tcol * 4 + j;
                float4 bb = *(float4*)&Bs[s * 128 + ((gr ^ (s & 7)) << 2)];
#pragma unroll
                for (int i = 0; i < 4; i++)
                    sacc[i][j] += a[i].x * bb.x + a[i].y * bb.y + a[i].z * bb.z + a[i].w * bb.w;
            }
        }
#pragma unroll
        for (int i = 0; i < 4; i++) {
            int r = trow4 + i;
            float gqi = gq[r];
#pragma unroll
            for (int j = 0; j < 4; j++) {
                int s = tcol * 4 + j;
                float val = 0.f;
                if (s0 + s <= c0 + r) val = sacc[i][j] * SCALE_ * expf(gqi - gk[s]);
                Ss[r * 68 + s] = val;
            }
        }
        __syncthreads();

#pragma unroll
        for (int l = 0; l < 8; l++) {
            int li = tid + l * 256;
            int c = li >> 5, gr = li & 31;
            size_t gi = ((size_t)(rowbase + s0 + c)) * D_ + h * HD_ + (gr << 2);
            *(float4*)&Bs[c * 128 + ((gr ^ (c & 7)) << 2)] = *(const float4*)&v[gi];
        }
        __syncthreads();

#pragma unroll
        for (int s = 0; s < 64; s++) {
            float4 b0 = *(float4*)&Bs[s * 128 + (((2 * tcol)     ^ (s & 7)) << 2)];
            float4 b1 = *(float4*)&Bs[s * 128 + (((2 * tcol + 1) ^ (s & 7)) << 2)];
#pragma unroll
            for (int i = 0; i < 4; i++) {
                float a = Ss[(trow4 + i) * 68 + s];
                oacc[i][0] += a * b0.x; oacc[i][1] += a * b0.y;
                oacc[i][2] += a * b0.z; oacc[i][3] += a * b0.w;
                oacc[i][4] += a * b1.x; oacc[i][5] += a * b1.y;
                oacc[i][6] += a * b1.z; oacc[i][7] += a * b1.w;
            }
        }
        __syncthreads();
    }

    // cross-chunk: oacc += (q * exp(gcum)) @ Spre
    float qd[4];
#pragma unroll
    for (int i = 0; i < 4; i++) qd[i] = expf(gq[trow4 + i]);
    size_t sbase = ((size_t)(blk >> 2)) * (HD_ * HD_);
    for (int d0 = 0; d0 < 128; d0 += 64) {
#pragma unroll
        for (int l = 0; l < 8; l++) {
            int li = tid + l * 256;
            int dd = li >> 5, gr = li & 31;
            *(float4*)&Bs[dd * 128 + ((gr ^ (dd & 7)) << 2)] =
                *(const float4*)&Spre[sbase + (size_t)(d0 + dd) * 128 + (gr << 2)];
        }
        __syncthreads();
#pragma unroll
        for (int dd = 0; dd < 64; dd++) {
            float4 b0 = *(float4*)&Bs[dd * 128 + (((2 * tcol)     ^ (dd & 7)) << 2)];
            float4 b1 = *(float4*)&Bs[dd * 128 + (((2 * tcol + 1) ^ (dd & 7)) << 2)];
#pragma unroll
            for (int i = 0; i < 4; i++) {
                float a = Qs[(trow4 + i) * 128 + d0 + dd] * qd[i];
                oacc[i][0] += a * b0.x; oacc[i][1] += a * b0.y;
                oacc[i][2] += a * b0.z; oacc[i][3] += a * b0.w;
                oacc[i][4] += a * b1.x; oacc[i][5] += a * b1.y;
                oacc[i][6] += a * b1.z; oacc[i][7] += a * b1.w;
            }
        }
        __syncthreads();
    }

#pragma unroll
    for (int i = 0; i < 4; i++) {
        float ss = 0.f;
#pragma unroll
        for (int j = 0; j < 8; j++) ss += oacc[i][j] * oacc[i][j];
        red[(trow4 + i) * 16 + tcol] = ss;
    }
    __syncthreads();
#pragma unroll
    for (int i = 0; i < 4; i++) {
        int r = trow4 + i;
        float ss = 0.f;
#pragma unroll
        for (int t2 = 0; t2 < 16; t2++) ss += red[r * 16 + t2];
        float rn = rsqrtf(ss * (1.0f / 128.0f) + 1e-5f);
        size_t gi = ((size_t)(rowbase + c0 + r)) * D_ + h * HD_ + tcol * 8;
        float4 g0 = *(const float4*)&g[gi];
        float4 g1 = *(const float4*)&g[gi + 4];
        float4 o0, o1;
        o0.x = oacc[i][0] * rn * (g0.x / (1.f + expf(-g0.x)));
        o0.y = oacc[i][1] * rn * (g0.y / (1.f + expf(-g0.y)));
        o0.z = oacc[i][2] * rn * (g0.z / (1.f + expf(-g0.z)));
        o0.w = oacc[i][3] * rn * (g0.w / (1.f + expf(-g0.w)));
        o1.x = oacc[i][4] * rn * (g1.x / (1.f + expf(-g1.x)));
        o1.y = oacc[i][5] * rn * (g1.y / (1.f + expf(-g1.y)));
        o1.z = oacc[i][6] * rn * (g1.z / (1.f + expf(-g1.z)));
        o1.w = oacc[i][7] * rn * (g1.w / (1.f + expf(-g1.w)));
        *(float4*)&o[gi]     = o0;
        *(float4*)&o[gi + 4] = o1;
    }
}

extern "C" void kernel_launch(void* const* d_in, const int* in_sizes, int n_in,
                              void* d_out, int out_size)
{
    const float* x    = (const float*)d_in[0];
    const float* cosb = (const float*)d_in[1];
    const float* sinb = (const float*)d_in[2];
    const float* Wq   = (const float*)d_in[3];
    const float* Wk   = (const float*)d_in[4];
    const float* Wv   = (const float*)d_in[5];
    const float* Wg   = (const float*)d_in[6];
    const float* Wgt  = (const float*)d_in[7];
    const float* Wout = (const float*)d_in[8];
    float* out = (float*)d_out;

    float *q, *k, *v, *g, *o, *gt, *gc, *sbuf, *spre;
    cudaGetSymbolAddress((void**)&q,    g_q);
    cudaGetSymbolAddress((void**)&k,    g_k);
    cudaGetSymbolAddress((void**)&v,    g_v);
    cudaGetSymbolAddress((void**)&g,    g_g);
    cudaGetSymbolAddress((void**)&o,    g_o);
    cudaGetSymbolAddress((void**)&gt,   g_gt);
    cudaGetSymbolAddress((void**)&gc,   g_gc);
    cudaGetSymbolAddress((void**)&sbuf, g_sinbuf);
    cudaGetSymbolAddress((void**)&spre, g_sprebuf);

    cudaFuncSetAttribute(out_kernel, cudaFuncAttributeMaxDynamicSharedMemorySize,
                         SMF_TOT * sizeof(float));

    dim3 ggrid(D_ / 128, BT_ / 128);
    sgemm_kernel<<<ggrid, 256>>>(x, Wq, q, BT_, D_, D_);
    sgemm_kernel<<<ggrid, 256>>>(x, Wk, k, BT_, D_, D_);
    sgemm_kernel<<<ggrid, 256>>>(x, Wv, v, BT_, D_, D_);
    sgemm_kernel<<<ggrid, 256>>>(x, Wg, g, BT_, D_, D_);
    gt_kernel<<<BT_, 128>>>(x, Wgt, gt);
    cumsum_kernel<<<B_ * H_ * NCH_, 256>>>(gt, gc);
    rope_kernel<<<(B_ * T_ * H_ * 64) / 256, 256>>>(q, k, cosb, sinb);
    sin_kernel<<<B_ * H_ * NCH_, 256>>>(k, v, gc, sbuf);
    scan_kernel<<<B_ * H_, 256>>>(sbuf, gc, spre);
    out_kernel<<<B_ * H_ * NCH_ * 4, 256, SMF_TOT * sizeof(float)>>>(q, k, v, g, gc, spre, o);
    sgemm_kernel<<<ggrid, 256>>>(o, Wout, out, BT_, D_, D_);
}

// round 4
// speedup vs baseline: 1.8607x; 1.8607x over previous
#include <cuda_runtime.h>
#include <cuda_bf16.h>
#include <cstdint>

#define B_   2
#define T_   4096
#define D_   2048
#define H_   16
#define HD_  128
#define CH_  256
#define NCH_ 16
#define BT_  (B_*T_)
#define SCALE_ 0.08838834764831845f

// ---------------- scratch ----------------
__device__ float g_q[(size_t)BT_*D_];
__device__ float g_k[(size_t)BT_*D_];
__device__ float g_v[(size_t)BT_*D_];
__device__ float g_g[(size_t)BT_*D_];
__device__ float g_o[(size_t)BT_*D_];
__device__ float g_gt[B_*H_*T_];
__device__ float g_gc[B_*H_*T_];
__device__ float g_sinbuf [(size_t)B_*H_*NCH_*HD_*HD_];
__device__ float g_sprebuf[(size_t)B_*H_*NCH_*HD_*HD_];
__device__ __nv_bfloat16 g_xhi[(size_t)BT_*D_];
__device__ __nv_bfloat16 g_xlo[(size_t)BT_*D_];
__device__ __nv_bfloat16 g_ohi[(size_t)BT_*D_];
__device__ __nv_bfloat16 g_olo[(size_t)BT_*D_];
__device__ __nv_bfloat16 g_wthi[5*(size_t)D_*D_];   // W^T [N,K]: q,k,v,g,out
__device__ __nv_bfloat16 g_wtlo[5*(size_t)D_*D_];

__device__ __forceinline__ float log_sigmoidf(float z) {
    return (z >= 0.f) ? -log1pf(expf(-z)) : (z - log1pf(expf(z)));
}

// ============================= MMA helpers (Ampere ISA, legal at compute_100) ==========
__device__ __forceinline__ uint32_t smem_u32(const void* p) {
    uint32_t a;
    asm("{ .reg .u64 t; cvta.to.shared.u64 t, %1; cvt.u32.u64 %0, t; }" : "=r"(a) : "l"(p));
    return a;
}
__device__ __forceinline__ void cp_async16(uint32_t s, const void* g) {
    asm volatile("cp.async.cg.shared.global [%0], [%1], 16;" :: "r"(s), "l"(g));
}
__device__ __forceinline__ void cp_commit() { asm volatile("cp.async.commit_group;"); }
template<int N> __device__ __forceinline__ void cp_wait() {
    asm volatile("cp.async.wait_group %0;" :: "n"(N));
}
__device__ __forceinline__ void ldmat4(uint32_t* r, uint32_t a) {
    asm volatile("ldmatrix.sync.aligned.m8n8.x4.shared.b16 {%0,%1,%2,%3}, [%4];"
        : "=r"(r[0]), "=r"(r[1]), "=r"(r[2]), "=r"(r[3]) : "r"(a));
}
__device__ __forceinline__ void mma_bf16(float* d, const uint32_t* a, uint32_t b0, uint32_t b1) {
    asm volatile(
        "mma.sync.aligned.m16n8k16.row.col.f32.bf16.bf16.f32 "
        "{%0,%1,%2,%3}, {%4,%5,%6,%7}, {%8,%9}, {%0,%1,%2,%3};"
        : "+f"(d[0]), "+f"(d[1]), "+f"(d[2]), "+f"(d[3])
        : "r"(a[0]), "r"(a[1]), "r"(a[2]), "r"(a[3]), "r"(b0), "r"(b1));
}

// ============================= tensor-core GEMM =============================
// C[M,2048] = (Ahi+Alo)[M,2048] @ (Bhi+Blo)^T, B operands [N,K] row-major.
// 128x128 CTA tile, BK=32, 8 warps (2x4), warp tile 64x32, cp.async double buffer.
#define LDS_ROW 40                      // bf16 per smem row (80 B, conflict-free ldmatrix)
#define STAGE_A (128 * LDS_ROW * 2)     // 10240 B
#define STAGE_T (2 * STAGE_A)           // A + B per stage

__global__ void __launch_bounds__(256) tc_gemm(
    const __nv_bfloat16* __restrict__ Ahi, const __nv_bfloat16* __restrict__ Alo,
    const __nv_bfloat16* __restrict__ Bhi, const __nv_bfloat16* __restrict__ Blo,
    float* __restrict__ C)
{
    __shared__ __align__(16) char smem[2 * STAGE_T];     // 40960 B
    const uint32_t smb = smem_u32(smem);

    int tid = threadIdx.x, lane = tid & 31, wid = tid >> 5;
    int wm = wid >> 2, wn = wid & 3;                     // 2 x 4 warp grid
    int m0 = blockIdx.y * 128, n0 = blockIdx.x * 128;

    // global load mapping: 512 16B-vectors per operand per chunk, 2 per thread
    int gr0 = tid >> 2;                                  // row 0..63 (li=tid)
    int gc0 = (tid & 3) << 3;                            // bf16 col 0,8,16,24
    // ldmatrix smem offsets (bytes, within stage)
    uint32_t aoff[4];
#pragma unroll
    for (int mt = 0; mt < 4; mt++)
        aoff[mt] = (uint32_t)(((wm * 64 + mt * 16 + (lane & 15)) * LDS_ROW + ((lane >> 4) << 3)) * 2);
    uint32_t boff[2];
    {
        int q = lane >> 3, r = lane & 7;
#pragma unroll
        for (int np = 0; np < 2; np++) {
            int n = wn * 32 + np * 16 + ((q >> 1) << 3) + r;
            int kc = (q & 1) << 3;
            boff[np] = (uint32_t)((n * LDS_ROW + kc) * 2);
        }
    }

    float acc[4][4][4];
#pragma unroll
    for (int i = 0; i < 4; i++)
#pragma unroll
        for (int j = 0; j < 4; j++)
#pragma unroll
            for (int e = 0; e < 4; e++) acc[i][j][e] = 0.f;

    const int NCHUNK = 192;                              // 3 passes x 64
    // prefetch chunk 0
    {
        const __nv_bfloat16* As = Ahi;
        const __nv_bfloat16* Bs = Bhi;
        uint32_t sA = smb, sB = smb + STAGE_A;
#pragma unroll
        for (int l = 0; l < 2; l++) {
            int row = gr0 + l * 64;
            uint32_t so = (uint32_t)(row * (LDS_ROW * 2) + gc0 * 2);
            cp_async16(sA + so, As + (size_t)(m0 + row) * D_ + gc0);
            cp_async16(sB + so, Bs + (size_t)(n0 + row) * D_ + gc0);
        }
        cp_commit();
    }

    for (int c = 0; c < NCHUNK; c++) {
        if (c + 1 < NCHUNK) {
            int cn = c + 1;
            int pass = cn >> 6;
            int kk = (cn & 63) << 5;
            const __nv_bfloat16* As = (pass == 1) ? Alo : Ahi;
            const __nv_bfloat16* Bs = (pass == 2) ? Blo : Bhi;
            uint32_t st = smb + (cn & 1) * STAGE_T;
#pragma unroll
            for (int l = 0; l < 2; l++) {
                int row = gr0 + l * 64;
                uint32_t so = (uint32_t)(row * (LDS_ROW * 2) + gc0 * 2);
                cp_async16(st + so,           As + (size_t)(m0 + row) * D_ + kk + gc0);
                cp_async16(st + STAGE_A + so, Bs + (size_t)(n0 + row) * D_ + kk + gc0);
            }
            cp_commit();
            cp_wait<1>();
        } else {
            cp_wait<0>();
        }
        __syncthreads();

        uint32_t sA = smb + (c & 1) * STAGE_T;
        uint32_t sB = sA + STAGE_A;
#pragma unroll
        for (int ks = 0; ks < 2; ks++) {
            uint32_t a[4][4], b[2][4];
#pragma unroll
            for (int mt = 0; mt < 4; mt++) ldmat4(a[mt], sA + aoff[mt] + ks * 32);
#pragma unroll
            for (int np = 0; np < 2; np++) ldmat4(b[np], sB + boff[np] + ks * 32);
#pragma unroll
            for (int mt = 0; mt < 4; mt++)
#pragma unroll
                for (int nt = 0; nt < 4; nt++)
                    mma_bf16(acc[mt][nt], a[mt], b[nt >> 1][(nt & 1) * 2], b[nt >> 1][(nt & 1) * 2 + 1]);
        }
        __syncthreads();
    }

    // epilogue: direct float2 stores
    int tq = lane >> 2, tr = lane & 3;
#pragma unroll
    for (int mt = 0; mt < 4; mt++) {
#pragma unroll
        for (int nt = 0; nt < 4; nt++) {
            int m = m0 + wm * 64 + mt * 16 + tq;
            int n = n0 + wn * 32 + nt * 8 + tr * 2;
            *(float2*)&C[(size_t)m * D_ + n]       = make_float2(acc[mt][nt][0], acc[mt][nt][1]);
            *(float2*)&C[(size_t)(m + 8) * D_ + n] = make_float2(acc[mt][nt][2], acc[mt][nt][3]);
        }
    }
}

// ---------------- fp32 -> bf16 hi/lo split ----------------
__global__ __launch_bounds__(256) void split_kernel(
    const float* __restrict__ a, __nv_bfloat16* __restrict__ hi, __nv_bfloat16* __restrict__ lo)
{
    size_t i = ((size_t)blockIdx.x * 256 + threadIdx.x) * 4;
    float4 v = *(const float4*)&a[i];
    __nv_bfloat16 h0 = __float2bfloat16(v.x), h1 = __float2bfloat16(v.y);
    __nv_bfloat16 h2 = __float2bfloat16(v.z), h3 = __float2bfloat16(v.w);
    __nv_bfloat16 l0 = __float2bfloat16(v.x - __bfloat162float(h0));
    __nv_bfloat16 l1 = __float2bfloat16(v.y - __bfloat162float(h1));
    __nv_bfloat16 l2 = __float2bfloat16(v.z - __bfloat162float(h2));
    __nv_bfloat16 l3 = __float2bfloat16(v.w - __bfloat162float(h3));
    __nv_bfloat162* hp = (__nv_bfloat162*)(hi + i);
    __nv_bfloat162* lp = (__nv_bfloat162*)(lo + i);
    hp[0] = __halves2bfloat162(h0, h1); hp[1] = __halves2bfloat162(h2, h3);
    lp[0] = __halves2bfloat162(l0, l1); lp[1] = __halves2bfloat162(l2, l3);
}

// ---------------- W[K,N] -> Wt_hi/lo[N,K] transpose+split ----------------
__global__ __launch_bounds__(256) void wsplit_kernel(
    const float* __restrict__ W, __nv_bfloat16* __restrict__ hi, __nv_bfloat16* __restrict__ lo)
{
    __shared__ float tile[32][33];
    int k0 = blockIdx.y * 32, n0 = blockIdx.x * 32;
    int tx = threadIdx.x & 31, ty = threadIdx.x >> 5;
#pragma unroll
    for (int i = 0; i < 32; i += 8)
        tile[ty + i][tx] = W[(size_t)(k0 + ty + i) * D_ + n0 + tx];
    __syncthreads();
#pragma unroll
    for (int i = 0; i < 32; i += 8) {
        float v = tile[tx][ty + i];
        __nv_bfloat16 h = __float2bfloat16(v);
        __nv_bfloat16 l = __float2bfloat16(v - __bfloat162float(h));
        size_t oi = (size_t)(n0 + ty + i) * D_ + k0 + tx;
        hi[oi] = h; lo[oi] = l;
    }
}

// ============================= retention (unchanged, passing) =============================
__global__ __launch_bounds__(128) void gt_kernel(
    const float* __restrict__ x, const float* __restrict__ Wgt, float* __restrict__ gt)
{
    int row = blockIdx.x;
    int tid = threadIdx.x;
    const float* xr = x + (size_t)row * D_;
    float acc[16];
#pragma unroll
    for (int h = 0; h < 16; h++) acc[h] = 0.f;
    for (int kk = tid; kk < D_; kk += 128) {
        float xv = xr[kk];
        const float4* w4 = (const float4*)(Wgt + (size_t)kk * 16);
        float4 w0 = w4[0], w1 = w4[1], w2 = w4[2], w3 = w4[3];
        acc[0]  += xv * w0.x; acc[1]  += xv * w0.y; acc[2]  += xv * w0.z; acc[3]  += xv * w0.w;
        acc[4]  += xv * w1.x; acc[5]  += xv * w1.y; acc[6]  += xv * w1.z; acc[7]  += xv * w1.w;
        acc[8]  += xv * w2.x; acc[9]  += xv * w2.y; acc[10] += xv * w2.z; acc[11] += xv * w2.w;
        acc[12] += xv * w3.x; acc[13] += xv * w3.y; acc[14] += xv * w3.z; acc[15] += xv * w3.w;
    }
#pragma unroll
    for (int h = 0; h < 16; h++)
#pragma unroll
        for (int off = 16; off > 0; off >>= 1)
            acc[h] += __shfl_down_sync(0xffffffffu, acc[h], off);
    __shared__ float part[4][16];
    int warp = tid >> 5, lane = tid & 31;
    if (lane == 0)
#pragma unroll
        for (int h = 0; h < 16; h++) part[warp][h] = acc[h];
    __syncthreads();
    if (tid < 16) {
        float s = part[0][tid] + part[1][tid] + part[2][tid] + part[3][tid];
        int b = row >> 12, t = row & 4095;
        gt[((size_t)(b * H_ + tid)) * T_ + t] = log_sigmoidf(s) * (1.f / 16.f);
    }
}

__global__ __launch_bounds__(256) void cumsum_kernel(
    const float* __restrict__ gt, float* __restrict__ gc)
{
    int bh = blockIdx.x >> 4;
    int n  = blockIdx.x & 15;
    int tid = threadIdx.x, lane = tid & 31, warp = tid >> 5;
    size_t idx = (size_t)bh * T_ + n * CH_ + tid;
    float v = gt[idx];
#pragma unroll
    for (int off = 1; off < 32; off <<= 1) {
        float y = __shfl_up_sync(0xffffffffu, v, off);
        if (lane >= off) v += y;
    }
    __shared__ float ws[8];
    if (lane == 31) ws[warp] = v;
    __syncthreads();
    if (tid == 0) {
        float s = 0.f;
#pragma unroll
        for (int w = 0; w < 8; w++) { float t = ws[w]; ws[w] = s; s += t; }
    }
    __syncthreads();
    gc[idx] = v + ws[warp];
}

__global__ __launch_bounds__(256) void rope_kernel(
    float* __restrict__ q, float* __restrict__ k,
    const float* __restrict__ cb, const float* __restrict__ sb)
{
    int p = blockIdx.x * 256 + threadIdx.x;
    int i = p & 63;
    int h = (p >> 6) & 15;
    int t = (p >> 10) & 4095;
    int b = p >> 22;
    float c = cb[t * 64 + i], s = sb[t * 64 + i];
    size_t base = ((size_t)(b * T_ + t)) * D_ + h * HD_ + 2 * i;
    float2 qv = *(float2*)&q[base];
    float2 kv = *(float2*)&k[base];
    float2 qo, ko;
    qo.x = qv.x * c - qv.y * s;  qo.y = qv.x * s + qv.y * c;
    ko.x = kv.x * c - kv.y * s;  ko.y = kv.x * s + kv.y * c;
    *(float2*)&q[base] = qo;
    *(float2*)&k[base] = ko;
}

__global__ __launch_bounds__(256) void sin_kernel(
    const float* __restrict__ k, const float* __restrict__ v,
    const float* __restrict__ gc, float* __restrict__ Sin)
{
    __shared__ __align__(16) float Ks[32 * 128];
    __shared__ __align__(16) float Vs[32 * 128];
    __shared__ float kd[32];
    int blk = blockIdx.x;
    int n = blk & 15, h = (blk >> 4) & 15, b = blk >> 8;
    int tid = threadIdx.x;
    int trow = tid >> 4, tcol = tid & 15;
    const float* gcc = gc + ((size_t)(b * H_ + h)) * T_ + n * CH_;
    float gtot = gcc[CH_ - 1];

    float acc[8][8];
#pragma unroll
    for (int i = 0; i < 8; i++)
#pragma unroll
        for (int j = 0; j < 8; j++) acc[i][j] = 0.f;

    for (int s0 = 0; s0 < CH_; s0 += 32) {
        __syncthreads();
        if (tid < 32) kd[tid] = expf(gtot - gcc[s0 + tid]) * SCALE_;
        __syncthreads();
#pragma unroll
        for (int l = 0; l < 4; l++) {
            int li = tid + l * 256;
            int c = li >> 5, gcol = (li & 31) << 2;
            size_t gi = ((size_t)(b * T_ + n * CH_ + s0 + c)) * D_ + h * HD_ + gcol;
            float4 kv4 = *(const float4*)&k[gi];
            float sc = kd[c];
            kv4.x *= sc; kv4.y *= sc; kv4.z *= sc; kv4.w *= sc;
            *(float4*)&Ks[c * 128 + gcol] = kv4;
            *(float4*)&Vs[c * 128 + gcol] = *(const float4*)&v[gi];
        }
        __syncthreads();
#pragma unroll
        for (int c = 0; c < 32; c++) {
            float4 a0 = *(float4*)&Ks[c * 128 + trow * 8];
            float4 a1 = *(float4*)&Ks[c * 128 + trow * 8 + 4];
            float4 b0 = *(float4*)&Vs[c * 128 + tcol * 8];
            float4 b1 = *(float4*)&Vs[c * 128 + tcol * 8 + 4];
            float a[8] = {a0.x, a0.y, a0.z, a0.w, a1.x, a1.y, a1.z, a1.w};
            float bb[8] = {b0.x, b0.y, b0.z, b0.w, b1.x, b1.y, b1.z, b1.w};
#pragma unroll
            for (int i = 0; i < 8; i++)
#pragma unroll
                for (int j = 0; j < 8; j++) acc[i][j] += a[i] * bb[j];
        }
    }
    size_t base = (size_t)blk * (HD_ * HD_);
#pragma unroll
    for (int i = 0; i < 8; i++) {
        size_t oi = base + (size_t)(trow * 8 + i) * HD_ + tcol * 8;
        *(float4*)&Sin[oi]     = make_float4(acc[i][0], acc[i][1], acc[i][2], acc[i][3]);
        *(float4*)&Sin[oi + 4] = make_float4(acc[i][4], acc[i][5], acc[i][6], acc[i][7]);
    }
}

__global__ __launch_bounds__(256) void scan_kernel(
    const float* __restrict__ Sin, const float* __restrict__ gc, float* __restrict__ Spre)
{
    int bh = blockIdx.x;
    float S[64];
#pragma unroll
    for (int l = 0; l < 64; l++) S[l] = 0.f;
    for (int n = 0; n < NCH_; n++) {
        float cd = expf(gc[(size_t)bh * T_ + n * CH_ + (CH_ - 1)]);
        size_t base = ((size_t)(bh * NCH_ + n)) * (HD_ * HD_);
#pragma unroll
        for (int l = 0; l < 64; l++) {
            int idx = threadIdx.x + l * 256;
            Spre[base + idx] = S[l];
            S[l] = S[l] * cd + Sin[base + idx];
        }
    }
}

#define QS_OFF  0
#define BS_OFF  8192
#define SS_OFF  16384
#define GQ_OFF  20736
#define GK_OFF  20800
#define RED_OFF 20864
#define SMF_TOT 21888

__global__ __launch_bounds__(256) void out_kernel(
    const float* __restrict__ q, const float* __restrict__ k,
    const float* __restrict__ v, const float* __restrict__ g,
    const float* __restrict__ gc, const float* __restrict__ Spre,
    float* __restrict__ o)
{
    extern __shared__ __align__(16) float sm[];
    float* Qs  = sm + QS_OFF;
    float* Bs  = sm + BS_OFF;
    float* Ss  = sm + SS_OFF;
    float* gq  = sm + GQ_OFF;
    float* gk  = sm + GK_OFF;
    float* red = sm + RED_OFF;

    int blk = blockIdx.x;
    int rt = blk & 3, n = (blk >> 2) & 15, h = (blk >> 6) & 15, b = blk >> 10;
    int tid = threadIdx.x, trow = tid >> 4, tcol = tid & 15;
    int trow4 = trow * 4;
    const float* gcc = gc + ((size_t)(b * H_ + h)) * T_ + n * CH_;
    int c0 = rt * 64;
    int rowbase = b * T_ + n * CH_;

#pragma unroll
    for (int l = 0; l < 8; l++) {
        int li = tid + l * 256;
        int c = li >> 5, gcol = (li & 31) << 2;
        size_t gi = ((size_t)(rowbase + c0 + c)) * D_ + h * HD_ + gcol;
        *(float4*)&Qs[c * 128 + gcol] = *(const float4*)&q[gi];
    }
    if (tid < 64) gq[tid] = gcc[c0 + tid];

    float oacc[4][8];
#pragma unroll
    for (int i = 0; i < 4; i++)
#pragma unroll
        for (int j = 0; j < 8; j++) oacc[i][j] = 0.f;
    __syncthreads();

    for (int st = 0; st <= rt; st++) {
        int s0 = st * 64;
#pragma unroll
        for (int l = 0; l < 8; l++) {
            int li = tid + l * 256;
            int c = li >> 5, gr = li & 31;
            size_t gi = ((size_t)(rowbase + s0 + c)) * D_ + h * HD_ + (gr << 2);
            *(float4*)&Bs[c * 128 + ((gr ^ (c & 7)) << 2)] = *(const float4*)&k[gi];
        }
        if (tid < 64) gk[tid] = gcc[s0 + tid];
        __syncthreads();

        float sacc[4][4];
#pragma unroll
        for (int i = 0; i < 4; i++)
#pragma unroll
            for (int j = 0; j < 4; j++) sacc[i][j] = 0.f;
#pragma unroll
        for (int gr = 0; gr < 32; gr++) {
            float4 a[4];
#pragma unroll
            for (int i = 0; i < 4; i++) a[i] = *(float4*)&Qs[(trow4 + i) * 128 + (gr << 2)];
#pragma unroll
            for (int j = 0; j < 4; j++) {
                int s = tcol * 4 + j;
                float4 bb = *(float4*)&Bs[s * 128 + ((gr ^ (s & 7)) << 2)];
#pragma unroll
                for (int i = 0; i < 4; i++)
                    sacc[i][j] += a[i].x * bb.x + a[i].y * bb.y + a[i].z * bb.z + a[i].w * bb.w;
            }
        }
#pragma unroll
        for (int i = 0; i < 4; i++) {
            int r = trow4 + i;
            float gqi = gq[r];
#pragma unroll
            for (int j = 0; j < 4; j++) {
                int s = tcol * 4 + j;
                float val = 0.f;
                if (s0 + s <= c0 + r) val = sacc[i][j] * SCALE_ * expf(gqi - gk[s]);
                Ss[r * 68 + s] = val;
            }
        }
        __syncthreads();

#pragma unroll
        for (int l = 0; l < 8; l++) {
            int li = tid + l * 256;
            int c = li >> 5, gr = li & 31;
            size_t gi = ((size_t)(rowbase + s0 + c)) * D_ + h * HD_ + (gr << 2);
            *(float4*)&Bs[c * 128 + ((gr ^ (c & 7)) << 2)] = *(const float4*)&v[gi];
        }
        __syncthreads();

#pragma unroll
        for (int s = 0; s < 64; s++) {
            float4 b0 = *(float4*)&Bs[s * 128 + (((2 * tcol)     ^ (s & 7)) << 2)];
            float4 b1 = *(float4*)&Bs[s * 128 + (((2 * tcol + 1) ^ (s & 7)) << 2)];
#pragma unroll
            for (int i = 0; i < 4; i++) {
                float a = Ss[(trow4 + i) * 68 + s];
                oacc[i][0] += a * b0.x; oacc[i][1] += a * b0.y;
                oacc[i][2] += a * b0.z; oacc[i][3] += a * b0.w;
                oacc[i][4] += a * b1.x; oacc[i][5] += a * b1.y;
                oacc[i][6] += a * b1.z; oacc[i][7] += a * b1.w;
            }
        }
        __syncthreads();
    }

    float qd[4];
#pragma unroll
    for (int i = 0; i < 4; i++) qd[i] = expf(gq[trow4 + i]);
    size_t sbase = ((size_t)(blk >> 2)) * (HD_ * HD_);
    for (int d0 = 0; d0 < 128; d0 += 64) {
#pragma unroll
        for (int l = 0; l < 8; l++) {
            int li = tid + l * 256;
            int dd = li >> 5, gr = li & 31;
            *(float4*)&Bs[dd * 128 + ((gr ^ (dd & 7)) << 2)] =
                *(const float4*)&Spre[sbase + (size_t)(d0 + dd) * 128 + (gr << 2)];
        }
        __syncthreads();
#pragma unroll
        for (int dd = 0; dd < 64; dd++) {
            float4 b0 = *(float4*)&Bs[dd * 128 + (((2 * tcol)     ^ (dd & 7)) << 2)];
            float4 b1 = *(float4*)&Bs[dd * 128 + (((2 * tcol + 1) ^ (dd & 7)) << 2)];
#pragma unroll
            for (int i = 0; i < 4; i++) {
                float a = Qs[(trow4 + i) * 128 + d0 + dd] * qd[i];
                oacc[i][0] += a * b0.x; oacc[i][1] += a * b0.y;
                oacc[i][2] += a * b0.z; oacc[i][3] += a * b0.w;
                oacc[i][4] += a * b1.x; oacc[i][5] += a * b1.y;
                oacc[i][6] += a * b1.z; oacc[i][7] += a * b1.w;
            }
        }
        __syncthreads();
    }

#pragma unroll
    for (int i = 0; i < 4; i++) {
        float ss = 0.f;
#pragma unroll
        for (int j = 0; j < 8; j++) ss += oacc[i][j] * oacc[i][j];
        red[(trow4 + i) * 16 + tcol] = ss;
    }
    __syncthreads();
#pragma unroll
    for (int i = 0; i < 4; i++) {
        int r = trow4 + i;
        float ss = 0.f;
#pragma unroll
        for (int t2 = 0; t2 < 16; t2++) ss += red[r * 16 + t2];
        float rn = rsqrtf(ss * (1.0f / 128.0f) + 1e-5f);
        size_t gi = ((size_t)(rowbase + c0 + r)) * D_ + h * HD_ + tcol * 8;
        float4 g0 = *(const float4*)&g[gi];
        float4 g1 = *(const float4*)&g[gi + 4];
        float4 o0, o1;
        o0.x = oacc[i][0] * rn * (g0.x / (1.f + expf(-g0.x)));
        o0.y = oacc[i][1] * rn * (g0.y / (1.f + expf(-g0.y)));
        o0.z = oacc[i][2] * rn * (g0.z / (1.f + expf(-g0.z)));
        o0.w = oacc[i][3] * rn * (g0.w / (1.f + expf(-g0.w)));
        o1.x = oacc[i][4] * rn * (g1.x / (1.f + expf(-g1.x)));
        o1.y = oacc[i][5] * rn * (g1.y / (1.f + expf(-g1.y)));
        o1.z = oacc[i][6] * rn * (g1.z / (1.f + expf(-g1.z)));
        o1.w = oacc[i][7] * rn * (g1.w / (1.f + expf(-g1.w)));
        *(float4*)&o[gi]     = o0;
        *(float4*)&o[gi + 4] = o1;
    }
}

// ============================= launcher =============================
extern "C" void kernel_launch(void* const* d_in, const int* in_sizes, int n_in,
                              void* d_out, int out_size)
{
    const float* x    = (const float*)d_in[0];
    const float* cosb = (const float*)d_in[1];
    const float* sinb = (const float*)d_in[2];
    const float* Wq   = (const float*)d_in[3];
    const float* Wk   = (const float*)d_in[4];
    const float* Wv   = (const float*)d_in[5];
    const float* Wg   = (const float*)d_in[6];
    const float* Wgt  = (const float*)d_in[7];
    const float* Wout = (const float*)d_in[8];
    float* out = (float*)d_out;

    float *q, *k, *v, *g, *o, *gt, *gc, *sbuf, *spre;
    __nv_bfloat16 *xhi, *xlo, *ohi, *olo, *wthi, *wtlo;
    cudaGetSymbolAddress((void**)&q,    g_q);
    cudaGetSymbolAddress((void**)&k,    g_k);
    cudaGetSymbolAddress((void**)&v,    g_v);
    cudaGetSymbolAddress((void**)&g,    g_g);
    cudaGetSymbolAddress((void**)&o,    g_o);
    cudaGetSymbolAddress((void**)&gt,   g_gt);
    cudaGetSymbolAddress((void**)&gc,   g_gc);
    cudaGetSymbolAddress((void**)&sbuf, g_sinbuf);
    cudaGetSymbolAddress((void**)&spre, g_sprebuf);
    cudaGetSymbolAddress((void**)&xhi,  g_xhi);
    cudaGetSymbolAddress((void**)&xlo,  g_xlo);
    cudaGetSymbolAddress((void**)&ohi,  g_ohi);
    cudaGetSymbolAddress((void**)&olo,  g_olo);
    cudaGetSymbolAddress((void**)&wthi, g_wthi);
    cudaGetSymbolAddress((void**)&wtlo, g_wtlo);

    cudaFuncSetAttribute(out_kernel, cudaFuncAttributeMaxDynamicSharedMemorySize,
                         SMF_TOT * sizeof(float));

    const size_t WSZ = (size_t)D_ * D_;
    dim3 wgrid(D_ / 32, D_ / 32);
    dim3 ggrid(D_ / 128, BT_ / 128);   // (16, 64)

    split_kernel<<<(BT_ * (D_ / 4)) / 256, 256>>>(x, xhi, xlo);
    wsplit_kernel<<<wgrid, 256>>>(Wq,   wthi + 0 * WSZ, wtlo + 0 * WSZ);
    wsplit_kernel<<<wgrid, 256>>>(Wk,   wthi + 1 * WSZ, wtlo + 1 * WSZ);
    wsplit_kernel<<<wgrid, 256>>>(Wv,   wthi + 2 * WSZ, wtlo + 2 * WSZ);
    wsplit_kernel<<<wgrid, 256>>>(Wg,   wthi + 3 * WSZ, wtlo + 3 * WSZ);
    wsplit_kernel<<<wgrid, 256>>>(Wout, wthi + 4 * WSZ, wtlo + 4 * WSZ);

    tc_gemm<<<ggrid, 256>>>(xhi, xlo, wthi + 0 * WSZ, wtlo + 0 * WSZ, q);
    tc_gemm<<<ggrid, 256>>>(xhi, xlo, wthi + 1 * WSZ, wtlo + 1 * WSZ, k);
    tc_gemm<<<ggrid, 256>>>(xhi, xlo, wthi + 2 * WSZ, wtlo + 2 * WSZ, v);
    tc_gemm<<<ggrid, 256>>>(xhi, xlo, wthi + 3 * WSZ, wtlo + 3 * WSZ, g);

    gt_kernel<<<BT_, 128>>>(x, Wgt, gt);
    cumsum_kernel<<<B_ * H_ * NCH_, 256>>>(gt, gc);
    rope_kernel<<<(B_ * T_ * H_ * 64) / 256, 256>>>(q, k, cosb, sinb);
    sin_kernel<<<B_ * H_ * NCH_, 256>>>(k, v, gc, sbuf);
    scan_kernel<<<B_ * H_, 256>>>(sbuf, gc, spre);
    out_kernel<<<B_ * H_ * NCH_ * 4, 256, SMF_TOT * sizeof(float)>>>(q, k, v, g, gc, spre, o);

    split_kernel<<<(BT_ * (D_ / 4)) / 256, 256>>>(o, ohi, olo);
    tc_gemm<<<ggrid, 256>>>(ohi, olo, wthi + 4 * WSZ, wtlo + 4 * WSZ, out);
}

// round 5
// speedup vs baseline: 2.0125x; 1.0816x over previous
#include <cuda_runtime.h>
#include <cuda_bf16.h>
#include <cstdint>

#define B_   2
#define T_   4096
#define D_   2048
#define H_   16
#define HD_  128
#define CH_  256
#define NCH_ 16
#define BT_  (B_*T_)
#define SCALE_ 0.08838834764831845f

// ---------------- scratch ----------------
__device__ float g_q[(size_t)BT_*D_];
__device__ float g_k[(size_t)BT_*D_];
__device__ float g_v[(size_t)BT_*D_];
__device__ float g_g[(size_t)BT_*D_];
__device__ float g_gt[B_*H_*T_];
__device__ float g_gc[B_*H_*T_];
__device__ float g_sinbuf [(size_t)B_*H_*NCH_*HD_*HD_];
__device__ float g_sprebuf[(size_t)B_*H_*NCH_*HD_*HD_];
__device__ __nv_bfloat16 g_xhi[(size_t)BT_*D_];
__device__ __nv_bfloat16 g_xlo[(size_t)BT_*D_];
__device__ __nv_bfloat16 g_ohi[(size_t)BT_*D_];
__device__ __nv_bfloat16 g_olo[(size_t)BT_*D_];
__device__ __nv_bfloat16 g_wthi[5*(size_t)D_*D_];   // W^T [N,K]: q,k,v,g,out
__device__ __nv_bfloat16 g_wtlo[5*(size_t)D_*D_];

__device__ __forceinline__ float log_sigmoidf(float z) {
    return (z >= 0.f) ? -log1pf(expf(-z)) : (z - log1pf(expf(z)));
}

// ============================= MMA helpers =============================
__device__ __forceinline__ uint32_t smem_u32(const void* p) {
    uint32_t a;
    asm("{ .reg .u64 t; cvta.to.shared.u64 t, %1; cvt.u32.u64 %0, t; }" : "=r"(a) : "l"(p));
    return a;
}
__device__ __forceinline__ void cp_async16(uint32_t s, const void* g) {
    asm volatile("cp.async.cg.shared.global [%0], [%1], 16;" :: "r"(s), "l"(g));
}
__device__ __forceinline__ void cp_commit() { asm volatile("cp.async.commit_group;"); }
template<int N> __device__ __forceinline__ void cp_wait() {
    asm volatile("cp.async.wait_group %0;" :: "n"(N));
}
__device__ __forceinline__ void ldmat4(uint32_t* r, uint32_t a) {
    asm volatile("ldmatrix.sync.aligned.m8n8.x4.shared.b16 {%0,%1,%2,%3}, [%4];"
        : "=r"(r[0]), "=r"(r[1]), "=r"(r[2]), "=r"(r[3]) : "r"(a));
}
__device__ __forceinline__ void mma_bf16(float* d, const uint32_t* a, uint32_t b0, uint32_t b1) {
    asm volatile(
        "mma.sync.aligned.m16n8k16.row.col.f32.bf16.bf16.f32 "
        "{%0,%1,%2,%3}, {%4,%5,%6,%7}, {%8,%9}, {%0,%1,%2,%3};"
        : "+f"(d[0]), "+f"(d[1]), "+f"(d[2]), "+f"(d[3])
        : "r"(a[0]), "r"(a[1]), "r"(a[2]), "r"(a[3]), "r"(b0), "r"(b1));
}

// ============================= tensor-core GEMM =============================
// C[M,2048] = (Ahi+Alo)[M,2048] @ (Bhi+Blo)^T, B operands [N,K] row-major.
// 128x128 CTA tile, BK=32, 8 warps (2x4), warp tile 64x32.
// 3-stage cp.async pipeline, ONE __syncthreads per chunk.
#define LDS_ROW 40                      // bf16 per smem row (80 B, conflict-free ldmatrix)
#define STAGE_A (128 * LDS_ROW * 2)     // 10240 B
#define STAGE_T (2 * STAGE_A)           // 20480 B (A + B)
#define NSTG3   3
#define TCG_SMEM (NSTG3 * STAGE_T)      // 61440 B

__global__ void __launch_bounds__(256) tc_gemm(
    const __nv_bfloat16* __restrict__ Ahi, const __nv_bfloat16* __restrict__ Alo,
    const __nv_bfloat16* __restrict__ Bhi, const __nv_bfloat16* __restrict__ Blo,
    float* __restrict__ C)
{
    extern __shared__ __align__(16) char smem[];
    const uint32_t smb = smem_u32(smem);

    int tid = threadIdx.x, lane = tid & 31, wid = tid >> 5;
    int wm = wid >> 2, wn = wid & 3;                     // 2 x 4 warp grid
    int m0 = blockIdx.y * 128, n0 = blockIdx.x * 128;

    int gr0 = tid >> 2;                                  // row 0..63
    int gc0 = (tid & 3) << 3;                            // bf16 col 0,8,16,24
    uint32_t so_base = (uint32_t)(gr0 * (LDS_ROW * 2) + gc0 * 2);
    uint32_t so_base2 = (uint32_t)((gr0 + 64) * (LDS_ROW * 2) + gc0 * 2);

    uint32_t aoff[4];
#pragma unroll
    for (int mt = 0; mt < 4; mt++)
        aoff[mt] = (uint32_t)(((wm * 64 + mt * 16 + (lane & 15)) * LDS_ROW + ((lane >> 4) << 3)) * 2);
    uint32_t boff[2];
    {
        int q = lane >> 3, r = lane & 7;
#pragma unroll
        for (int np = 0; np < 2; np++) {
            int n = wn * 32 + np * 16 + ((q >> 1) << 3) + r;
            int kc = (q & 1) << 3;
            boff[np] = (uint32_t)((n * LDS_ROW + kc) * 2);
        }
    }

    float acc[4][4][4];
#pragma unroll
    for (int i = 0; i < 4; i++)
#pragma unroll
        for (int j = 0; j < 4; j++)
#pragma unroll
            for (int e = 0; e < 4; e++) acc[i][j][e] = 0.f;

    const int NCHUNK = 192;                              // 3 passes x 64

    // prologue: issue chunks 0 and 1 (one commit group each)
#pragma unroll
    for (int pc = 0; pc < 2; pc++) {
        int pass = 0;
        int kk = pc << 5;
        const __nv_bfloat16* As = Ahi;
        const __nv_bfloat16* Bs = Bhi;
        uint32_t st = smb + pc * STAGE_T;
        cp_async16(st + so_base,            As + (size_t)(m0 + gr0) * D_ + kk + gc0);
        cp_async16(st + so_base2,           As + (size_t)(m0 + gr0 + 64) * D_ + kk + gc0);
        cp_async16(st + STAGE_A + so_base,  Bs + (size_t)(n0 + gr0) * D_ + kk + gc0);
        cp_async16(st + STAGE_A + so_base2, Bs + (size_t)(n0 + gr0 + 64) * D_ + kk + gc0);
        cp_commit();
        (void)pass;
    }

    int st_c = 0;                                        // stage of chunk c
    for (int c = 0; c < NCHUNK; c++) {
        cp_wait<1>();                                    // chunk c resident (this thread)
        __syncthreads();                                 // visible to all; stage (c-1)%3 free

        // issue chunk c+2 into stage (c+2)%3 == (c-1+3)%3
        int cn = c + 2;
        if (cn < NCHUNK) {
            int pass = cn >> 6;
            int kk = (cn & 63) << 5;
            const __nv_bfloat16* As = (pass == 1) ? Alo : Ahi;
            const __nv_bfloat16* Bs = (pass == 2) ? Blo : Bhi;
            int stn = st_c + 2; if (stn >= NSTG3) stn -= NSTG3;
            uint32_t st = smb + stn * STAGE_T;
            cp_async16(st + so_base,            As + (size_t)(m0 + gr0) * D_ + kk + gc0);
            cp_async16(st + so_base2,           As + (size_t)(m0 + gr0 + 64) * D_ + kk + gc0);
            cp_async16(st + STAGE_A + so_base,  Bs + (size_t)(n0 + gr0) * D_ + kk + gc0);
            cp_async16(st + STAGE_A + so_base2, Bs + (size_t)(n0 + gr0 + 64) * D_ + kk + gc0);
        }
        cp_commit();                                     // empty group in tail keeps counts

        uint32_t sA = smb + st_c * STAGE_T;
        uint32_t sB = sA + STAGE_A;
#pragma unroll
        for (int ks = 0; ks < 2; ks++) {
            uint32_t a[4][4], b[2][4];
#pragma unroll
            for (int mt = 0; mt < 4; mt++) ldmat4(a[mt], sA + aoff[mt] + ks * 32);
#pragma unroll
            for (int np = 0; np < 2; np++) ldmat4(b[np], sB + boff[np] + ks * 32);
#pragma unroll
            for (int mt = 0; mt < 4; mt++)
#pragma unroll
                for (int nt = 0; nt < 4; nt++)
                    mma_bf16(acc[mt][nt], a[mt], b[nt >> 1][(nt & 1) * 2], b[nt >> 1][(nt & 1) * 2 + 1]);
        }
        if (++st_c >= NSTG3) st_c = 0;
    }

    // epilogue: direct float2 stores
    int tq = lane >> 2, tr = lane & 3;
#pragma unroll
    for (int mt = 0; mt < 4; mt++) {
#pragma unroll
        for (int nt = 0; nt < 4; nt++) {
            int m = m0 + wm * 64 + mt * 16 + tq;
            int n = n0 + wn * 32 + nt * 8 + tr * 2;
            *(float2*)&C[(size_t)m * D_ + n]       = make_float2(acc[mt][nt][0], acc[mt][nt][1]);
            *(float2*)&C[(size_t)(m + 8) * D_ + n] = make_float2(acc[mt][nt][2], acc[mt][nt][3]);
        }
    }
}

// ---------------- fp32 -> bf16 hi/lo split ----------------
__global__ __launch_bounds__(256) void split_kernel(
    const float* __restrict__ a, __nv_bfloat16* __restrict__ hi, __nv_bfloat16* __restrict__ lo)
{
    size_t i = ((size_t)blockIdx.x * 256 + threadIdx.x) * 4;
    float4 v = *(const float4*)&a[i];
    __nv_bfloat16 h0 = __float2bfloat16(v.x), h1 = __float2bfloat16(v.y);
    __nv_bfloat16 h2 = __float2bfloat16(v.z), h3 = __float2bfloat16(v.w);
    __nv_bfloat16 l0 = __float2bfloat16(v.x - __bfloat162float(h0));
    __nv_bfloat16 l1 = __float2bfloat16(v.y - __bfloat162float(h1));
    __nv_bfloat16 l2 = __float2bfloat16(v.z - __bfloat162float(h2));
    __nv_bfloat16 l3 = __float2bfloat16(v.w - __bfloat162float(h3));
    __nv_bfloat162* hp = (__nv_bfloat162*)(hi + i);
    __nv_bfloat162* lp = (__nv_bfloat162*)(lo + i);
    hp[0] = __halves2bfloat162(h0, h1); hp[1] = __halves2bfloat162(h2, h3);
    lp[0] = __halves2bfloat162(l0, l1); lp[1] = __halves2bfloat162(l2, l3);
}

// ---------------- W[K,N] -> Wt_hi/lo[N,K] transpose+split ----------------
__global__ __launch_bounds__(256) void wsplit_kernel(
    const float* __restrict__ W, __nv_bfloat16* __restrict__ hi, __nv_bfloat16* __restrict__ lo)
{
    __shared__ float tile[32][33];
    int k0 = blockIdx.y * 32, n0 = blockIdx.x * 32;
    int tx = threadIdx.x & 31, ty = threadIdx.x >> 5;
#pragma unroll
    for (int i = 0; i < 32; i += 8)
        tile[ty + i][tx] = W[(size_t)(k0 + ty + i) * D_ + n0 + tx];
    __syncthreads();
#pragma unroll
    for (int i = 0; i < 32; i += 8) {
        float v = tile[tx][ty + i];
        __nv_bfloat16 h = __float2bfloat16(v);
        __nv_bfloat16 l = __float2bfloat16(v - __bfloat162float(h));
        size_t oi = (size_t)(n0 + ty + i) * D_ + k0 + tx;
        hi[oi] = h; lo[oi] = l;
    }
}

// ============================= retention =============================
__global__ __launch_bounds__(128) void gt_kernel(
    const float* __restrict__ x, const float* __restrict__ Wgt, float* __restrict__ gt)
{
    int row = blockIdx.x;
    int tid = threadIdx.x;
    const float* xr = x + (size_t)row * D_;
    float acc[16];
#pragma unroll
    for (int h = 0; h < 16; h++) acc[h] = 0.f;
    for (int kk = tid; kk < D_; kk += 128) {
        float xv = xr[kk];
        const float4* w4 = (const float4*)(Wgt + (size_t)kk * 16);
        float4 w0 = w4[0], w1 = w4[1], w2 = w4[2], w3 = w4[3];
        acc[0]  += xv * w0.x; acc[1]  += xv * w0.y; acc[2]  += xv * w0.z; acc[3]  += xv * w0.w;
        acc[4]  += xv * w1.x; acc[5]  += xv * w1.y; acc[6]  += xv * w1.z; acc[7]  += xv * w1.w;
        acc[8]  += xv * w2.x; acc[9]  += xv * w2.y; acc[10] += xv * w2.z; acc[11] += xv * w2.w;
        acc[12] += xv * w3.x; acc[13] += xv * w3.y; acc[14] += xv * w3.z; acc[15] += xv * w3.w;
    }
#pragma unroll
    for (int h = 0; h < 16; h++)
#pragma unroll
        for (int off = 16; off > 0; off >>= 1)
            acc[h] += __shfl_down_sync(0xffffffffu, acc[h], off);
    __shared__ float part[4][16];
    int warp = tid >> 5, lane = tid & 31;
    if (lane == 0)
#pragma unroll
        for (int h = 0; h < 16; h++) part[warp][h] = acc[h];
    __syncthreads();
    if (tid < 16) {
        float s = part[0][tid] + part[1][tid] + part[2][tid] + part[3][tid];
        int b = row >> 12, t = row & 4095;
        gt[((size_t)(b * H_ + tid)) * T_ + t] = log_sigmoidf(s) * (1.f / 16.f);
    }
}

__global__ __launch_bounds__(256) void cumsum_kernel(
    const float* __restrict__ gt, float* __restrict__ gc)
{
    int bh = blockIdx.x >> 4;
    int n  = blockIdx.x & 15;
    int tid = threadIdx.x, lane = tid & 31, warp = tid >> 5;
    size_t idx = (size_t)bh * T_ + n * CH_ + tid;
    float v = gt[idx];
#pragma unroll
    for (int off = 1; off < 32; off <<= 1) {
        float y = __shfl_up_sync(0xffffffffu, v, off);
        if (lane >= off) v += y;
    }
    __shared__ float ws[8];
    if (lane == 31) ws[warp] = v;
    __syncthreads();
    if (tid == 0) {
        float s = 0.f;
#pragma unroll
        for (int w = 0; w < 8; w++) { float t = ws[w]; ws[w] = s; s += t; }
    }
    __syncthreads();
    gc[idx] = v + ws[warp];
}

__global__ __launch_bounds__(256) void rope_kernel(
    float* __restrict__ q, float* __restrict__ k,
    const float* __restrict__ cb, const float* __restrict__ sb)
{
    int p = blockIdx.x * 256 + threadIdx.x;
    int i = p & 63;
    int h = (p >> 6) & 15;
    int t = (p >> 10) & 4095;
    int b = p >> 22;
    float c = cb[t * 64 + i], s = sb[t * 64 + i];
    size_t base = ((size_t)(b * T_ + t)) * D_ + h * HD_ + 2 * i;
    float2 qv = *(float2*)&q[base];
    float2 kv = *(float2*)&k[base];
    float2 qo, ko;
    qo.x = qv.x * c - qv.y * s;  qo.y = qv.x * s + qv.y * c;
    ko.x = kv.x * c - kv.y * s;  ko.y = kv.x * s + kv.y * c;
    *(float2*)&q[base] = qo;
    *(float2*)&k[base] = ko;
}

__global__ __launch_bounds__(256) void sin_kernel(
    const float* __restrict__ k, const float* __restrict__ v,
    const float* __restrict__ gc, float* __restrict__ Sin)
{
    __shared__ __align__(16) float Ks[32 * 128];
    __shared__ __align__(16) float Vs[32 * 128];
    __shared__ float kd[32];
    int blk = blockIdx.x;
    int n = blk & 15, h = (blk >> 4) & 15, b = blk >> 8;
    int tid = threadIdx.x;
    int trow = tid >> 4, tcol = tid & 15;
    const float* gcc = gc + ((size_t)(b * H_ + h)) * T_ + n * CH_;
    float gtot = gcc[CH_ - 1];

    float acc[8][8];
#pragma unroll
    for (int i = 0; i < 8; i++)
#pragma unroll
        for (int j = 0; j < 8; j++) acc[i][j] = 0.f;

    for (int s0 = 0; s0 < CH_; s0 += 32) {
        __syncthreads();
        if (tid < 32) kd[tid] = expf(gtot - gcc[s0 + tid]) * SCALE_;
        __syncthreads();
#pragma unroll
        for (int l = 0; l < 4; l++) {
            int li = tid + l * 256;
            int c = li >> 5, gcol = (li & 31) << 2;
            size_t gi = ((size_t)(b * T_ + n * CH_ + s0 + c)) * D_ + h * HD_ + gcol;
            float4 kv4 = *(const float4*)&k[gi];
            float sc = kd[c];
            kv4.x *= sc; kv4.y *= sc; kv4.z *= sc; kv4.w *= sc;
            *(float4*)&Ks[c * 128 + gcol] = kv4;
            *(float4*)&Vs[c * 128 + gcol] = *(const float4*)&v[gi];
        }
        __syncthreads();
#pragma unroll
        for (int c = 0; c < 32; c++) {
            float4 a0 = *(float4*)&Ks[c * 128 + trow * 8];
            float4 a1 = *(float4*)&Ks[c * 128 + trow * 8 + 4];
            float4 b0 = *(float4*)&Vs[c * 128 + tcol * 8];
            float4 b1 = *(float4*)&Vs[c * 128 + tcol * 8 + 4];
            float a[8] = {a0.x, a0.y, a0.z, a0.w, a1.x, a1.y, a1.z, a1.w};
            float bb[8] = {b0.x, b0.y, b0.z, b0.w, b1.x, b1.y, b1.z, b1.w};
#pragma unroll
            for (int i = 0; i < 8; i++)
#pragma unroll
                for (int j = 0; j < 8; j++) acc[i][j] += a[i] * bb[j];
        }
    }
    size_t base = (size_t)blk * (HD_ * HD_);
#pragma unroll
    for (int i = 0; i < 8; i++) {
        size_t oi = base + (size_t)(trow * 8 + i) * HD_ + tcol * 8;
        *(float4*)&Sin[oi]     = make_float4(acc[i][0], acc[i][1], acc[i][2], acc[i][3]);
        *(float4*)&Sin[oi + 4] = make_float4(acc[i][4], acc[i][5], acc[i][6], acc[i][7]);
    }
}

__global__ __launch_bounds__(256) void scan_kernel(
    const float* __restrict__ Sin, const float* __restrict__ gc, float* __restrict__ Spre)
{
    int bh = blockIdx.x;
    float S[64];
#pragma unroll
    for (int l = 0; l < 64; l++) S[l] = 0.f;
    for (int n = 0; n < NCH_; n++) {
        float cd = expf(gc[(size_t)bh * T_ + n * CH_ + (CH_ - 1)]);
        size_t base = ((size_t)(bh * NCH_ + n)) * (HD_ * HD_);
#pragma unroll
        for (int l = 0; l < 64; l++) {
            int idx = threadIdx.x + l * 256;
            Spre[base + idx] = S[l];
            S[l] = S[l] * cd + Sin[base + idx];
        }
    }
}

#define QS_OFF  0
#define BS_OFF  8192
#define SS_OFF  16384
#define GQ_OFF  20736
#define GK_OFF  20800
#define RED_OFF 20864
#define SMF_TOT 21888

__global__ __launch_bounds__(256) void out_kernel(
    const float* __restrict__ q, const float* __restrict__ k,
    const float* __restrict__ v, const float* __restrict__ g,
    const float* __restrict__ gc, const float* __restrict__ Spre,
    __nv_bfloat16* __restrict__ ohi, __nv_bfloat16* __restrict__ olo)
{
    extern __shared__ __align__(16) float sm[];
    float* Qs  = sm + QS_OFF;
    float* Bs  = sm + BS_OFF;
    float* Ss  = sm + SS_OFF;
    float* gq  = sm + GQ_OFF;
    float* gk  = sm + GK_OFF;
    float* red = sm + RED_OFF;

    int blk = blockIdx.x;
    int rt = blk & 3, n = (blk >> 2) & 15, h = (blk >> 6) & 15, b = blk >> 10;
    int tid = threadIdx.x, trow = tid >> 4, tcol = tid & 15;
    int trow4 = trow * 4;
    const float* gcc = gc + ((size_t)(b * H_ + h)) * T_ + n * CH_;
    int c0 = rt * 64;
    int rowbase = b * T_ + n * CH_;

#pragma unroll
    for (int l = 0; l < 8; l++) {
        int li = tid + l * 256;
        int c = li >> 5, gcol = (li & 31) << 2;
        size_t gi = ((size_t)(rowbase + c0 + c)) * D_ + h * HD_ + gcol;
        *(float4*)&Qs[c * 128 + gcol] = *(const float4*)&q[gi];
    }
    if (tid < 64) gq[tid] = gcc[c0 + tid];

    float oacc[4][8];
#pragma unroll
    for (int i = 0; i < 4; i++)
#pragma unroll
        for (int j = 0; j < 8; j++) oacc[i][j] = 0.f;
    __syncthreads();

    for (int st = 0; st <= rt; st++) {
        int s0 = st * 64;
#pragma unroll
        for (int l = 0; l < 8; l++) {
            int li = tid + l * 256;
            int c = li >> 5, gr = li & 31;
            size_t gi = ((size_t)(rowbase + s0 + c)) * D_ + h * HD_ + (gr << 2);
            *(float4*)&Bs[c * 128 + ((gr ^ (c & 7)) << 2)] = *(const float4*)&k[gi];
        }
        if (tid < 64) gk[tid] = gcc[s0 + tid];
        __syncthreads();

        float sacc[4][4];
#pragma unroll
        for (int i = 0; i < 4; i++)
#pragma unroll
            for (int j = 0; j < 4; j++) sacc[i][j] = 0.f;
#pragma unroll
        for (int gr = 0; gr < 32; gr++) {
            float4 a[4];
#pragma unroll
            for (int i = 0; i < 4; i++) a[i] = *(float4*)&Qs[(trow4 + i) * 128 + (gr << 2)];
#pragma unroll
            for (int j = 0; j < 4; j++) {
                int s = tcol * 4 + j;
                float4 bb = *(float4*)&Bs[s * 128 + ((gr ^ (s & 7)) << 2)];
#pragma unroll
                for (int i = 0; i < 4; i++)
                    sacc[i][j] += a[i].x * bb.x + a[i].y * bb.y + a[i].z * bb.z + a[i].w * bb.w;
            }
        }
#pragma unroll
        for (int i = 0; i < 4; i++) {
            int r = trow4 + i;
            float gqi = gq[r];
#pragma unroll
            for (int j = 0; j < 4; j++) {
                int s = tcol * 4 + j;
                float val = 0.f;
                if (s0 + s <= c0 + r) val = sacc[i][j] * SCALE_ * expf(gqi - gk[s]);
                Ss[r * 68 + s] = val;
            }
        }
        __syncthreads();

#pragma unroll
        for (int l = 0; l < 8; l++) {
            int li = tid + l * 256;
            int c = li >> 5, gr = li & 31;
            size_t gi = ((size_t)(rowbase + s0 + c)) * D_ + h * HD_ + (gr << 2);
            *(float4*)&Bs[c * 128 + ((gr ^ (c & 7)) << 2)] = *(const float4*)&v[gi];
        }
        __syncthreads();

#pragma unroll
        for (int s = 0; s < 64; s++) {
            float4 b0 = *(float4*)&Bs[s * 128 + (((2 * tcol)     ^ (s & 7)) << 2)];
            float4 b1 = *(float4*)&Bs[s * 128 + (((2 * tcol + 1) ^ (s & 7)) << 2)];
#pragma unroll
            for (int i = 0; i < 4; i++) {
                float a = Ss[(trow4 + i) * 68 + s];
                oacc[i][0] += a * b0.x; oacc[i][1] += a * b0.y;
                oacc[i][2] += a * b0.z; oacc[i][3] += a * b0.w;
                oacc[i][4] += a * b1.x; oacc[i][5] += a * b1.y;
                oacc[i][6] += a * b1.z; oacc[i][7] += a * b1.w;
            }
        }
        __syncthreads();
    }

    float qd[4];
#pragma unroll
    for (int i = 0; i < 4; i++) qd[i] = expf(gq[trow4 + i]);
    size_t sbase = ((size_t)(blk >> 2)) * (HD_ * HD_);
    for (int d0 = 0; d0 < 128; d0 += 64) {
#pragma unroll
        for (int l = 0; l < 8; l++) {
            int li = tid + l * 256;
            int dd = li >> 5, gr = li & 31;
            *(float4*)&Bs[dd * 128 + ((gr ^ (dd & 7)) << 2)] =
                *(const float4*)&Spre[sbase + (size_t)(d0 + dd) * 128 + (gr << 2)];
        }
        __syncthreads();
#pragma unroll
        for (int dd = 0; dd < 64; dd++) {
            float4 b0 = *(float4*)&Bs[dd * 128 + (((2 * tcol)     ^ (dd & 7)) << 2)];
            float4 b1 = *(float4*)&Bs[dd * 128 + (((2 * tcol + 1) ^ (dd & 7)) << 2)];
#pragma unroll
            for (int i = 0; i < 4; i++) {
                float a = Qs[(trow4 + i) * 128 + d0 + dd] * qd[i];
                oacc[i][0] += a * b0.x; oacc[i][1] += a * b0.y;
                oacc[i][2] += a * b0.z; oacc[i][3] += a * b0.w;
                oacc[i][4] += a * b1.x; oacc[i][5] += a * b1.y;
                oacc[i][6] += a * b1.z; oacc[i][7] += a * b1.w;
            }
        }
        __syncthreads();
    }

#pragma unroll
    for (int i = 0; i < 4; i++) {
        float ss = 0.f;
#pragma unroll
        for (int j = 0; j < 8; j++) ss += oacc[i][j] * oacc[i][j];
        red[(trow4 + i) * 16 + tcol] = ss;
    }
    __syncthreads();
#pragma unroll
    for (int i = 0; i < 4; i++) {
        int r = trow4 + i;
        float ss = 0.f;
#pragma unroll
        for (int t2 = 0; t2 < 16; t2++) ss += red[r * 16 + t2];
        float rn = rsqrtf(ss * (1.0f / 128.0f) + 1e-5f);
        size_t gi = ((size_t)(rowbase + c0 + r)) * D_ + h * HD_ + tcol * 8;
        float4 g0 = *(const float4*)&g[gi];
        float4 g1 = *(const float4*)&g[gi + 4];
        float ov[8];
        ov[0] = oacc[i][0] * rn * (g0.x / (1.f + expf(-g0.x)));
        ov[1] = oacc[i][1] * rn * (g0.y / (1.f + expf(-g0.y)));
        ov[2] = oacc[i][2] * rn * (g0.z / (1.f + expf(-g0.z)));
        ov[3] = oacc[i][3] * rn * (g0.w / (1.f + expf(-g0.w)));
        ov[4] = oacc[i][4] * rn * (g1.x / (1.f + expf(-g1.x)));
        ov[5] = oacc[i][5] * rn * (g1.y / (1.f + expf(-g1.y)));
        ov[6] = oacc[i][6] * rn * (g1.z / (1.f + expf(-g1.z)));
        ov[7] = oacc[i][7] * rn * (g1.w / (1.f + expf(-g1.w)));
        // fused hi/lo split store (8 bf16 = 16B each)
        __nv_bfloat162 hv[4], lv[4];
#pragma unroll
        for (int j = 0; j < 4; j++) {
            __nv_bfloat16 h0 = __float2bfloat16(ov[2*j]);
            __nv_bfloat16 h1 = __float2bfloat16(ov[2*j+1]);
            __nv_bfloat16 l0 = __float2bfloat16(ov[2*j]   - __bfloat162float(h0));
            __nv_bfloat16 l1 = __float2bfloat16(ov[2*j+1] - __bfloat162float(h1));
            hv[j] = __halves2bfloat162(h0, h1);
            lv[j] = __halves2bfloat162(l0, l1);
        }
        *(uint4*)&ohi[gi] = *(uint4*)hv;
        *(uint4*)&olo[gi] = *(uint4*)lv;
    }
}

// ============================= launcher =============================
extern "C" void kernel_launch(void* const* d_in, const int* in_sizes, int n_in,
                              void* d_out, int out_size)
{
    const float* x    = (const float*)d_in[0];
    const float* cosb = (const float*)d_in[1];
    const float* sinb = (const float*)d_in[2];
    const float* Wq   = (const float*)d_in[3];
    const float* Wk   = (const float*)d_in[4];
    const float* Wv   = (const float*)d_in[5];
    const float* Wg   = (const float*)d_in[6];
    const float* Wgt  = (const float*)d_in[7];
    const float* Wout = (const float*)d_in[8];
    float* out = (float*)d_out;

    float *q, *k, *v, *g, *gt, *gc, *sbuf, *spre;
    __nv_bfloat16 *xhi, *xlo, *ohi, *olo, *wthi, *wtlo;
    cudaGetSymbolAddress((void**)&q,    g_q);
    cudaGetSymbolAddress((void**)&k,    g_k);
    cudaGetSymbolAddress((void**)&v,    g_v);
    cudaGetSymbolAddress((void**)&g,    g_g);
    cudaGetSymbolAddress((void**)&gt,   g_gt);
    cudaGetSymbolAddress((void**)&gc,   g_gc);
    cudaGetSymbolAddress((void**)&sbuf, g_sinbuf);
    cudaGetSymbolAddress((void**)&spre, g_sprebuf);
    cudaGetSymbolAddress((void**)&xhi,  g_xhi);
    cudaGetSymbolAddress((void**)&xlo,  g_xlo);
    cudaGetSymbolAddress((void**)&ohi,  g_ohi);
    cudaGetSymbolAddress((void**)&olo,  g_olo);
    cudaGetSymbolAddress((void**)&wthi, g_wthi);
    cudaGetSymbolAddress((void**)&wtlo, g_wtlo);

    cudaFuncSetAttribute(out_kernel, cudaFuncAttributeMaxDynamicSharedMemorySize,
                         SMF_TOT * sizeof(float));
    cudaFuncSetAttribute(tc_gemm, cudaFuncAttributeMaxDynamicSharedMemorySize, TCG_SMEM);

    const size_t WSZ = (size_t)D_ * D_;
    dim3 wgrid(D_ / 32, D_ / 32);
    dim3 ggrid(D_ / 128, BT_ / 128);   // (16, 64)

    split_kernel<<<(BT_ * (D_ / 4)) / 256, 256>>>(x, xhi, xlo);
    wsplit_kernel<<<wgrid, 256>>>(Wq,   wthi + 0 * WSZ, wtlo + 0 * WSZ);
    wsplit_kernel<<<wgrid, 256>>>(Wk,   wthi + 1 * WSZ, wtlo + 1 * WSZ);
    wsplit_kernel<<<wgrid, 256>>>(Wv,   wthi + 2 * WSZ, wtlo + 2 * WSZ);
    wsplit_kernel<<<wgrid, 256>>>(Wg,   wthi + 3 * WSZ, wtlo + 3 * WSZ);
    wsplit_kernel<<<wgrid, 256>>>(Wout, wthi + 4 * WSZ, wtlo + 4 * WSZ);

    tc_gemm<<<ggrid, 256, TCG_SMEM>>>(xhi, xlo, wthi + 0 * WSZ, wtlo + 0 * WSZ, q);
    tc_gemm<<<ggrid, 256, TCG_SMEM>>>(xhi, xlo, wthi + 1 * WSZ, wtlo + 1 * WSZ, k);
    tc_gemm<<<ggrid, 256, TCG_SMEM>>>(xhi, xlo, wthi + 2 * WSZ, wtlo + 2 * WSZ, v);
    tc_gemm<<<ggrid, 256, TCG_SMEM>>>(xhi, xlo, wthi + 3 * WSZ, wtlo + 3 * WSZ, g);

    gt_kernel<<<BT_, 128>>>(x, Wgt, gt);
    cumsum_kernel<<<B_ * H_ * NCH_, 256>>>(gt, gc);
    rope_kernel<<<(B_ * T_ * H_ * 64) / 256, 256>>>(q, k, cosb, sinb);
    sin_kernel<<<B_ * H_ * NCH_, 256>>>(k, v, gc, sbuf);
    scan_kernel<<<B_ * H_, 256>>>(sbuf, gc, spre);
    out_kernel<<<B_ * H_ * NCH_ * 4, 256, SMF_TOT * sizeof(float)>>>(q, k, v, g, gc, spre, ohi, olo);

    tc_gemm<<<ggrid, 256, TCG_SMEM>>>(ohi, olo, wthi + 4 * WSZ, wtlo + 4 * WSZ, out);
}

// round 6
// speedup vs baseline: 2.1450x; 1.0658x over previous
#include <cuda_runtime.h>
#include <cuda_bf16.h>
#include <cstdint>

#define B_   2
#define T_   4096
#define D_   2048
#define H_   16
#define HD_  128
#define CH_  256
#define NCH_ 16
#define BT_  (B_*T_)
#define SCALE_ 0.08838834764831845f

// ---------------- scratch ----------------
__device__ float g_q[(size_t)BT_*D_];
__device__ float g_k[(size_t)BT_*D_];
__device__ float g_v[(size_t)BT_*D_];
__device__ float g_g[(size_t)BT_*D_];
__device__ float g_gt[B_*H_*T_];
__device__ float g_gc[B_*H_*T_];
__device__ float g_sinbuf [(size_t)B_*H_*NCH_*HD_*HD_];
__device__ float g_sprebuf[(size_t)B_*H_*NCH_*HD_*HD_];
__device__ __nv_bfloat16 g_xhi[(size_t)BT_*D_];
__device__ __nv_bfloat16 g_xlo[(size_t)BT_*D_];
__device__ __nv_bfloat16 g_ohi[(size_t)BT_*D_];
__device__ __nv_bfloat16 g_olo[(size_t)BT_*D_];
__device__ __nv_bfloat16 g_wthi[5*(size_t)D_*D_];   // W^T [N,K]: q,k,v,g,out
__device__ __nv_bfloat16 g_wtlo[5*(size_t)D_*D_];

__device__ __forceinline__ float log_sigmoidf(float z) {
    return (z >= 0.f) ? -log1pf(expf(-z)) : (z - log1pf(expf(z)));
}

// ============================= MMA helpers =============================
__device__ __forceinline__ uint32_t smem_u32(const void* p) {
    uint32_t a;
    asm("{ .reg .u64 t; cvta.to.shared.u64 t, %1; cvt.u32.u64 %0, t; }" : "=r"(a) : "l"(p));
    return a;
}
__device__ __forceinline__ void cp_async16(uint32_t s, const void* g) {
    asm volatile("cp.async.cg.shared.global [%0], [%1], 16;" :: "r"(s), "l"(g));
}
__device__ __forceinline__ void cp_commit() { asm volatile("cp.async.commit_group;"); }
template<int N> __device__ __forceinline__ void cp_wait() {
    asm volatile("cp.async.wait_group %0;" :: "n"(N));
}
__device__ __forceinline__ void ldmat4(uint32_t* r, uint32_t a) {
    asm volatile("ldmatrix.sync.aligned.m8n8.x4.shared.b16 {%0,%1,%2,%3}, [%4];"
        : "=r"(r[0]), "=r"(r[1]), "=r"(r[2]), "=r"(r[3]) : "r"(a));
}
__device__ __forceinline__ void mma_bf16(float* d, const uint32_t* a, uint32_t b0, uint32_t b1) {
    asm volatile(
        "mma.sync.aligned.m16n8k16.row.col.f32.bf16.bf16.f32 "
        "{%0,%1,%2,%3}, {%4,%5,%6,%7}, {%8,%9}, {%0,%1,%2,%3};"
        : "+f"(d[0]), "+f"(d[1]), "+f"(d[2]), "+f"(d[3])
        : "r"(a[0]), "r"(a[1]), "r"(a[2]), "r"(a[3]), "r"(b0), "r"(b1));
}

// ============================= tensor-core GEMM =============================
// C[M,2048] = (Ahi+Alo)[M,2048] @ (Bhi+Blo)^T, B operands [N,K] row-major.
// 128x128 CTA tile, BK=32, 8 warps (2x4), warp tile 64x32.
// 4-stage cp.async pipeline, one __syncthreads per chunk, 2 CTAs/SM.
// Optional fused interleaved RoPE in the epilogue (for q/k projections).
#define LDS_ROW 40                      // bf16 per smem row (80 B, conflict-free ldmatrix)
#define STAGE_A (128 * LDS_ROW * 2)     // 10240 B
#define STAGE_T (2 * STAGE_A)           // 20480 B (A + B)
#define NSTG4   4
#define TCG_SMEM (NSTG4 * STAGE_T)      // 81920 B

__global__ void __launch_bounds__(256, 2) tc_gemm(
    const __nv_bfloat16* __restrict__ Ahi, const __nv_bfloat16* __restrict__ Alo,
    const __nv_bfloat16* __restrict__ Bhi, const __nv_bfloat16* __restrict__ Blo,
    float* __restrict__ C,
    const float* __restrict__ rope_cos, const float* __restrict__ rope_sin)
{
    extern __shared__ __align__(16) char smem[];
    const uint32_t smb = smem_u32(smem);

    int tid = threadIdx.x, lane = tid & 31, wid = tid >> 5;
    int wm = wid >> 2, wn = wid & 3;                     // 2 x 4 warp grid
    int m0 = blockIdx.y * 128, n0 = blockIdx.x * 128;

    int gr0 = tid >> 2;                                  // row 0..63
    int gc0 = (tid & 3) << 3;                            // bf16 col 0,8,16,24
    uint32_t so_base  = (uint32_t)(gr0 * (LDS_ROW * 2) + gc0 * 2);
    uint32_t so_base2 = (uint32_t)((gr0 + 64) * (LDS_ROW * 2) + gc0 * 2);

    uint32_t aoff[4];
#pragma unroll
    for (int mt = 0; mt < 4; mt++)
        aoff[mt] = (uint32_t)(((wm * 64 + mt * 16 + (lane & 15)) * LDS_ROW + ((lane >> 4) << 3)) * 2);
    uint32_t boff[2];
    {
        int q = lane >> 3, r = lane & 7;
#pragma unroll
        for (int np = 0; np < 2; np++) {
            int n = wn * 32 + np * 16 + ((q >> 1) << 3) + r;
            int kc = (q & 1) << 3;
            boff[np] = (uint32_t)((n * LDS_ROW + kc) * 2);
        }
    }

    float acc[4][4][4];
#pragma unroll
    for (int i = 0; i < 4; i++)
#pragma unroll
        for (int j = 0; j < 4; j++)
#pragma unroll
            for (int e = 0; e < 4; e++) acc[i][j][e] = 0.f;

    const int NCHUNK = 192;                              // 3 passes x 64

    // prologue: issue chunks 0,1,2 (pass 0 => Ahi/Bhi)
#pragma unroll
    for (int pc = 0; pc < 3; pc++) {
        int kk = pc << 5;
        uint32_t st = smb + pc * STAGE_T;
        cp_async16(st + so_base,            Ahi + (size_t)(m0 + gr0) * D_ + kk + gc0);
        cp_async16(st + so_base2,           Ahi + (size_t)(m0 + gr0 + 64) * D_ + kk + gc0);
        cp_async16(st + STAGE_A + so_base,  Bhi + (size_t)(n0 + gr0) * D_ + kk + gc0);
        cp_async16(st + STAGE_A + so_base2, Bhi + (size_t)(n0 + gr0 + 64) * D_ + kk + gc0);
        cp_commit();
    }

    int st_c = 0;                                        // stage of chunk c
    for (int c = 0; c < NCHUNK; c++) {
        cp_wait<2>();                                    // chunk c resident (this thread)
        __syncthreads();                                 // visible to all; stage (c+3)&3 free

        int cn = c + 3;
        if (cn < NCHUNK) {
            int pass = cn >> 6;
            int kk = (cn & 63) << 5;
            const __nv_bfloat16* As = (pass == 1) ? Alo : Ahi;
            const __nv_bfloat16* Bs = (pass == 2) ? Blo : Bhi;
            uint32_t st = smb + ((st_c + 3) & 3) * STAGE_T;
            cp_async16(st + so_base,            As + (size_t)(m0 + gr0) * D_ + kk + gc0);
            cp_async16(st + so_base2,           As + (size_t)(m0 + gr0 + 64) * D_ + kk + gc0);
            cp_async16(st + STAGE_A + so_base,  Bs + (size_t)(n0 + gr0) * D_ + kk + gc0);
            cp_async16(st + STAGE_A + so_base2, Bs + (size_t)(n0 + gr0 + 64) * D_ + kk + gc0);
        }
        cp_commit();                                     // empty group in tail keeps counts

        uint32_t sA = smb + st_c * STAGE_T;
        uint32_t sB = sA + STAGE_A;
#pragma unroll
        for (int ks = 0; ks < 2; ks++) {
            uint32_t a[4][4], b[2][4];
#pragma unroll
            for (int mt = 0; mt < 4; mt++) ldmat4(a[mt], sA + aoff[mt] + ks * 32);
#pragma unroll
            for (int np = 0; np < 2; np++) ldmat4(b[np], sB + boff[np] + ks * 32);
#pragma unroll
            for (int mt = 0; mt < 4; mt++)
#pragma unroll
                for (int nt = 0; nt < 4; nt++)
                    mma_bf16(acc[mt][nt], a[mt], b[nt >> 1][(nt & 1) * 2], b[nt >> 1][(nt & 1) * 2 + 1]);
        }
        st_c = (st_c + 1) & 3;
    }

    // epilogue: optional fused RoPE (acc pairs are exactly the (2i,2i+1) rope pairs)
    int tq = lane >> 2, tr = lane & 3;
#pragma unroll
    for (int mt = 0; mt < 4; mt++) {
#pragma unroll
        for (int nt = 0; nt < 4; nt++) {
            int m = m0 + wm * 64 + mt * 16 + tq;
            int n = n0 + wn * 32 + nt * 8 + tr * 2;
            float v0 = acc[mt][nt][0], v1 = acc[mt][nt][1];
            float v2 = acc[mt][nt][2], v3 = acc[mt][nt][3];
            if (rope_cos) {
                int i  = (n & 127) >> 1;
                int t1 = m & 4095, t2 = (m + 8) & 4095;
                float c1 = rope_cos[t1 * 64 + i], s1 = rope_sin[t1 * 64 + i];
                float c2 = rope_cos[t2 * 64 + i], s2 = rope_sin[t2 * 64 + i];
                float r0 = v0 * c1 - v1 * s1, r1 = v0 * s1 + v1 * c1;
                float r2 = v2 * c2 - v3 * s2, r3 = v2 * s2 + v3 * c2;
                v0 = r0; v1 = r1; v2 = r2; v3 = r3;
            }
            *(float2*)&C[(size_t)m * D_ + n]       = make_float2(v0, v1);
            *(float2*)&C[(size_t)(m + 8) * D_ + n] = make_float2(v2, v3);
        }
    }
}

// ---------------- fp32 -> bf16 hi/lo split ----------------
__global__ __launch_bounds__(256) void split_kernel(
    const float* __restrict__ a, __nv_bfloat16* __restrict__ hi, __nv_bfloat16* __restrict__ lo)
{
    size_t i = ((size_t)blockIdx.x * 256 + threadIdx.x) * 4;
    float4 v = *(const float4*)&a[i];
    __nv_bfloat16 h0 = __float2bfloat16(v.x), h1 = __float2bfloat16(v.y);
    __nv_bfloat16 h2 = __float2bfloat16(v.z), h3 = __float2bfloat16(v.w);
    __nv_bfloat16 l0 = __float2bfloat16(v.x - __bfloat162float(h0));
    __nv_bfloat16 l1 = __float2bfloat16(v.y - __bfloat162float(h1));
    __nv_bfloat16 l2 = __float2bfloat16(v.z - __bfloat162float(h2));
    __nv_bfloat16 l3 = __float2bfloat16(v.w - __bfloat162float(h3));
    __nv_bfloat162* hp = (__nv_bfloat162*)(hi + i);
    __nv_bfloat162* lp = (__nv_bfloat162*)(lo + i);
    hp[0] = __halves2bfloat162(h0, h1); hp[1] = __halves2bfloat162(h2, h3);
    lp[0] = __halves2bfloat162(l0, l1); lp[1] = __halves2bfloat162(l2, l3);
}

// ---------------- all 5 weights: W[K,N] -> Wt_hi/lo[N,K] transpose+split ----------------
__global__ __launch_bounds__(256) void wsplit_all(
    const float* __restrict__ W0, const float* __restrict__ W1,
    const float* __restrict__ W2, const float* __restrict__ W3,
    const float* __restrict__ W4,
    __nv_bfloat16* __restrict__ hi, __nv_bfloat16* __restrict__ lo)
{
    __shared__ float tile[32][33];
    int z = blockIdx.z;
    const float* W = (z == 0) ? W0 : (z == 1) ? W1 : (z == 2) ? W2 : (z == 3) ? W3 : W4;
    size_t off = (size_t)z * D_ * D_;
    int k0 = blockIdx.y * 32, n0 = blockIdx.x * 32;
    int tx = threadIdx.x & 31, ty = threadIdx.x >> 5;
#pragma unroll
    for (int i = 0; i < 32; i += 8)
        tile[ty + i][tx] = W[(size_t)(k0 + ty + i) * D_ + n0 + tx];
    __syncthreads();
#pragma unroll
    for (int i = 0; i < 32; i += 8) {
        float v = tile[tx][ty + i];
        __nv_bfloat16 h = __float2bfloat16(v);
        __nv_bfloat16 l = __float2bfloat16(v - __bfloat162float(h));
        size_t oi = off + (size_t)(n0 + ty + i) * D_ + k0 + tx;
        hi[oi] = h; lo[oi] = l;
    }
}

// ============================= retention =============================
__global__ __launch_bounds__(128) void gt_kernel(
    const float* __restrict__ x, const float* __restrict__ Wgt, float* __restrict__ gt)
{
    int row = blockIdx.x;
    int tid = threadIdx.x;
    const float* xr = x + (size_t)row * D_;
    float acc[16];
#pragma unroll
    for (int h = 0; h < 16; h++) acc[h] = 0.f;
    for (int kk = tid; kk < D_; kk += 128) {
        float xv = xr[kk];
        const float4* w4 = (const float4*)(Wgt + (size_t)kk * 16);
        float4 w0 = w4[0], w1 = w4[1], w2 = w4[2], w3 = w4[3];
        acc[0]  += xv * w0.x; acc[1]  += xv * w0.y; acc[2]  += xv * w0.z; acc[3]  += xv * w0.w;
        acc[4]  += xv * w1.x; acc[5]  += xv * w1.y; acc[6]  += xv * w1.z; acc[7]  += xv * w1.w;
        acc[8]  += xv * w2.x; acc[9]  += xv * w2.y; acc[10] += xv * w2.z; acc[11] += xv * w2.w;
        acc[12] += xv * w3.x; acc[13] += xv * w3.y; acc[14] += xv * w3.z; acc[15] += xv * w3.w;
    }
#pragma unroll
    for (int h = 0; h < 16; h++)
#pragma unroll
        for (int off = 16; off > 0; off >>= 1)
            acc[h] += __shfl_down_sync(0xffffffffu, acc[h], off);
    __shared__ float part[4][16];
    int warp = tid >> 5, lane = tid & 31;
    if (lane == 0)
#pragma unroll
        for (int h = 0; h < 16; h++) part[warp][h] = acc[h];
    __syncthreads();
    if (tid < 16) {
        float s = part[0][tid] + part[1][tid] + part[2][tid] + part[3][tid];
        int b = row >> 12, t = row & 4095;
        gt[((size_t)(b * H_ + tid)) * T_ + t] = log_sigmoidf(s) * (1.f / 16.f);
    }
}

__global__ __launch_bounds__(256) void cumsum_kernel(
    const float* __restrict__ gt, float* __restrict__ gc)
{
    int bh = blockIdx.x >> 4;
    int n  = blockIdx.x & 15;
    int tid = threadIdx.x, lane = tid & 31, warp = tid >> 5;
    size_t idx = (size_t)bh * T_ + n * CH_ + tid;
    float v = gt[idx];
#pragma unroll
    for (int off = 1; off < 32; off <<= 1) {
        float y = __shfl_up_sync(0xffffffffu, v, off);
        if (lane >= off) v += y;
    }
    __shared__ float ws[8];
    if (lane == 31) ws[warp] = v;
    __syncthreads();
    if (tid == 0) {
        float s = 0.f;
#pragma unroll
        for (int w = 0; w < 8; w++) { float t = ws[w]; ws[w] = s; s += t; }
    }
    __syncthreads();
    gc[idx] = v + ws[warp];
}

__global__ __launch_bounds__(256) void sin_kernel(
    const float* __restrict__ k, const float* __restrict__ v,
    const float* __restrict__ gc, float* __restrict__ Sin)
{
    __shared__ __align__(16) float Ks[32 * 128];
    __shared__ __align__(16) float Vs[32 * 128];
    __shared__ float kd[32];
    int blk = blockIdx.x;
    int n = blk & 15, h = (blk >> 4) & 15, b = blk >> 8;
    int tid = threadIdx.x;
    int trow = tid >> 4, tcol = tid & 15;
    const float* gcc = gc + ((size_t)(b * H_ + h)) * T_ + n * CH_;
    float gtot = gcc[CH_ - 1];

    float acc[8][8];
#pragma unroll
    for (int i = 0; i < 8; i++)
#pragma unroll
        for (int j = 0; j < 8; j++) acc[i][j] = 0.f;

    for (int s0 = 0; s0 < CH_; s0 += 32) {
        __syncthreads();
        if (tid < 32) kd[tid] = expf(gtot - gcc[s0 + tid]) * SCALE_;
        __syncthreads();
#pragma unroll
        for (int l = 0; l < 4; l++) {
            int li = tid + l * 256;
            int c = li >> 5, gcol = (li & 31) << 2;
            size_t gi = ((size_t)(b * T_ + n * CH_ + s0 + c)) * D_ + h * HD_ + gcol;
            float4 kv4 = *(const float4*)&k[gi];
            float sc = kd[c];
            kv4.x *= sc; kv4.y *= sc; kv4.z *= sc; kv4.w *= sc;
            *(float4*)&Ks[c * 128 + gcol] = kv4;
            *(float4*)&Vs[c * 128 + gcol] = *(const float4*)&v[gi];
        }
        __syncthreads();
#pragma unroll
        for (int c = 0; c < 32; c++) {
            float4 a0 = *(float4*)&Ks[c * 128 + trow * 8];
            float4 a1 = *(float4*)&Ks[c * 128 + trow * 8 + 4];
            float4 b0 = *(float4*)&Vs[c * 128 + tcol * 8];
            float4 b1 = *(float4*)&Vs[c * 128 + tcol * 8 + 4];
            float a[8] = {a0.x, a0.y, a0.z, a0.w, a1.x, a1.y, a1.z, a1.w};
            float bb[8] = {b0.x, b0.y, b0.z, b0.w, b1.x, b1.y, b1.z, b1.w};
#pragma unroll
            for (int i = 0; i < 8; i++)
#pragma unroll
                for (int j = 0; j < 8; j++) acc[i][j] += a[i] * bb[j];
        }
    }
    size_t base = (size_t)blk * (HD_ * HD_);
#pragma unroll
    for (int i = 0; i < 8; i++) {
        size_t oi = base + (size_t)(trow * 8 + i) * HD_ + tcol * 8;
        *(float4*)&Sin[oi]     = make_float4(acc[i][0], acc[i][1], acc[i][2], acc[i][3]);
        *(float4*)&Sin[oi + 4] = make_float4(acc[i][4], acc[i][5], acc[i][6], acc[i][7]);
    }
}

// parallel over (bh, 8 parts of the 16K state elements); serial only over 16 chunks
__global__ __launch_bounds__(256) void scan_kernel(
    const float* __restrict__ Sin, const float* __restrict__ gc, float* __restrict__ Spre)
{
    int blk = blockIdx.x;              // 256 = 32 bh x 8 parts
    int bh = blk >> 3, part = blk & 7;
    int e0 = part * 2048 + threadIdx.x;
    float S[8];
#pragma unroll
    for (int l = 0; l < 8; l++) S[l] = 0.f;
    for (int n = 0; n < NCH_; n++) {
        float cd = expf(gc[(size_t)bh * T_ + n * CH_ + (CH_ - 1)]);
        size_t base = ((size_t)(bh * NCH_ + n)) * (HD_ * HD_);
#pragma unroll
        for (int l = 0; l < 8; l++) {
            int idx = e0 + l * 256;
            Spre[base + idx] = S[l];
            S[l] = S[l] * cd + Sin[base + idx];
        }
    }
}

#define QS_OFF  0
#define BS_OFF  8192
#define SS_OFF  16384
#define GQ_OFF  20736
#define GK_OFF  20800
#define RED_OFF 20864
#define SMF_TOT 21888

__global__ __launch_bounds__(256) void out_kernel(
    const float* __restrict__ q, const float* __restrict__ k,
    const float* __restrict__ v, const float* __restrict__ g,
    const float* __restrict__ gc, const float* __restrict__ Spre,
    __nv_bfloat16* __restrict__ ohi, __nv_bfloat16* __restrict__ olo)
{
    extern __shared__ __align__(16) float sm[];
    float* Qs  = sm + QS_OFF;
    float* Bs  = sm + BS_OFF;
    float* Ss  = sm + SS_OFF;
    float* gq  = sm + GQ_OFF;
    float* gk  = sm + GK_OFF;
    float* red = sm + RED_OFF;

    int blk = blockIdx.x;
    int rt = blk & 3, n = (blk >> 2) & 15, h = (blk >> 6) & 15, b = blk >> 10;
    int tid = threadIdx.x, trow = tid >> 4, tcol = tid & 15;
    int trow4 = trow * 4;
    const float* gcc = gc + ((size_t)(b * H_ + h)) * T_ + n * CH_;
    int c0 = rt * 64;
    int rowbase = b * T_ + n * CH_;

#pragma unroll
    for (int l = 0; l < 8; l++) {
        int li = tid + l * 256;
        int c = li >> 5, gcol = (li & 31) << 2;
        size_t gi = ((size_t)(rowbase + c0 + c)) * D_ + h * HD_ + gcol;
        *(float4*)&Qs[c * 128 + gcol] = *(const float4*)&q[gi];
    }
    if (tid < 64) gq[tid] = gcc[c0 + tid];

    float oacc[4][8];
#pragma unroll
    for (int i = 0; i < 4; i++)
#pragma unroll
        for (int j = 0; j < 8; j++) oacc[i][j] = 0.f;
    __syncthreads();

    for (int st = 0; st <= rt; st++) {
        int s0 = st * 64;
#pragma unroll
        for (int l = 0; l < 8; l++) {
            int li = tid + l * 256;
            int c = li >> 5, gr = li & 31;
            size_t gi = ((size_t)(rowbase + s0 + c)) * D_ + h * HD_ + (gr << 2);
            *(float4*)&Bs[c * 128 + ((gr ^ (c & 7)) << 2)] = *(const float4*)&k[gi];
        }
        if (tid < 64) gk[tid] = gcc[s0 + tid];
        __syncthreads();

        float sacc[4][4];
#pragma unroll
        for (int i = 0; i < 4; i++)
#pragma unroll
            for (int j = 0; j < 4; j++) sacc[i][j] = 0.f;
#pragma unroll
        for (int gr = 0; gr < 32; gr++) {
            float4 a[4];
#pragma unroll
            for (int i = 0; i < 4; i++) a[i] = *(float4*)&Qs[(trow4 + i) * 128 + (gr << 2)];
#pragma unroll
            for (int j = 0; j < 4; j++) {
                int s = tcol * 4 + j;
                float4 bb = *(float4*)&Bs[s * 128 + ((gr ^ (s & 7)) << 2)];
#pragma unroll
                for (int i = 0; i < 4; i++)
                    sacc[i][j] += a[i].x * bb.x + a[i].y * bb.y + a[i].z * bb.z + a[i].w * bb.w;
            }
        }
#pragma unroll
        for (int i = 0; i < 4; i++) {
            int r = trow4 + i;
            float gqi = gq[r];
#pragma unroll
            for (int j = 0; j < 4; j++) {
                int s = tcol * 4 + j;
                float val = 0.f;
                if (s0 + s <= c0 + r) val = sacc[i][j] * SCALE_ * expf(gqi - gk[s]);
                Ss[r * 68 + s] = val;
            }
        }
        __syncthreads();

#pragma unroll
        for (int l = 0; l < 8; l++) {
            int li = tid + l * 256;
            int c = li >> 5, gr = li & 31;
            size_t gi = ((size_t)(rowbase + s0 + c)) * D_ + h * HD_ + (gr << 2);
            *(float4*)&Bs[c * 128 + ((gr ^ (c & 7)) << 2)] = *(const float4*)&v[gi];
        }
        __syncthreads();

#pragma unroll
        for (int s = 0; s < 64; s++) {
            float4 b0 = *(float4*)&Bs[s * 128 + (((2 * tcol)     ^ (s & 7)) << 2)];
            float4 b1 = *(float4*)&Bs[s * 128 + (((2 * tcol + 1) ^ (s & 7)) << 2)];
#pragma unroll
            for (int i = 0; i < 4; i++) {
                float a = Ss[(trow4 + i) * 68 + s];
                oacc[i][0] += a * b0.x; oacc[i][1] += a * b0.y;
                oacc[i][2] += a * b0.z; oacc[i][3] += a * b0.w;
                oacc[i][4] += a * b1.x; oacc[i][5] += a * b1.y;
                oacc[i][6] += a * b1.z; oacc[i][7] += a * b1.w;
            }
        }
        __syncthreads();
    }

    float qd[4];
#pragma unroll
    for (int i = 0; i < 4; i++) qd[i] = expf(gq[trow4 + i]);
    size_t sbase = ((size_t)(blk >> 2)) * (HD_ * HD_);
    for (int d0 = 0; d0 < 128; d0 += 64) {
#pragma unroll
        for (int l = 0; l < 8; l++) {
            int li = tid + l * 256;
            int dd = li >> 5, gr = li & 31;
            *(float4*)&Bs[dd * 128 + ((gr ^ (dd & 7)) << 2)] =
                *(const float4*)&Spre[sbase + (size_t)(d0 + dd) * 128 + (gr << 2)];
        }
        __syncthreads();
#pragma unroll
        for (int dd = 0; dd < 64; dd++) {
            float4 b0 = *(float4*)&Bs[dd * 128 + (((2 * tcol)     ^ (dd & 7)) << 2)];
            float4 b1 = *(float4*)&Bs[dd * 128 + (((2 * tcol + 1) ^ (dd & 7)) << 2)];
#pragma unroll
            for (int i = 0; i < 4; i++) {
                float a = Qs[(trow4 + i) * 128 + d0 + dd] * qd[i];
                oacc[i][0] += a * b0.x; oacc[i][1] += a * b0.y;
                oacc[i][2] += a * b0.z; oacc[i][3] += a * b0.w;
                oacc[i][4] += a * b1.x; oacc[i][5] += a * b1.y;
                oacc[i][6] += a * b1.z; oacc[i][7] += a * b1.w;
            }
        }
        __syncthreads();
    }

#pragma unroll
    for (int i = 0; i < 4; i++) {
        float ss = 0.f;
#pragma unroll
        for (int j = 0; j < 8; j++) ss += oacc[i][j] * oacc[i][j];
        red[(trow4 + i) * 16 + tcol] = ss;
    }
    __syncthreads();
#pragma unroll
    for (int i = 0; i < 4; i++) {
        int r = trow4 + i;
        float ss = 0.f;
#pragma unroll
        for (int t2 = 0; t2 < 16; t2++) ss += red[r * 16 + t2];
        float rn = rsqrtf(ss * (1.0f / 128.0f) + 1e-5f);
        size_t gi = ((size_t)(rowbase + c0 + r)) * D_ + h * HD_ + tcol * 8;
        float4 g0 = *(const float4*)&g[gi];
        float4 g1 = *(const float4*)&g[gi + 4];
        float ov[8];
        ov[0] = oacc[i][0] * rn * (g0.x / (1.f + expf(-g0.x)));
        ov[1] = oacc[i][1] * rn * (g0.y / (1.f + expf(-g0.y)));
        ov[2] = oacc[i][2] * rn * (g0.z / (1.f + expf(-g0.z)));
        ov[3] = oacc[i][3] * rn * (g0.w / (1.f + expf(-g0.w)));
        ov[4] = oacc[i][4] * rn * (g1.x / (1.f + expf(-g1.x)));
        ov[5] = oacc[i][5] * rn * (g1.y / (1.f + expf(-g1.y)));
        ov[6] = oacc[i][6] * rn * (g1.z / (1.f + expf(-g1.z)));
        ov[7] = oacc[i][7] * rn * (g1.w / (1.f + expf(-g1.w)));
        __nv_bfloat162 hv[4], lv[4];
#pragma unroll
        for (int j = 0; j < 4; j++) {
            __nv_bfloat16 h0 = __float2bfloat16(ov[2*j]);
            __nv_bfloat16 h1 = __float2bfloat16(ov[2*j+1]);
            __nv_bfloat16 l0 = __float2bfloat16(ov[2*j]   - __bfloat162float(h0));
            __nv_bfloat16 l1 = __float2bfloat16(ov[2*j+1] - __bfloat162float(h1));
            hv[j] = __halves2bfloat162(h0, h1);
            lv[j] = __halves2bfloat162(l0, l1);
        }
        *(uint4*)&ohi[gi] = *(uint4*)hv;
        *(uint4*)&olo[gi] = *(uint4*)lv;
    }
}

// ============================= launcher =============================
extern "C" void kernel_launch(void* const* d_in, const int* in_sizes, int n_in,
                              void* d_out, int out_size)
{
    const float* x    = (const float*)d_in[0];
    const float* cosb = (const float*)d_in[1];
    const float* sinb = (const float*)d_in[2];
    const float* Wq   = (const float*)d_in[3];
    const float* Wk   = (const float*)d_in[4];
    const float* Wv   = (const float*)d_in[5];
    const float* Wg   = (const float*)d_in[6];
    const float* Wgt  = (const float*)d_in[7];
    const float* Wout = (const float*)d_in[8];
    float* out = (float*)d_out;

    float *q, *k, *v, *g, *gt, *gc, *sbuf, *spre;
    __nv_bfloat16 *xhi, *xlo, *ohi, *olo, *wthi, *wtlo;
    cudaGetSymbolAddress((void**)&q,    g_q);
    cudaGetSymbolAddress((void**)&k,    g_k);
    cudaGetSymbolAddress((void**)&v,    g_v);
    cudaGetSymbolAddress((void**)&g,    g_g);
    cudaGetSymbolAddress((void**)&gt,   g_gt);
    cudaGetSymbolAddress((void**)&gc,   g_gc);
    cudaGetSymbolAddress((void**)&sbuf, g_sinbuf);
    cudaGetSymbolAddress((void**)&spre, g_sprebuf);
    cudaGetSymbolAddress((void**)&xhi,  g_xhi);
    cudaGetSymbolAddress((void**)&xlo,  g_xlo);
    cudaGetSymbolAddress((void**)&ohi,  g_ohi);
    cudaGetSymbolAddress((void**)&olo,  g_olo);
    cudaGetSymbolAddress((void**)&wthi, g_wthi);
    cudaGetSymbolAddress((void**)&wtlo, g_wtlo);

    cudaFuncSetAttribute(out_kernel, cudaFuncAttributeMaxDynamicSharedMemorySize,
                         SMF_TOT * sizeof(float));
    cudaFuncSetAttribute(tc_gemm, cudaFuncAttributeMaxDynamicSharedMemorySize, TCG_SMEM);

    const size_t WSZ = (size_t)D_ * D_;
    dim3 wgrid(D_ / 32, D_ / 32, 5);
    dim3 ggrid(D_ / 128, BT_ / 128);   // (16, 64)

    wsplit_all<<<wgrid, 256>>>(Wq, Wk, Wv, Wg, Wout, wthi, wtlo);        // 1
    split_kernel<<<(BT_ * (D_ / 4)) / 256, 256>>>(x, xhi, xlo);          // 2

    tc_gemm<<<ggrid, 256, TCG_SMEM>>>(xhi, xlo, wthi + 0 * WSZ, wtlo + 0 * WSZ, q, cosb, sinb); // 3
    tc_gemm<<<ggrid, 256, TCG_SMEM>>>(xhi, xlo, wthi + 1 * WSZ, wtlo + 1 * WSZ, k, cosb, sinb); // 4
    tc_gemm<<<ggrid, 256, TCG_SMEM>>>(xhi, xlo, wthi + 2 * WSZ, wtlo + 2 * WSZ, v, nullptr, nullptr); // 5
    tc_gemm<<<ggrid, 256, TCG_SMEM>>>(xhi, xlo, wthi + 3 * WSZ, wtlo + 3 * WSZ, g, nullptr, nullptr); // 6 <- ncu

    gt_kernel<<<BT_, 128>>>(x, Wgt, gt);
    cumsum_kernel<<<B_ * H_ * NCH_, 256>>>(gt, gc);
    sin_kernel<<<B_ * H_ * NCH_, 256>>>(k, v, gc, sbuf);
    scan_kernel<<<B_ * H_ * 8, 256>>>(sbuf, gc, spre);
    out_kernel<<<B_ * H_ * NCH_ * 4, 256, SMF_TOT * sizeof(float)>>>(q, k, v, g, gc, spre, ohi, olo);

    tc_gemm<<<ggrid, 256, TCG_SMEM>>>(ohi, olo, wthi + 4 * WSZ, wtlo + 4 * WSZ, out, nullptr, nullptr);
}

// round 7
// speedup vs baseline: 2.1455x; 1.0002x over previous
#include <cuda_runtime.h>
#include <cuda_bf16.h>
#include <cstdint>

#define B_   2
#define T_   4096
#define D_   2048
#define H_   16
#define HD_  128
#define CH_  256
#define NCH_ 16
#define BT_  (B_*T_)
#define SCALE_ 0.08838834764831845f

// ---------------- scratch ----------------
__device__ float g_q[(size_t)BT_*D_];
__device__ float g_k[(size_t)BT_*D_];
__device__ float g_v[(size_t)BT_*D_];
__device__ float g_g[(size_t)BT_*D_];
__device__ float g_gt[B_*H_*T_];
__device__ float g_gc[B_*H_*T_];
__device__ float g_sinbuf [(size_t)B_*H_*NCH_*HD_*HD_];
__device__ float g_sprebuf[(size_t)B_*H_*NCH_*HD_*HD_];
__device__ __nv_bfloat16 g_xhi[(size_t)BT_*D_];
__device__ __nv_bfloat16 g_xlo[(size_t)BT_*D_];
__device__ __nv_bfloat16 g_ohi[(size_t)BT_*D_];
__device__ __nv_bfloat16 g_olo[(size_t)BT_*D_];
__device__ __nv_bfloat16 g_wthi[5*(size_t)D_*D_];   // W^T [N,K]: q,k,v,g,out
__device__ __nv_bfloat16 g_wtlo[5*(size_t)D_*D_];

__device__ __forceinline__ float log_sigmoidf(float z) {
    return (z >= 0.f) ? -log1pf(expf(-z)) : (z - log1pf(expf(z)));
}

// ============================= MMA helpers =============================
__device__ __forceinline__ uint32_t smem_u32(const void* p) {
    uint32_t a;
    asm("{ .reg .u64 t; cvta.to.shared.u64 t, %1; cvt.u32.u64 %0, t; }" : "=r"(a) : "l"(p));
    return a;
}
__device__ __forceinline__ void cp_async16(uint32_t s, const void* g) {
    asm volatile("cp.async.cg.shared.global [%0], [%1], 16;" :: "r"(s), "l"(g));
}
__device__ __forceinline__ void cp_commit() { asm volatile("cp.async.commit_group;"); }
template<int N> __device__ __forceinline__ void cp_wait() {
    asm volatile("cp.async.wait_group %0;" :: "n"(N));
}
__device__ __forceinline__ void ldmat4(uint32_t* r, uint32_t a) {
    asm volatile("ldmatrix.sync.aligned.m8n8.x4.shared.b16 {%0,%1,%2,%3}, [%4];"
        : "=r"(r[0]), "=r"(r[1]), "=r"(r[2]), "=r"(r[3]) : "r"(a));
}
__device__ __forceinline__ void mma_bf16(float* d, const uint32_t* a, uint32_t b0, uint32_t b1) {
    asm volatile(
        "mma.sync.aligned.m16n8k16.row.col.f32.bf16.bf16.f32 "
        "{%0,%1,%2,%3}, {%4,%5,%6,%7}, {%8,%9}, {%0,%1,%2,%3};"
        : "+f"(d[0]), "+f"(d[1]), "+f"(d[2]), "+f"(d[3])
        : "r"(a[0]), "r"(a[1]), "r"(a[2]), "r"(a[3]), "r"(b0), "r"(b1));
}

// ============================= tensor-core GEMM =============================
// C[M,2048] = (Ahi+Alo)[M,2048] @ (Bhi+Blo)^T, B operands [N,K] row-major.
// 128x128 CTA tile, BK=32, 4 warps (2x2), warp tile 64x64 (smem-traffic-optimal).
// 4-stage cp.async pipeline, one __syncthreads per chunk, 2 CTAs/SM.
// Optional fused interleaved RoPE in the epilogue (for q/k projections).
#define LDS_ROW 40                      // bf16 per smem row (80 B, conflict-free ldmatrix)
#define STAGE_A (128 * LDS_ROW * 2)     // 10240 B
#define STAGE_T (2 * STAGE_A)           // 20480 B (A + B)
#define NSTG4   4
#define TCG_SMEM (NSTG4 * STAGE_T)      // 81920 B

__global__ void __launch_bounds__(128, 2) tc_gemm(
    const __nv_bfloat16* __restrict__ Ahi, const __nv_bfloat16* __restrict__ Alo,
    const __nv_bfloat16* __restrict__ Bhi, const __nv_bfloat16* __restrict__ Blo,
    float* __restrict__ C,
    const float* __restrict__ rope_cos, const float* __restrict__ rope_sin)
{
    extern __shared__ __align__(16) char smem[];
    const uint32_t smb = smem_u32(smem);

    int tid = threadIdx.x, lane = tid & 31, wid = tid >> 5;
    int wm = wid >> 1, wn = wid & 1;                     // 2 x 2 warp grid
    int m0 = blockIdx.y * 128, n0 = blockIdx.x * 128;

    // global loads: 128 rows x 32 bf16 per operand per chunk = 512 vec16; 4/thread/operand
    int gr0 = tid >> 2;                                  // row 0..31
    int gc0 = (tid & 3) << 3;                            // bf16 col 0,8,16,24
    uint32_t so_[4];
#pragma unroll
    for (int i = 0; i < 4; i++)
        so_[i] = (uint32_t)((gr0 + 32 * i) * (LDS_ROW * 2) + gc0 * 2);

    uint32_t aoff[4];
#pragma unroll
    for (int mt = 0; mt < 4; mt++)
        aoff[mt] = (uint32_t)(((wm * 64 + mt * 16 + (lane & 15)) * LDS_ROW + ((lane >> 4) << 3)) * 2);
    uint32_t boff[4];
    {
        int q = lane >> 3, r = lane & 7;
#pragma unroll
        for (int np = 0; np < 4; np++) {
            int n = wn * 64 + np * 16 + ((q >> 1) << 3) + r;
            int kc = (q & 1) << 3;
            boff[np] = (uint32_t)((n * LDS_ROW + kc) * 2);
        }
    }

    float acc[4][8][4];
#pragma unroll
    for (int i = 0; i < 4; i++)
#pragma unroll
        for (int j = 0; j < 8; j++)
#pragma unroll
            for (int e = 0; e < 4; e++) acc[i][j][e] = 0.f;

    const int NCHUNK = 192;                              // 3 passes x 64

    // prologue: issue chunks 0,1,2 (pass 0 => Ahi/Bhi)
#pragma unroll
    for (int pc = 0; pc < 3; pc++) {
        int kk = pc << 5;
        uint32_t st = smb + pc * STAGE_T;
#pragma unroll
        for (int i = 0; i < 4; i++) {
            cp_async16(st + so_[i],           Ahi + (size_t)(m0 + gr0 + 32 * i) * D_ + kk + gc0);
            cp_async16(st + STAGE_A + so_[i], Bhi + (size_t)(n0 + gr0 + 32 * i) * D_ + kk + gc0);
        }
        cp_commit();
    }

    int st_c = 0;                                        // stage of chunk c
    for (int c = 0; c < NCHUNK; c++) {
        cp_wait<2>();                                    // chunk c resident (this thread)
        __syncthreads();                                 // visible to all; stage (c+3)&3 free

        int cn = c + 3;
        if (cn < NCHUNK) {
            int pass = cn >> 6;
            int kk = (cn & 63) << 5;
            const __nv_bfloat16* As = (pass == 1) ? Alo : Ahi;
            const __nv_bfloat16* Bs = (pass == 2) ? Blo : Bhi;
            uint32_t st = smb + ((st_c + 3) & 3) * STAGE_T;
#pragma unroll
            for (int i = 0; i < 4; i++) {
                cp_async16(st + so_[i],           As + (size_t)(m0 + gr0 + 32 * i) * D_ + kk + gc0);
                cp_async16(st + STAGE_A + so_[i], Bs + (size_t)(n0 + gr0 + 32 * i) * D_ + kk + gc0);
            }
        }
        cp_commit();                                     // empty group in tail keeps counts

        uint32_t sA = smb + st_c * STAGE_T;
        uint32_t sB = sA + STAGE_A;
#pragma unroll
        for (int ks = 0; ks < 2; ks++) {
            uint32_t a[4][4], b[4][4];
#pragma unroll
            for (int mt = 0; mt < 4; mt++) ldmat4(a[mt], sA + aoff[mt] + ks * 32);
#pragma unroll
            for (int np = 0; np < 4; np++) ldmat4(b[np], sB + boff[np] + ks * 32);
#pragma unroll
            for (int mt = 0; mt < 4; mt++)
#pragma unroll
                for (int nt = 0; nt < 8; nt++)
                    mma_bf16(acc[mt][nt], a[mt], b[nt >> 1][(nt & 1) * 2], b[nt >> 1][(nt & 1) * 2 + 1]);
        }
        st_c = (st_c + 1) & 3;
    }

    // epilogue: optional fused RoPE (acc pairs are exactly the (2i,2i+1) rope pairs)
    int tq = lane >> 2, tr = lane & 3;
#pragma unroll
    for (int mt = 0; mt < 4; mt++) {
#pragma unroll
        for (int nt = 0; nt < 8; nt++) {
            int m = m0 + wm * 64 + mt * 16 + tq;
            int n = n0 + wn * 64 + nt * 8 + tr * 2;
            float v0 = acc[mt][nt][0], v1 = acc[mt][nt][1];
            float v2 = acc[mt][nt][2], v3 = acc[mt][nt][3];
            if (rope_cos) {
                int i  = (n & 127) >> 1;
                int t1 = m & 4095, t2 = (m + 8) & 4095;
                float c1 = rope_cos[t1 * 64 + i], s1 = rope_sin[t1 * 64 + i];
                float c2 = rope_cos[t2 * 64 + i], s2 = rope_sin[t2 * 64 + i];
                float r0 = v0 * c1 - v1 * s1, r1 = v0 * s1 + v1 * c1;
                float r2 = v2 * c2 - v3 * s2, r3 = v2 * s2 + v3 * c2;
                v0 = r0; v1 = r1; v2 = r2; v3 = r3;
            }
            *(float2*)&C[(size_t)m * D_ + n]       = make_float2(v0, v1);
            *(float2*)&C[(size_t)(m + 8) * D_ + n] = make_float2(v2, v3);
        }
    }
}

// ---------------- fp32 -> bf16 hi/lo split ----------------
__global__ __launch_bounds__(256) void split_kernel(
    const float* __restrict__ a, __nv_bfloat16* __restrict__ hi, __nv_bfloat16* __restrict__ lo)
{
    size_t i = ((size_t)blockIdx.x * 256 + threadIdx.x) * 4;
    float4 v = *(const float4*)&a[i];
    __nv_bfloat16 h0 = __float2bfloat16(v.x), h1 = __float2bfloat16(v.y);
    __nv_bfloat16 h2 = __float2bfloat16(v.z), h3 = __float2bfloat16(v.w);
    __nv_bfloat16 l0 = __float2bfloat16(v.x - __bfloat162float(h0));
    __nv_bfloat16 l1 = __float2bfloat16(v.y - __bfloat162float(h1));
    __nv_bfloat16 l2 = __float2bfloat16(v.z - __bfloat162float(h2));
    __nv_bfloat16 l3 = __float2bfloat16(v.w - __bfloat162float(h3));
    __nv_bfloat162* hp = (__nv_bfloat162*)(hi + i);
    __nv_bfloat162* lp = (__nv_bfloat162*)(lo + i);
    hp[0] = __halves2bfloat162(h0, h1); hp[1] = __halves2bfloat162(h2, h3);
    lp[0] = __halves2bfloat162(l0, l1); lp[1] = __halves2bfloat162(l2, l3);
}

// ---------------- all 5 weights: W[K,N] -> Wt_hi/lo[N,K] transpose+split ----------------
__global__ __launch_bounds__(256) void wsplit_all(
    const float* __restrict__ W0, const float* __restrict__ W1,
    const float* __restrict__ W2, const float* __restrict__ W3,
    const float* __restrict__ W4,
    __nv_bfloat16* __restrict__ hi, __nv_bfloat16* __restrict__ lo)
{
    __shared__ float tile[32][33];
    int z = blockIdx.z;
    const float* W = (z == 0) ? W0 : (z == 1) ? W1 : (z == 2) ? W2 : (z == 3) ? W3 : W4;
    size_t off = (size_t)z * D_ * D_;
    int k0 = blockIdx.y * 32, n0 = blockIdx.x * 32;
    int tx = threadIdx.x & 31, ty = threadIdx.x >> 5;
#pragma unroll
    for (int i = 0; i < 32; i += 8)
        tile[ty + i][tx] = W[(size_t)(k0 + ty + i) * D_ + n0 + tx];
    __syncthreads();
#pragma unroll
    for (int i = 0; i < 32; i += 8) {
        float v = tile[tx][ty + i];
        __nv_bfloat16 h = __float2bfloat16(v);
        __nv_bfloat16 l = __float2bfloat16(v - __bfloat162float(h));
        size_t oi = off + (size_t)(n0 + ty + i) * D_ + k0 + tx;
        hi[oi] = h; lo[oi] = l;
    }
}

// ============================= retention =============================
__global__ __launch_bounds__(128) void gt_kernel(
    const float* __restrict__ x, const float* __restrict__ Wgt, float* __restrict__ gt)
{
    int row = blockIdx.x;
    int tid = threadIdx.x;
    const float* xr = x + (size_t)row * D_;
    float acc[16];
#pragma unroll
    for (int h = 0; h < 16; h++) acc[h] = 0.f;
    for (int kk = tid; kk < D_; kk += 128) {
        float xv = xr[kk];
        const float4* w4 = (const float4*)(Wgt + (size_t)kk * 16);
        float4 w0 = w4[0], w1 = w4[1], w2 = w4[2], w3 = w4[3];
        acc[0]  += xv * w0.x; acc[1]  += xv * w0.y; acc[2]  += xv * w0.z; acc[3]  += xv * w0.w;
        acc[4]  += xv * w1.x; acc[5]  += xv * w1.y; acc[6]  += xv * w1.z; acc[7]  += xv * w1.w;
        acc[8]  += xv * w2.x; acc[9]  += xv * w2.y; acc[10] += xv * w2.z; acc[11] += xv * w2.w;
        acc[12] += xv * w3.x; acc[13] += xv * w3.y; acc[14] += xv * w3.z; acc[15] += xv * w3.w;
    }
#pragma unroll
    for (int h = 0; h < 16; h++)
#pragma unroll
        for (int off = 16; off > 0; off >>= 1)
            acc[h] += __shfl_down_sync(0xffffffffu, acc[h], off);
    __shared__ float part[4][16];
    int warp = tid >> 5, lane = tid & 31;
    if (lane == 0)
#pragma unroll
        for (int h = 0; h < 16; h++) part[warp][h] = acc[h];
    __syncthreads();
    if (tid < 16) {
        float s = part[0][tid] + part[1][tid] + part[2][tid] + part[3][tid];
        int b = row >> 12, t = row & 4095;
        gt[((size_t)(b * H_ + tid)) * T_ + t] = log_sigmoidf(s) * (1.f / 16.f);
    }
}

__global__ __launch_bounds__(256) void cumsum_kernel(
    const float* __restrict__ gt, float* __restrict__ gc)
{
    int bh = blockIdx.x >> 4;
    int n  = blockIdx.x & 15;
    int tid = threadIdx.x, lane = tid & 31, warp = tid >> 5;
    size_t idx = (size_t)bh * T_ + n * CH_ + tid;
    float v = gt[idx];
#pragma unroll
    for (int off = 1; off < 32; off <<= 1) {
        float y = __shfl_up_sync(0xffffffffu, v, off);
        if (lane >= off) v += y;
    }
    __shared__ float ws[8];
    if (lane == 31) ws[warp] = v;
    __syncthreads();
    if (tid == 0) {
        float s = 0.f;
#pragma unroll
        for (int w = 0; w < 8; w++) { float t = ws[w]; ws[w] = s; s += t; }
    }
    __syncthreads();
    gc[idx] = v + ws[warp];
}

__global__ __launch_bounds__(256) void sin_kernel(
    const float* __restrict__ k, const float* __restrict__ v,
    const float* __restrict__ gc, float* __restrict__ Sin)
{
    __shared__ __align__(16) float Ks[32 * 128];
    __shared__ __align__(16) float Vs[32 * 128];
    __shared__ float kd[32];
    int blk = blockIdx.x;
    int n = blk & 15, h = (blk >> 4) & 15, b = blk >> 8;
    int tid = threadIdx.x;
    int trow = tid >> 4, tcol = tid & 15;
    const float* gcc = gc + ((size_t)(b * H_ + h)) * T_ + n * CH_;
    float gtot = gcc[CH_ - 1];

    float acc[8][8];
#pragma unroll
    for (int i = 0; i < 8; i++)
#pragma unroll
        for (int j = 0; j < 8; j++) acc[i][j] = 0.f;

    for (int s0 = 0; s0 < CH_; s0 += 32) {
        __syncthreads();
        if (tid < 32) kd[tid] = expf(gtot - gcc[s0 + tid]) * SCALE_;
        __syncthreads();
#pragma unroll
        for (int l = 0; l < 4; l++) {
            int li = tid + l * 256;
            int c = li >> 5, gcol = (li & 31) << 2;
            size_t gi = ((size_t)(b * T_ + n * CH_ + s0 + c)) * D_ + h * HD_ + gcol;
            float4 kv4 = *(const float4*)&k[gi];
            float sc = kd[c];
            kv4.x *= sc; kv4.y *= sc; kv4.z *= sc; kv4.w *= sc;
            *(float4*)&Ks[c * 128 + gcol] = kv4;
            *(float4*)&Vs[c * 128 + gcol] = *(const float4*)&v[gi];
        }
        __syncthreads();
#pragma unroll
        for (int c = 0; c < 32; c++) {
            float4 a0 = *(float4*)&Ks[c * 128 + trow * 8];
            float4 a1 = *(float4*)&Ks[c * 128 + trow * 8 + 4];
            float4 b0 = *(float4*)&Vs[c * 128 + tcol * 8];
            float4 b1 = *(float4*)&Vs[c * 128 + tcol * 8 + 4];
            float a[8] = {a0.x, a0.y, a0.z, a0.w, a1.x, a1.y, a1.z, a1.w};
            float bb[8] = {b0.x, b0.y, b0.z, b0.w, b1.x, b1.y, b1.z, b1.w};
#pragma unroll
            for (int i = 0; i < 8; i++)
#pragma unroll
                for (int j = 0; j < 8; j++) acc[i][j] += a[i] * bb[j];
        }
    }
    size_t base = (size_t)blk * (HD_ * HD_);
#pragma unroll
    for (int i = 0; i < 8; i++) {
        size_t oi = base + (size_t)(trow * 8 + i) * HD_ + tcol * 8;
        *(float4*)&Sin[oi]     = make_float4(acc[i][0], acc[i][1], acc[i][2], acc[i][3]);
        *(float4*)&Sin[oi + 4] = make_float4(acc[i][4], acc[i][5], acc[i][6], acc[i][7]);
    }
}

// parallel over (bh, 8 parts of the 16K state elements); serial only over 16 chunks
__global__ __launch_bounds__(256) void scan_kernel(
    const float* __restrict__ Sin, const float* __restrict__ gc, float* __restrict__ Spre)
{
    int blk = blockIdx.x;              // 256 = 32 bh x 8 parts
    int bh = blk >> 3, part = blk & 7;
    int e0 = part * 2048 + threadIdx.x;
    float S[8];
#pragma unroll
    for (int l = 0; l < 8; l++) S[l] = 0.f;
    for (int n = 0; n < NCH_; n++) {
        float cd = expf(gc[(size_t)bh * T_ + n * CH_ + (CH_ - 1)]);
        size_t base = ((size_t)(bh * NCH_ + n)) * (HD_ * HD_);
#pragma unroll
        for (int l = 0; l < 8; l++) {
            int idx = e0 + l * 256;
            Spre[base + idx] = S[l];
            S[l] = S[l] * cd + Sin[base + idx];
        }
    }
}

#define QS_OFF  0
#define BS_OFF  8192
#define SS_OFF  16384
#define GQ_OFF  20736
#define GK_OFF  20800
#define RED_OFF 20864
#define SMF_TOT 21888

__global__ __launch_bounds__(256) void out_kernel(
    const float* __restrict__ q, const float* __restrict__ k,
    const float* __restrict__ v, const float* __restrict__ g,
    const float* __restrict__ gc, const float* __restrict__ Spre,
    __nv_bfloat16* __restrict__ ohi, __nv_bfloat16* __restrict__ olo)
{
    extern __shared__ __align__(16) float sm[];
    float* Qs  = sm + QS_OFF;
    float* Bs  = sm + BS_OFF;
    float* Ss  = sm + SS_OFF;
    float* gq  = sm + GQ_OFF;
    float* gk  = sm + GK_OFF;
    float* red = sm + RED_OFF;

    int blk = blockIdx.x;
    int rt = blk & 3, n = (blk >> 2) & 15, h = (blk >> 6) & 15, b = blk >> 10;
    int tid = threadIdx.x, trow = tid >> 4, tcol = tid & 15;
    int trow4 = trow * 4;
    const float* gcc = gc + ((size_t)(b * H_ + h)) * T_ + n * CH_;
    int c0 = rt * 64;
    int rowbase = b * T_ + n * CH_;

#pragma unroll
    for (int l = 0; l < 8; l++) {
        int li = tid + l * 256;
        int c = li >> 5, gcol = (li & 31) << 2;
        size_t gi = ((size_t)(rowbase + c0 + c)) * D_ + h * HD_ + gcol;
        *(float4*)&Qs[c * 128 + gcol] = *(const float4*)&q[gi];
    }
    if (tid < 64) gq[tid] = gcc[c0 + tid];

    float oacc[4][8];
#pragma unroll
    for (int i = 0; i < 4; i++)
#pragma unroll
        for (int j = 0; j < 8; j++) oacc[i][j] = 0.f;
    __syncthreads();

    for (int st = 0; st <= rt; st++) {
        int s0 = st * 64;
#pragma unroll
        for (int l = 0; l < 8; l++) {
            int li = tid + l * 256;
            int c = li >> 5, gr = li & 31;
            size_t gi = ((size_t)(rowbase + s0 + c)) * D_ + h * HD_ + (gr << 2);
            *(float4*)&Bs[c * 128 + ((gr ^ (c & 7)) << 2)] = *(const float4*)&k[gi];
        }
        if (tid < 64) gk[tid] = gcc[s0 + tid];
        __syncthreads();

        float sacc[4][4];
#pragma unroll
        for (int i = 0; i < 4; i++)
#pragma unroll
            for (int j = 0; j < 4; j++) sacc[i][j] = 0.f;
#pragma unroll
        for (int gr = 0; gr < 32; gr++) {
            float4 a[4];
#pragma unroll
            for (int i = 0; i < 4; i++) a[i] = *(float4*)&Qs[(trow4 + i) * 128 + (gr << 2)];
#pragma unroll
            for (int j = 0; j < 4; j++) {
                int s = tcol * 4 + j;
                float4 bb = *(float4*)&Bs[s * 128 + ((gr ^ (s & 7)) << 2)];
#pragma unroll
                for (int i = 0; i < 4; i++)
                    sacc[i][j] += a[i].x * bb.x + a[i].y * bb.y + a[i].z * bb.z + a[i].w * bb.w;
            }
        }
#pragma unroll
        for (int i = 0; i < 4; i++) {
            int r = trow4 + i;
            float gqi = gq[r];
#pragma unroll
            for (int j = 0; j < 4; j++) {
                int s = tcol * 4 + j;
                float val = 0.f;
                if (s0 + s <= c0 + r) val = sacc[i][j] * SCALE_ * expf(gqi - gk[s]);
                Ss[r * 68 + s] = val;
            }
        }
        __syncthreads();

#pragma unroll
        for (int l = 0; l < 8; l++) {
            int li = tid + l * 256;
            int c = li >> 5, gr = li & 31;
            size_t gi = ((size_t)(rowbase + s0 + c)) * D_ + h * HD_ + (gr << 2);
            *(float4*)&Bs[c * 128 + ((gr ^ (c & 7)) << 2)] = *(const float4*)&v[gi];
        }
        __syncthreads();

#pragma unroll
        for (int s = 0; s < 64; s++) {
            float4 b0 = *(float4*)&Bs[s * 128 + (((2 * tcol)     ^ (s & 7)) << 2)];
            float4 b1 = *(float4*)&Bs[s * 128 + (((2 * tcol + 1) ^ (s & 7)) << 2)];
#pragma unroll
            for (int i = 0; i < 4; i++) {
                float a = Ss[(trow4 + i) * 68 + s];
                oacc[i][0] += a * b0.x; oacc[i][1] += a * b0.y;
                oacc[i][2] += a * b0.z; oacc[i][3] += a * b0.w;
                oacc[i][4] += a * b1.x; oacc[i][5] += a * b1.y;
                oacc[i][6] += a * b1.z; oacc[i][7] += a * b1.w;
            }
        }
        __syncthreads();
    }

    float qd[4];
#pragma unroll
    for (int i = 0; i < 4; i++) qd[i] = expf(gq[trow4 + i]);
    size_t sbase = ((size_t)(blk >> 2)) * (HD_ * HD_);
    for (int d0 = 0; d0 < 128; d0 += 64) {
#pragma unroll
        for (int l = 0; l < 8; l++) {
            int li = tid + l * 256;
            int dd = li >> 5, gr = li & 31;
            *(float4*)&Bs[dd * 128 + ((gr ^ (dd & 7)) << 2)] =
                *(const float4*)&Spre[sbase + (size_t)(d0 + dd) * 128 + (gr << 2)];
        }
        __syncthreads();
#pragma unroll
        for (int dd = 0; dd < 64; dd++) {
            float4 b0 = *(float4*)&Bs[dd * 128 + (((2 * tcol)     ^ (dd & 7)) << 2)];
            float4 b1 = *(float4*)&Bs[dd * 128 + (((2 * tcol + 1) ^ (dd & 7)) << 2)];
#pragma unroll
            for (int i = 0; i < 4; i++) {
                float a = Qs[(trow4 + i) * 128 + d0 + dd] * qd[i];
                oacc[i][0] += a * b0.x; oacc[i][1] += a * b0.y;
                oacc[i][2] += a * b0.z; oacc[i][3] += a * b0.w;
                oacc[i][4] += a * b1.x; oacc[i][5] += a * b1.y;
                oacc[i][6] += a * b1.z; oacc[i][7] += a * b1.w;
            }
        }
        __syncthreads();
    }

#pragma unroll
    for (int i = 0; i < 4; i++) {
        float ss = 0.f;
#pragma unroll
        for (int j = 0; j < 8; j++) ss += oacc[i][j] * oacc[i][j];
        red[(trow4 + i) * 16 + tcol] = ss;
    }
    __syncthreads();
#pragma unroll
    for (int i = 0; i < 4; i++) {
        int r = trow4 + i;
        float ss = 0.f;
#pragma unroll
        for (int t2 = 0; t2 < 16; t2++) ss += red[r * 16 + t2];
        float rn = rsqrtf(ss * (1.0f / 128.0f) + 1e-5f);
        size_t gi = ((size_t)(rowbase + c0 + r)) * D_ + h * HD_ + tcol * 8;
        float4 g0 = *(const float4*)&g[gi];
        float4 g1 = *(const float4*)&g[gi + 4];
        float ov[8];
        ov[0] = oacc[i][0] * rn * (g0.x / (1.f + expf(-g0.x)));
        ov[1] = oacc[i][1] * rn * (g0.y / (1.f + expf(-g0.y)));
        ov[2] = oacc[i][2] * rn * (g0.z / (1.f + expf(-g0.z)));
        ov[3] = oacc[i][3] * rn * (g0.w / (1.f + expf(-g0.w)));
        ov[4] = oacc[i][4] * rn * (g1.x / (1.f + expf(-g1.x)));
        ov[5] = oacc[i][5] * rn * (g1.y / (1.f + expf(-g1.y)));
        ov[6] = oacc[i][6] * rn * (g1.z / (1.f + expf(-g1.z)));
        ov[7] = oacc[i][7] * rn * (g1.w / (1.f + expf(-g1.w)));
        __nv_bfloat162 hv[4], lv[4];
#pragma unroll
        for (int j = 0; j < 4; j++) {
            __nv_bfloat16 h0 = __float2bfloat16(ov[2*j]);
            __nv_bfloat16 h1 = __float2bfloat16(ov[2*j+1]);
            __nv_bfloat16 l0 = __float2bfloat16(ov[2*j]   - __bfloat162float(h0));
            __nv_bfloat16 l1 = __float2bfloat16(ov[2*j+1] - __bfloat162float(h1));
            hv[j] = __halves2bfloat162(h0, h1);
            lv[j] = __halves2bfloat162(l0, l1);
        }
        *(uint4*)&ohi[gi] = *(uint4*)hv;
        *(uint4*)&olo[gi] = *(uint4*)lv;
    }
}

// ============================= launcher =============================
extern "C" void kernel_launch(void* const* d_in, const int* in_sizes, int n_in,
                              void* d_out, int out_size)
{
    const float* x    = (const float*)d_in[0];
    const float* cosb = (const float*)d_in[1];
    const float* sinb = (const float*)d_in[2];
    const float* Wq   = (const float*)d_in[3];
    const float* Wk   = (const float*)d_in[4];
    const float* Wv   = (const float*)d_in[5];
    const float* Wg   = (const float*)d_in[6];
    const float* Wgt  = (const float*)d_in[7];
    const float* Wout = (const float*)d_in[8];
    float* out = (float*)d_out;

    float *q, *k, *v, *g, *gt, *gc, *sbuf, *spre;
    __nv_bfloat16 *xhi, *xlo, *ohi, *olo, *wthi, *wtlo;
    cudaGetSymbolAddress((void**)&q,    g_q);
    cudaGetSymbolAddress((void**)&k,    g_k);
    cudaGetSymbolAddress((void**)&v,    g_v);
    cudaGetSymbolAddress((void**)&g,    g_g);
    cudaGetSymbolAddress((void**)&gt,   g_gt);
    cudaGetSymbolAddress((void**)&gc,   g_gc);
    cudaGetSymbolAddress((void**)&sbuf, g_sinbuf);
    cudaGetSymbolAddress((void**)&spre, g_sprebuf);
    cudaGetSymbolAddress((void**)&xhi,  g_xhi);
    cudaGetSymbolAddress((void**)&xlo,  g_xlo);
    cudaGetSymbolAddress((void**)&ohi,  g_ohi);
    cudaGetSymbolAddress((void**)&olo,  g_olo);
    cudaGetSymbolAddress((void**)&wthi, g_wthi);
    cudaGetSymbolAddress((void**)&wtlo, g_wtlo);

    cudaFuncSetAttribute(out_kernel, cudaFuncAttributeMaxDynamicSharedMemorySize,
                         SMF_TOT * sizeof(float));
    cudaFuncSetAttribute(tc_gemm, cudaFuncAttributeMaxDynamicSharedMemorySize, TCG_SMEM);

    const size_t WSZ = (size_t)D_ * D_;
    dim3 wgrid(D_ / 32, D_ / 32, 5);
    dim3 ggrid(D_ / 128, BT_ / 128);   // (16, 64)

    wsplit_all<<<wgrid, 256>>>(Wq, Wk, Wv, Wg, Wout, wthi, wtlo);        // 1
    split_kernel<<<(BT_ * (D_ / 4)) / 256, 256>>>(x, xhi, xlo);          // 2

    tc_gemm<<<ggrid, 128, TCG_SMEM>>>(xhi, xlo, wthi + 0 * WSZ, wtlo + 0 * WSZ, q, cosb, sinb); // 3
    tc_gemm<<<ggrid, 128, TCG_SMEM>>>(xhi, xlo, wthi + 1 * WSZ, wtlo + 1 * WSZ, k, cosb, sinb); // 4
    tc_gemm<<<ggrid, 128, TCG_SMEM>>>(xhi, xlo, wthi + 2 * WSZ, wtlo + 2 * WSZ, v, nullptr, nullptr); // 5
    tc_gemm<<<ggrid, 128, TCG_SMEM>>>(xhi, xlo, wthi + 3 * WSZ, wtlo + 3 * WSZ, g, nullptr, nullptr); // 6 <- ncu
    gt_kernel<<<BT_, 128>>>(x, Wgt, gt);
    cumsum_kernel<<<B_ * H_ * NCH_, 256>>>(gt, gc);
    sin_kernel<<<B_ * H_ * NCH_, 256>>>(k, v, gc, sbuf);
    scan_kernel<<<B_ * H_ * 8, 256>>>(sbuf, gc, spre);
    out_kernel<<<B_ * H_ * NCH_ * 4, 256, SMF_TOT * sizeof(float)>>>(q, k, v, g, gc, spre, ohi, olo);

    tc_gemm<<<ggrid, 128, TCG_SMEM>>>(ohi, olo, wthi + 4 * WSZ, wtlo + 4 * WSZ, out, nullptr, nullptr);
}

// round 8
// speedup vs baseline: 2.2034x; 1.0270x over previous
#include <cuda_runtime.h>
#include <cuda_bf16.h>
#include <cstdint>

#define B_   2
#define T_   4096
#define D_   2048
#define H_   16
#define HD_  128
#define CH_  256
#define NCH_ 16
#define BT_  (B_*T_)
#define SCALE_ 0.08838834764831845f

// ---------------- scratch ----------------
__device__ float g_q[(size_t)BT_*D_];
__device__ float g_k[(size_t)BT_*D_];
__device__ float g_v[(size_t)BT_*D_];
__device__ float g_g[(size_t)BT_*D_];
__device__ float g_gt[B_*H_*T_];
__device__ float g_gc[B_*H_*T_];
__device__ float g_sinbuf [(size_t)B_*H_*NCH_*HD_*HD_];
__device__ float g_sprebuf[(size_t)B_*H_*NCH_*HD_*HD_];
__device__ __nv_bfloat16 g_xhi[(size_t)BT_*D_];
__device__ __nv_bfloat16 g_xlo[(size_t)BT_*D_];
__device__ __nv_bfloat16 g_ohi[(size_t)BT_*D_];
__device__ __nv_bfloat16 g_olo[(size_t)BT_*D_];
__device__ __nv_bfloat16 g_wthi[5*(size_t)D_*D_];   // W^T [N,K]: q,k,v,g,out
__device__ __nv_bfloat16 g_wtlo[5*(size_t)D_*D_];

__device__ __forceinline__ float log_sigmoidf(float z) {
    return (z >= 0.f) ? -log1pf(expf(-z)) : (z - log1pf(expf(z)));
}

// ============================= MMA helpers =============================
__device__ __forceinline__ uint32_t smem_u32(const void* p) {
    uint32_t a;
    asm("{ .reg .u64 t; cvta.to.shared.u64 t, %1; cvt.u32.u64 %0, t; }" : "=r"(a) : "l"(p));
    return a;
}
__device__ __forceinline__ void cp_async16(uint32_t s, const void* g) {
    asm volatile("cp.async.cg.shared.global [%0], [%1], 16;" :: "r"(s), "l"(g));
}
__device__ __forceinline__ void cp_commit() { asm volatile("cp.async.commit_group;"); }
template<int N> __device__ __forceinline__ void cp_wait() {
    asm volatile("cp.async.wait_group %0;" :: "n"(N));
}
__device__ __forceinline__ void ldmat4(uint32_t* r, uint32_t a) {
    asm volatile("ldmatrix.sync.aligned.m8n8.x4.shared.b16 {%0,%1,%2,%3}, [%4];"
        : "=r"(r[0]), "=r"(r[1]), "=r"(r[2]), "=r"(r[3]) : "r"(a));
}
__device__ __forceinline__ void mma_bf16(float* d, const uint32_t* a, uint32_t b0, uint32_t b1) {
    asm volatile(
        "mma.sync.aligned.m16n8k16.row.col.f32.bf16.bf16.f32 "
        "{%0,%1,%2,%3}, {%4,%5,%6,%7}, {%8,%9}, {%0,%1,%2,%3};"
        : "+f"(d[0]), "+f"(d[1]), "+f"(d[2]), "+f"(d[3])
        : "r"(a[0]), "r"(a[1]), "r"(a[2]), "r"(a[3]), "r"(b0), "r"(b1));
}

// ============================= tensor-core GEMM =============================
// C[M,2048] = (Ahi+Alo)[M,2048] @ (Bhi+Blo)^T, B operands [N,K] row-major.
// 128x128 CTA tile, BK=64 (amortizes the measured ~700cyc/chunk fixed overhead),
// 4 warps (2x2), warp tile 64x64. 3-stage cp.async pipeline, issue distance 2,
// one __syncthreads per chunk, 2 CTAs/SM (2x108KB smem).
#define LDS_ROW 72                      // bf16 per smem row (144 B; 4-bank row stride, 16B aligned)
#define STAGE_A (128 * LDS_ROW * 2)     // 18432 B
#define STAGE_T (2 * STAGE_A)           // 36864 B (A + B)
#define NSTG3   3
#define TCG_SMEM (NSTG3 * STAGE_T)      // 110592 B

__global__ void __launch_bounds__(128, 2) tc_gemm(
    const __nv_bfloat16* __restrict__ Ahi, const __nv_bfloat16* __restrict__ Alo,
    const __nv_bfloat16* __restrict__ Bhi, const __nv_bfloat16* __restrict__ Blo,
    float* __restrict__ C,
    const float* __restrict__ rope_cos, const float* __restrict__ rope_sin)
{
    extern __shared__ __align__(16) char smem[];
    const uint32_t smb = smem_u32(smem);

    int tid = threadIdx.x, lane = tid & 31, wid = tid >> 5;
    int wm = wid >> 1, wn = wid & 1;                     // 2 x 2 warp grid
    int m0 = blockIdx.y * 128, n0 = blockIdx.x * 128;

    // global loads: 128 rows x 64 bf16 per operand per chunk = 1024 vec16; 8/thread/operand
    int row_t = tid >> 3;                                // 0..15
    int col_t = (tid & 7) << 3;                          // bf16 col 0..56
    uint32_t so_[8];
#pragma unroll
    for (int i = 0; i < 8; i++)
        so_[i] = (uint32_t)((row_t + 16 * i) * (LDS_ROW * 2) + col_t * 2);

    uint32_t aoff[4];
#pragma unroll
    for (int mt = 0; mt < 4; mt++)
        aoff[mt] = (uint32_t)(((wm * 64 + mt * 16 + (lane & 15)) * LDS_ROW + ((lane >> 4) << 3)) * 2);
    uint32_t boff[4];
    {
        int q = lane >> 3, r = lane & 7;
#pragma unroll
        for (int np = 0; np < 4; np++) {
            int n = wn * 64 + np * 16 + ((q >> 1) << 3) + r;
            int kc = (q & 1) << 3;
            boff[np] = (uint32_t)((n * LDS_ROW + kc) * 2);
        }
    }

    float acc[4][8][4];
#pragma unroll
    for (int i = 0; i < 4; i++)
#pragma unroll
        for (int j = 0; j < 8; j++)
#pragma unroll
            for (int e = 0; e < 4; e++) acc[i][j][e] = 0.f;

    const int NCHUNK = 96;                               // 3 passes x 32 (BK=64)

    // prologue: issue chunks 0,1 (pass 0 => Ahi/Bhi)
#pragma unroll
    for (int pc = 0; pc < 2; pc++) {
        int kk = pc << 6;
        uint32_t st = smb + pc * STAGE_T;
#pragma unroll
        for (int i = 0; i < 8; i++) {
            cp_async16(st + so_[i],           Ahi + (size_t)(m0 + row_t + 16 * i) * D_ + kk + col_t);
            cp_async16(st + STAGE_A + so_[i], Bhi + (size_t)(n0 + row_t + 16 * i) * D_ + kk + col_t);
        }
        cp_commit();
    }

    int st_c = 0;                                        // stage of chunk c
    for (int c = 0; c < NCHUNK; c++) {
        cp_wait<1>();                                    // chunk c resident (this thread)
        __syncthreads();                                 // visible; stage (c-1)%3 compute done

        int cn = c + 2;
        if (cn < NCHUNK) {
            int pass = cn >> 5;
            int kk = (cn & 31) << 6;
            const __nv_bfloat16* As = (pass == 1) ? Alo : Ahi;
            const __nv_bfloat16* Bs = (pass == 2) ? Blo : Bhi;
            int stn = st_c + 2; if (stn >= NSTG3) stn -= NSTG3;   // == (c-1)%3
            uint32_t st = smb + stn * STAGE_T;
#pragma unroll
            for (int i = 0; i < 8; i++) {
                cp_async16(st + so_[i],           As + (size_t)(m0 + row_t + 16 * i) * D_ + kk + col_t);
                cp_async16(st + STAGE_A + so_[i], Bs + (size_t)(n0 + row_t + 16 * i) * D_ + kk + col_t);
            }
        }
        cp_commit();                                     // empty group in tail keeps counts

        uint32_t sA = smb + st_c * STAGE_T;
        uint32_t sB = sA + STAGE_A;
#pragma unroll
        for (int ks = 0; ks < 4; ks++) {
            uint32_t a[4][4], b[4][4];
#pragma unroll
            for (int mt = 0; mt < 4; mt++) ldmat4(a[mt], sA + aoff[mt] + ks * 32);
#pragma unroll
            for (int np = 0; np < 4; np++) ldmat4(b[np], sB + boff[np] + ks * 32);
#pragma unroll
            for (int mt = 0; mt < 4; mt++)
#pragma unroll
                for (int nt = 0; nt < 8; nt++)
                    mma_bf16(acc[mt][nt], a[mt], b[nt >> 1][(nt & 1) * 2], b[nt >> 1][(nt & 1) * 2 + 1]);
        }
        st_c = (st_c + 1 == NSTG3) ? 0 : st_c + 1;
    }

    // epilogue: optional fused RoPE (acc pairs are exactly the (2i,2i+1) rope pairs)
    int tq = lane >> 2, tr = lane & 3;
#pragma unroll
    for (int mt = 0; mt < 4; mt++) {
#pragma unroll
        for (int nt = 0; nt < 8; nt++) {
            int m = m0 + wm * 64 + mt * 16 + tq;
            int n = n0 + wn * 64 + nt * 8 + tr * 2;
            float v0 = acc[mt][nt][0], v1 = acc[mt][nt][1];
            float v2 = acc[mt][nt][2], v3 = acc[mt][nt][3];
            if (rope_cos) {
                int i  = (n & 127) >> 1;
                int t1 = m & 4095, t2 = (m + 8) & 4095;
                float c1 = rope_cos[t1 * 64 + i], s1 = rope_sin[t1 * 64 + i];
                float c2 = rope_cos[t2 * 64 + i], s2 = rope_sin[t2 * 64 + i];
                float r0 = v0 * c1 - v1 * s1, r1 = v0 * s1 + v1 * c1;
                float r2 = v2 * c2 - v3 * s2, r3 = v2 * s2 + v3 * c2;
                v0 = r0; v1 = r1; v2 = r2; v3 = r3;
            }
            *(float2*)&C[(size_t)m * D_ + n]       = make_float2(v0, v1);
            *(float2*)&C[(size_t)(m + 8) * D_ + n] = make_float2(v2, v3);
        }
    }
}

// ---------------- fp32 -> bf16 hi/lo split ----------------
__global__ __launch_bounds__(256) void split_kernel(
    const float* __restrict__ a, __nv_bfloat16* __restrict__ hi, __nv_bfloat16* __restrict__ lo)
{
    size_t i = ((size_t)blockIdx.x * 256 + threadIdx.x) * 4;
    float4 v = *(const float4*)&a[i];
    __nv_bfloat16 h0 = __float2bfloat16(v.x), h1 = __float2bfloat16(v.y);
    __nv_bfloat16 h2 = __float2bfloat16(v.z), h3 = __float2bfloat16(v.w);
    __nv_bfloat16 l0 = __float2bfloat16(v.x - __bfloat162float(h0));
    __nv_bfloat16 l1 = __float2bfloat16(v.y - __bfloat162float(h1));
    __nv_bfloat16 l2 = __float2bfloat16(v.z - __bfloat162float(h2));
    __nv_bfloat16 l3 = __float2bfloat16(v.w - __bfloat162float(h3));
    __nv_bfloat162* hp = (__nv_bfloat162*)(hi + i);
    __nv_bfloat162* lp = (__nv_bfloat162*)(lo + i);
    hp[0] = __halves2bfloat162(h0, h1); hp[1] = __halves2bfloat162(h2, h3);
    lp[0] = __halves2bfloat162(l0, l1); lp[1] = __halves2bfloat162(l2, l3);
}

// ---------------- all 5 weights: W[K,N] -> Wt_hi/lo[N,K] transpose+split ----------------
__global__ __launch_bounds__(256) void wsplit_all(
    const float* __restrict__ W0, const float* __restrict__ W1,
    const float* __restrict__ W2, const float* __restrict__ W3,
    const float* __restrict__ W4,
    __nv_bfloat16* __restrict__ hi, __nv_bfloat16* __restrict__ lo)
{
    __shared__ float tile[32][33];
    int z = blockIdx.z;
    const float* W = (z == 0) ? W0 : (z == 1) ? W1 : (z == 2) ? W2 : (z == 3) ? W3 : W4;
    size_t off = (size_t)z * D_ * D_;
    int k0 = blockIdx.y * 32, n0 = blockIdx.x * 32;
    int tx = threadIdx.x & 31, ty = threadIdx.x >> 5;
#pragma unroll
    for (int i = 0; i < 32; i += 8)
        tile[ty + i][tx] = W[(size_t)(k0 + ty + i) * D_ + n0 + tx];
    __syncthreads();
#pragma unroll
    for (int i = 0; i < 32; i += 8) {
        float v = tile[tx][ty + i];
        __nv_bfloat16 h = __float2bfloat16(v);
        __nv_bfloat16 l = __float2bfloat16(v - __bfloat162float(h));
        size_t oi = off + (size_t)(n0 + ty + i) * D_ + k0 + tx;
        hi[oi] = h; lo[oi] = l;
    }
}

// ============================= retention =============================
__global__ __launch_bounds__(128) void gt_kernel(
    const float* __restrict__ x, const float* __restrict__ Wgt, float* __restrict__ gt)
{
    int row = blockIdx.x;
    int tid = threadIdx.x;
    const float* xr = x + (size_t)row * D_;
    float acc[16];
#pragma unroll
    for (int h = 0; h < 16; h++) acc[h] = 0.f;
    for (int kk = tid; kk < D_; kk += 128) {
        float xv = xr[kk];
        const float4* w4 = (const float4*)(Wgt + (size_t)kk * 16);
        float4 w0 = w4[0], w1 = w4[1], w2 = w4[2], w3 = w4[3];
        acc[0]  += xv * w0.x; acc[1]  += xv * w0.y; acc[2]  += xv * w0.z; acc[3]  += xv * w0.w;
        acc[4]  += xv * w1.x; acc[5]  += xv * w1.y; acc[6]  += xv * w1.z; acc[7]  += xv * w1.w;
        acc[8]  += xv * w2.x; acc[9]  += xv * w2.y; acc[10] += xv * w2.z; acc[11] += xv * w2.w;
        acc[12] += xv * w3.x; acc[13] += xv * w3.y; acc[14] += xv * w3.z; acc[15] += xv * w3.w;
    }
#pragma unroll
    for (int h = 0; h < 16; h++)
#pragma unroll
        for (int off = 16; off > 0; off >>= 1)
            acc[h] += __shfl_down_sync(0xffffffffu, acc[h], off);
    __shared__ float part[4][16];
    int warp = tid >> 5, lane = tid & 31;
    if (lane == 0)
#pragma unroll
        for (int h = 0; h < 16; h++) part[warp][h] = acc[h];
    __syncthreads();
    if (tid < 16) {
        float s = part[0][tid] + part[1][tid] + part[2][tid] + part[3][tid];
        int b = row >> 12, t = row & 4095;
        gt[((size_t)(b * H_ + tid)) * T_ + t] = log_sigmoidf(s) * (1.f / 16.f);
    }
}

__global__ __launch_bounds__(256) void cumsum_kernel(
    const float* __restrict__ gt, float* __restrict__ gc)
{
    int bh = blockIdx.x >> 4;
    int n  = blockIdx.x & 15;
    int tid = threadIdx.x, lane = tid & 31, warp = tid >> 5;
    size_t idx = (size_t)bh * T_ + n * CH_ + tid;
    float v = gt[idx];
#pragma unroll
    for (int off = 1; off < 32; off <<= 1) {
        float y = __shfl_up_sync(0xffffffffu, v, off);
        if (lane >= off) v += y;
    }
    __shared__ float ws[8];
    if (lane == 31) ws[warp] = v;
    __syncthreads();
    if (tid == 0) {
        float s = 0.f;
#pragma unroll
        for (int w = 0; w < 8; w++) { float t = ws[w]; ws[w] = s; s += t; }
    }
    __syncthreads();
    gc[idx] = v + ws[warp];
}

__global__ __launch_bounds__(256) void sin_kernel(
    const float* __restrict__ k, const float* __restrict__ v,
    const float* __restrict__ gc, float* __restrict__ Sin)
{
    __shared__ __align__(16) float Ks[32 * 128];
    __shared__ __align__(16) float Vs[32 * 128];
    __shared__ float kd[32];
    int blk = blockIdx.x;
    int n = blk & 15, h = (blk >> 4) & 15, b = blk >> 8;
    int tid = threadIdx.x;
    int trow = tid >> 4, tcol = tid & 15;
    const float* gcc = gc + ((size_t)(b * H_ + h)) * T_ + n * CH_;
    float gtot = gcc[CH_ - 1];

    float acc[8][8];
#pragma unroll
    for (int i = 0; i < 8; i++)
#pragma unroll
        for (int j = 0; j < 8; j++) acc[i][j] = 0.f;

    for (int s0 = 0; s0 < CH_; s0 += 32) {
        __syncthreads();
        if (tid < 32) kd[tid] = expf(gtot - gcc[s0 + tid]) * SCALE_;
        __syncthreads();
#pragma unroll
        for (int l = 0; l < 4; l++) {
            int li = tid + l * 256;
            int c = li >> 5, gcol = (li & 31) << 2;
            size_t gi = ((size_t)(b * T_ + n * CH_ + s0 + c)) * D_ + h * HD_ + gcol;
            float4 kv4 = *(const float4*)&k[gi];
            float sc = kd[c];
            kv4.x *= sc; kv4.y *= sc; kv4.z *= sc; kv4.w *= sc;
            *(float4*)&Ks[c * 128 + gcol] = kv4;
            *(float4*)&Vs[c * 128 + gcol] = *(const float4*)&v[gi];
        }
        __syncthreads();
#pragma unroll
        for (int c = 0; c < 32; c++) {
            float4 a0 = *(float4*)&Ks[c * 128 + trow * 8];
            float4 a1 = *(float4*)&Ks[c * 128 + trow * 8 + 4];
            float4 b0 = *(float4*)&Vs[c * 128 + tcol * 8];
            float4 b1 = *(float4*)&Vs[c * 128 + tcol * 8 + 4];
            float a[8] = {a0.x, a0.y, a0.z, a0.w, a1.x, a1.y, a1.z, a1.w};
            float bb[8] = {b0.x, b0.y, b0.z, b0.w, b1.x, b1.y, b1.z, b1.w};
#pragma unroll
            for (int i = 0; i < 8; i++)
#pragma unroll
                for (int j = 0; j < 8; j++) acc[i][j] += a[i] * bb[j];
        }
    }
    size_t base = (size_t)blk * (HD_ * HD_);
#pragma unroll
    for (int i = 0; i < 8; i++) {
        size_t oi = base + (size_t)(trow * 8 + i) * HD_ + tcol * 8;
        *(float4*)&Sin[oi]     = make_float4(acc[i][0], acc[i][1], acc[i][2], acc[i][3]);
        *(float4*)&Sin[oi + 4] = make_float4(acc[i][4], acc[i][5], acc[i][6], acc[i][7]);
    }
}

// parallel over (bh, 8 parts of the 16K state elements); serial only over 16 chunks
__global__ __launch_bounds__(256) void scan_kernel(
    const float* __restrict__ Sin, const float* __restrict__ gc, float* __restrict__ Spre)
{
    int blk = blockIdx.x;              // 256 = 32 bh x 8 parts
    int bh = blk >> 3, part = blk & 7;
    int e0 = part * 2048 + threadIdx.x;
    float S[8];
#pragma unroll
    for (int l = 0; l < 8; l++) S[l] = 0.f;
    for (int n = 0; n < NCH_; n++) {
        float cd = expf(gc[(size_t)bh * T_ + n * CH_ + (CH_ - 1)]);
        size_t base = ((size_t)(bh * NCH_ + n)) * (HD_ * HD_);
#pragma unroll
        for (int l = 0; l < 8; l++) {
            int idx = e0 + l * 256;
            Spre[base + idx] = S[l];
            S[l] = S[l] * cd + Sin[base + idx];
        }
    }
}

#define QS_OFF  0
#define BS_OFF  8192
#define SS_OFF  16384
#define GQ_OFF  20736
#define GK_OFF  20800
#define RED_OFF 20864
#define SMF_TOT 21888

__global__ __launch_bounds__(256) void out_kernel(
    const float* __restrict__ q, const float* __restrict__ k,
    const float* __restrict__ v, const float* __restrict__ g,
    const float* __restrict__ gc, const float* __restrict__ Spre,
    __nv_bfloat16* __restrict__ ohi, __nv_bfloat16* __restrict__ olo)
{
    extern __shared__ __align__(16) float sm[];
    float* Qs  = sm + QS_OFF;
    float* Bs  = sm + BS_OFF;
    float* Ss  = sm + SS_OFF;
    float* gq  = sm + GQ_OFF;
    float* gk  = sm + GK_OFF;
    float* red = sm + RED_OFF;

    int blk = blockIdx.x;
    int rt = blk & 3, n = (blk >> 2) & 15, h = (blk >> 6) & 15, b = blk >> 10;
    int tid = threadIdx.x, trow = tid >> 4, tcol = tid & 15;
    int trow4 = trow * 4;
    const float* gcc = gc + ((size_t)(b * H_ + h)) * T_ + n * CH_;
    int c0 = rt * 64;
    int rowbase = b * T_ + n * CH_;

#pragma unroll
    for (int l = 0; l < 8; l++) {
        int li = tid + l * 256;
        int c = li >> 5, gcol = (li & 31) << 2;
        size_t gi = ((size_t)(rowbase + c0 + c)) * D_ + h * HD_ + gcol;
        *(float4*)&Qs[c * 128 + gcol] = *(const float4*)&q[gi];
    }
    if (tid < 64) gq[tid] = gcc[c0 + tid];

    float oacc[4][8];
#pragma unroll
    for (int i = 0; i < 4; i++)
#pragma unroll
        for (int j = 0; j < 8; j++) oacc[i][j] = 0.f;
    __syncthreads();

    for (int st = 0; st <= rt; st++) {
        int s0 = st * 64;
#pragma unroll
        for (int l = 0; l < 8; l++) {
            int li = tid + l * 256;
            int c = li >> 5, gr = li & 31;
            size_t gi = ((size_t)(rowbase + s0 + c)) * D_ + h * HD_ + (gr << 2);
            *(float4*)&Bs[c * 128 + ((gr ^ (c & 7)) << 2)] = *(const float4*)&k[gi];
        }
        if (tid < 64) gk[tid] = gcc[s0 + tid];
        __syncthreads();

        float sacc[4][4];
#pragma unroll
        for (int i = 0; i < 4; i++)
#pragma unroll
            for (int j = 0; j < 4; j++) sacc[i][j] = 0.f;
#pragma unroll
        for (int gr = 0; gr < 32; gr++) {
            float4 a[4];
#pragma unroll
            for (int i = 0; i < 4; i++) a[i] = *(float4*)&Qs[(trow4 + i) * 128 + (gr << 2)];
#pragma unroll
            for (int j = 0; j < 4; j++) {
                int s = tcol * 4 + j;
                float4 bb = *(float4*)&Bs[s * 128 + ((gr ^ (s & 7)) << 2)];
#pragma unroll
                for (int i = 0; i < 4; i++)
                    sacc[i][j] += a[i].x * bb.x + a[i].y * bb.y + a[i].z * bb.z + a[i].w * bb.w;
            }
        }
#pragma unroll
        for (int i = 0; i < 4; i++) {
            int r = trow4 + i;
            float gqi = gq[r];
#pragma unroll
            for (int j = 0; j < 4; j++) {
                int s = tcol * 4 + j;
                float val = 0.f;
                if (s0 + s <= c0 + r) val = sacc[i][j] * SCALE_ * expf(gqi - gk[s]);
                Ss[r * 68 + s] = val;
            }
        }
        __syncthreads();

#pragma unroll
        for (int l = 0; l < 8; l++) {
            int li = tid + l * 256;
            int c = li >> 5, gr = li & 31;
            size_t gi = ((size_t)(rowbase + s0 + c)) * D_ + h * HD_ + (gr << 2);
            *(float4*)&Bs[c * 128 + ((gr ^ (c & 7)) << 2)] = *(const float4*)&v[gi];
        }
        __syncthreads();

#pragma unroll
        for (int s = 0; s < 64; s++) {
            float4 b0 = *(float4*)&Bs[s * 128 + (((2 * tcol)     ^ (s & 7)) << 2)];
            float4 b1 = *(float4*)&Bs[s * 128 + (((2 * tcol + 1) ^ (s & 7)) << 2)];
#pragma unroll
            for (int i = 0; i < 4; i++) {
                float a = Ss[(trow4 + i) * 68 + s];
                oacc[i][0] += a * b0.x; oacc[i][1] += a * b0.y;
                oacc[i][2] += a * b0.z; oacc[i][3] += a * b0.w;
                oacc[i][4] += a * b1.x; oacc[i][5] += a * b1.y;
                oacc[i][6] += a * b1.z; oacc[i][7] += a * b1.w;
            }
        }
        __syncthreads();
    }

    float qd[4];
#pragma unroll
    for (int i = 0; i < 4; i++) qd[i] = expf(gq[trow4 + i]);
    size_t sbase = ((size_t)(blk >> 2)) * (HD_ * HD_);
    for (int d0 = 0; d0 < 128; d0 += 64) {
#pragma unroll
        for (int l = 0; l < 8; l++) {
            int li = tid + l * 256;
            int dd = li >> 5, gr = li & 31;
            *(float4*)&Bs[dd * 128 + ((gr ^ (dd & 7)) << 2)] =
                *(const float4*)&Spre[sbase + (size_t)(d0 + dd) * 128 + (gr << 2)];
        }
        __syncthreads();
#pragma unroll
        for (int dd = 0; dd < 64; dd++) {
            float4 b0 = *(float4*)&Bs[dd * 128 + (((2 * tcol)     ^ (dd & 7)) << 2)];
            float4 b1 = *(float4*)&Bs[dd * 128 + (((2 * tcol + 1) ^ (dd & 7)) << 2)];
#pragma unroll
            for (int i = 0; i < 4; i++) {
                float a = Qs[(trow4 + i) * 128 + d0 + dd] * qd[i];
                oacc[i][0] += a * b0.x; oacc[i][1] += a * b0.y;
                oacc[i][2] += a * b0.z; oacc[i][3] += a * b0.w;
                oacc[i][4] += a * b1.x; oacc[i][5] += a * b1.y;
                oacc[i][6] += a * b1.z; oacc[i][7] += a * b1.w;
            }
        }
        __syncthreads();
    }

#pragma unroll
    for (int i = 0; i < 4; i++) {
        float ss = 0.f;
#pragma unroll
        for (int j = 0; j < 8; j++) ss += oacc[i][j] * oacc[i][j];
        red[(trow4 + i) * 16 + tcol] = ss;
    }
    __syncthreads();
#pragma unroll
    for (int i = 0; i < 4; i++) {
        int r = trow4 + i;
        float ss = 0.f;
#pragma unroll
        for (int t2 = 0; t2 < 16; t2++) ss += red[r * 16 + t2];
        float rn = rsqrtf(ss * (1.0f / 128.0f) + 1e-5f);
        size_t gi = ((size_t)(rowbase + c0 + r)) * D_ + h * HD_ + tcol * 8;
        float4 g0 = *(const float4*)&g[gi];
        float4 g1 = *(const float4*)&g[gi + 4];
        float ov[8];
        ov[0] = oacc[i][0] * rn * (g0.x / (1.f + expf(-g0.x)));
        ov[1] = oacc[i][1] * rn * (g0.y / (1.f + expf(-g0.y)));
        ov[2] = oacc[i][2] * rn * (g0.z / (1.f + expf(-g0.z)));
        ov[3] = oacc[i][3] * rn * (g0.w / (1.f + expf(-g0.w)));
        ov[4] = oacc[i][4] * rn * (g1.x / (1.f + expf(-g1.x)));
        ov[5] = oacc[i][5] * rn * (g1.y / (1.f + expf(-g1.y)));
        ov[6] = oacc[i][6] * rn * (g1.z / (1.f + expf(-g1.z)));
        ov[7] = oacc[i][7] * rn * (g1.w / (1.f + expf(-g1.w)));
        __nv_bfloat162 hv[4], lv[4];
#pragma unroll
        for (int j = 0; j < 4; j++) {
            __nv_bfloat16 h0 = __float2bfloat16(ov[2*j]);
            __nv_bfloat16 h1 = __float2bfloat16(ov[2*j+1]);
            __nv_bfloat16 l0 = __float2bfloat16(ov[2*j]   - __bfloat162float(h0));
            __nv_bfloat16 l1 = __float2bfloat16(ov[2*j+1] - __bfloat162float(h1));
            hv[j] = __halves2bfloat162(h0, h1);
            lv[j] = __halves2bfloat162(l0, l1);
        }
        *(uint4*)&ohi[gi] = *(uint4*)hv;
        *(uint4*)&olo[gi] = *(uint4*)lv;
    }
}

// ============================= launcher =============================
extern "C" void kernel_launch(void* const* d_in, const int* in_sizes, int n_in,
                              void* d_out, int out_size)
{
    const float* x    = (const float*)d_in[0];
    const float* cosb = (const float*)d_in[1];
    const float* sinb = (const float*)d_in[2];
    const float* Wq   = (const float*)d_in[3];
    const float* Wk   = (const float*)d_in[4];
    const float* Wv   = (const float*)d_in[5];
    const float* Wg   = (const float*)d_in[6];
    const float* Wgt  = (const float*)d_in[7];
    const float* Wout = (const float*)d_in[8];
    float* out = (float*)d_out;

    float *q, *k, *v, *g, *gt, *gc, *sbuf, *spre;
    __nv_bfloat16 *xhi, *xlo, *ohi, *olo, *wthi, *wtlo;
    cudaGetSymbolAddress((void**)&q,    g_q);
    cudaGetSymbolAddress((void**)&k,    g_k);
    cudaGetSymbolAddress((void**)&v,    g_v);
    cudaGetSymbolAddress((void**)&g,    g_g);
    cudaGetSymbolAddress((void**)&gt,   g_gt);
    cudaGetSymbolAddress((void**)&gc,   g_gc);
    cudaGetSymbolAddress((void**)&sbuf, g_sinbuf);
    cudaGetSymbolAddress((void**)&spre, g_sprebuf);
    cudaGetSymbolAddress((void**)&xhi,  g_xhi);
    cudaGetSymbolAddress((void**)&xlo,  g_xlo);
    cudaGetSymbolAddress((void**)&ohi,  g_ohi);
    cudaGetSymbolAddress((void**)&olo,  g_olo);
    cudaGetSymbolAddress((void**)&wthi, g_wthi);
    cudaGetSymbolAddress((void**)&wtlo, g_wtlo);

    cudaFuncSetAttribute(out_kernel, cudaFuncAttributeMaxDynamicSharedMemorySize,
                         SMF_TOT * sizeof(float));
    cudaFuncSetAttribute(tc_gemm, cudaFuncAttributeMaxDynamicSharedMemorySize, TCG_SMEM);

    const size_t WSZ = (size_t)D_ * D_;
    dim3 wgrid(D_ / 32, D_ / 32, 5);
    dim3 ggrid(D_ / 128, BT_ / 128);   // (16, 64)

    wsplit_all<<<wgrid, 256>>>(Wq, Wk, Wv, Wg, Wout, wthi, wtlo);        // 1
    split_kernel<<<(BT_ * (D_ / 4)) / 256, 256>>>(x, xhi, xlo);          // 2

    tc_gemm<<<ggrid, 128, TCG_SMEM>>>(xhi, xlo, wthi + 0 * WSZ, wtlo + 0 * WSZ, q, cosb, sinb); // 3
    tc_gemm<<<ggrid, 128, TCG_SMEM>>>(xhi, xlo, wthi + 1 * WSZ, wtlo + 1 * WSZ, k, cosb, sinb); // 4
    tc_gemm<<<ggrid, 128, TCG_SMEM>>>(xhi, xlo, wthi + 2 * WSZ, wtlo + 2 * WSZ, v, nullptr, nullptr); // 5
    tc_gemm<<<ggrid, 128, TCG_SMEM>>>(xhi, xlo, wthi + 3 * WSZ, wtlo + 3 * WSZ, g, nullptr, nullptr); // 6 <- ncu
    gt_kernel<<<BT_, 128>>>(x, Wgt, gt);
    cumsum_kernel<<<B_ * H_ * NCH_, 256>>>(gt, gc);
    sin_kernel<<<B_ * H_ * NCH_, 256>>>(k, v, gc, sbuf);
    scan_kernel<<<B_ * H_ * 8, 256>>>(sbuf, gc, spre);
    out_kernel<<<B_ * H_ * NCH_ * 4, 256, SMF_TOT * sizeof(float)>>>(q, k, v, g, gc, spre, ohi, olo);

    tc_gemm<<<ggrid, 128, TCG_SMEM>>>(ohi, olo, wthi + 4 * WSZ, wtlo + 4 * WSZ, out, nullptr, nullptr);
}

// round 9
// speedup vs baseline: 2.3952x; 1.0871x over previous
#include <cuda_runtime.h>
#include <cuda_bf16.h>
#include <cstdint>

#define B_   2
#define T_   4096
#define D_   2048
#define H_   16
#define HD_  128
#define CH_  256
#define NCH_ 16
#define BT_  (B_*T_)
#define SCALE_ 0.08838834764831845f

// ---------------- scratch ----------------
__device__ float g_q[(size_t)BT_*D_];
__device__ float g_k[(size_t)BT_*D_];
__device__ float g_v[(size_t)BT_*D_];
__device__ float g_g[(size_t)BT_*D_];
__device__ float g_gt[B_*H_*T_];
__device__ float g_gc[B_*H_*T_];
__device__ float g_sinbuf [(size_t)B_*H_*NCH_*HD_*HD_];
__device__ float g_sprebuf[(size_t)B_*H_*NCH_*HD_*HD_];
__device__ __nv_bfloat16 g_xhi[(size_t)BT_*D_];
__device__ __nv_bfloat16 g_xlo[(size_t)BT_*D_];
__device__ __nv_bfloat16 g_ohi[(size_t)BT_*D_];
__device__ __nv_bfloat16 g_olo[(size_t)BT_*D_];
__device__ __nv_bfloat16 g_wthi[5*(size_t)D_*D_];   // W^T [N,K]: q,k,v,g,out
__device__ __nv_bfloat16 g_wtlo[5*(size_t)D_*D_];

__device__ __forceinline__ float log_sigmoidf(float z) {
    return (z >= 0.f) ? -log1pf(expf(-z)) : (z - log1pf(expf(z)));
}

// ============================= MMA helpers =============================
__device__ __forceinline__ uint32_t smem_u32(const void* p) {
    uint32_t a;
    asm("{ .reg .u64 t; cvta.to.shared.u64 t, %1; cvt.u32.u64 %0, t; }" : "=r"(a) : "l"(p));
    return a;
}
__device__ __forceinline__ void cp_async16(uint32_t s, const void* g) {
    asm volatile("cp.async.cg.shared.global [%0], [%1], 16;" :: "r"(s), "l"(g));
}
__device__ __forceinline__ void cp_commit() { asm volatile("cp.async.commit_group;"); }
template<int N> __device__ __forceinline__ void cp_wait() {
    asm volatile("cp.async.wait_group %0;" :: "n"(N));
}
__device__ __forceinline__ void ldmat4(uint32_t* r, uint32_t a) {
    asm volatile("ldmatrix.sync.aligned.m8n8.x4.shared.b16 {%0,%1,%2,%3}, [%4];"
        : "=r"(r[0]), "=r"(r[1]), "=r"(r[2]), "=r"(r[3]) : "r"(a));
}
__device__ __forceinline__ void mma_bf16(float* d, const uint32_t* a, uint32_t b0, uint32_t b1) {
    asm volatile(
        "mma.sync.aligned.m16n8k16.row.col.f32.bf16.bf16.f32 "
        "{%0,%1,%2,%3}, {%4,%5,%6,%7}, {%8,%9}, {%0,%1,%2,%3};"
        : "+f"(d[0]), "+f"(d[1]), "+f"(d[2]), "+f"(d[3])
        : "r"(a[0]), "r"(a[1]), "r"(a[2]), "r"(a[3]), "r"(b0), "r"(b1));
}

// ============================= tensor-core GEMM =============================
// C[M,2048] = (Ahi+Alo)[M,2048] @ (Bhi+Blo)^T, B operands [N,K] row-major.
// 128x128 CTA tile, BK=64, 4 warps (2x2), warp tile 64x64.
// 3-stage cp.async pipeline (issue distance 2), one __syncthreads per chunk,
// software-pipelined ldmatrix (double-buffered fragments) so the tensor pipe
// starts ~60cyc after the barrier; cp.async issues are buried behind MMA(ks0).
#define LDS_ROW 72                      // bf16 per smem row (144 B; 4-bank row stride, 16B aligned)
#define STAGE_A (128 * LDS_ROW * 2)     // 18432 B
#define STAGE_T (2 * STAGE_A)           // 36864 B (A + B)
#define NSTG3   3
#define TCG_SMEM (NSTG3 * STAGE_T)      // 110592 B

__global__ void __launch_bounds__(128, 2) tc_gemm(
    const __nv_bfloat16* __restrict__ Ahi, const __nv_bfloat16* __restrict__ Alo,
    const __nv_bfloat16* __restrict__ Bhi, const __nv_bfloat16* __restrict__ Blo,
    float* __restrict__ C,
    const float* __restrict__ rope_cos, const float* __restrict__ rope_sin)
{
    extern __shared__ __align__(16) char smem[];
    const uint32_t smb = smem_u32(smem);

    int tid = threadIdx.x, lane = tid & 31, wid = tid >> 5;
    int wm = wid >> 1, wn = wid & 1;                     // 2 x 2 warp grid
    int m0 = blockIdx.y * 128, n0 = blockIdx.x * 128;

    // global loads: 128 rows x 64 bf16 per operand per chunk = 1024 vec16; 8/thread/operand
    int row_t = tid >> 3;                                // 0..15
    int col_t = (tid & 7) << 3;                          // bf16 col 0..56
    uint32_t so_[8];
#pragma unroll
    for (int i = 0; i < 8; i++)
        so_[i] = (uint32_t)((row_t + 16 * i) * (LDS_ROW * 2) + col_t * 2);

    uint32_t aoff[4];
#pragma unroll
    for (int mt = 0; mt < 4; mt++)
        aoff[mt] = (uint32_t)(((wm * 64 + mt * 16 + (lane & 15)) * LDS_ROW + ((lane >> 4) << 3)) * 2);
    uint32_t boff[4];
    {
        int q = lane >> 3, r = lane & 7;
#pragma unroll
        for (int np = 0; np < 4; np++) {
            int n = wn * 64 + np * 16 + ((q >> 1) << 3) + r;
            int kc = (q & 1) << 3;
            boff[np] = (uint32_t)((n * LDS_ROW + kc) * 2);
        }
    }

    float acc[4][8][4];
#pragma unroll
    for (int i = 0; i < 4; i++)
#pragma unroll
        for (int j = 0; j < 8; j++)
#pragma unroll
            for (int e = 0; e < 4; e++) acc[i][j][e] = 0.f;

    const int NCHUNK = 96;                               // 3 passes x 32 (BK=64)

    // prologue: issue chunks 0,1 (pass 0 => Ahi/Bhi)
#pragma unroll
    for (int pc = 0; pc < 2; pc++) {
        int kk = pc << 6;
        uint32_t st = smb + pc * STAGE_T;
#pragma unroll
        for (int i = 0; i < 8; i++) {
            cp_async16(st + so_[i],           Ahi + (size_t)(m0 + row_t + 16 * i) * D_ + kk + col_t);
            cp_async16(st + STAGE_A + so_[i], Bhi + (size_t)(n0 + row_t + 16 * i) * D_ + kk + col_t);
        }
        cp_commit();
    }

    uint32_t fa0[4][4], fb0[4][4], fa1[4][4], fb1[4][4];

#define LDM_BLK(fa, fb, sA, sB, ks) do { \
    _Pragma("unroll") for (int mt = 0; mt < 4; mt++) ldmat4((fa)[mt], (sA) + aoff[mt] + (ks) * 32); \
    _Pragma("unroll") for (int np = 0; np < 4; np++) ldmat4((fb)[np], (sB) + boff[np] + (ks) * 32); \
} while (0)
#define MMA_BLK(fa, fb) do { \
    _Pragma("unroll") for (int mt = 0; mt < 4; mt++) \
        _Pragma("unroll") for (int nt = 0; nt < 8; nt++) \
            mma_bf16(acc[mt][nt], (fa)[mt], (fb)[nt >> 1][(nt & 1) * 2], (fb)[nt >> 1][(nt & 1) * 2 + 1]); \
} while (0)

    int st_c = 0;                                        // stage of chunk c
    for (int c = 0; c < NCHUNK; c++) {
        cp_wait<1>();                                    // chunk c resident (this thread)
        __syncthreads();                                 // visible; stage (c-1)%3 compute done

        uint32_t sA = smb + st_c * STAGE_T;
        uint32_t sB = sA + STAGE_A;

        LDM_BLK(fa0, fb0, sA, sB, 0);                    // frags ks0
        LDM_BLK(fa1, fb1, sA, sB, 1);                    // prefetch ks1
        MMA_BLK(fa0, fb0);                               // tensor starts immediately

        // issue next-next chunk loads while tensor pipe crunches ks0
        int cn = c + 2;
        if (cn < NCHUNK) {
            int pass = cn >> 5;
            int kk = (cn & 31) << 6;
            const __nv_bfloat16* As = (pass == 1) ? Alo : Ahi;
            const __nv_bfloat16* Bs = (pass == 2) ? Blo : Bhi;
            int stn = st_c + 2; if (stn >= NSTG3) stn -= NSTG3;   // == (c-1)%3
            uint32_t st = smb + stn * STAGE_T;
#pragma unroll
            for (int i = 0; i < 8; i++) {
                cp_async16(st + so_[i],           As + (size_t)(m0 + row_t + 16 * i) * D_ + kk + col_t);
                cp_async16(st + STAGE_A + so_[i], Bs + (size_t)(n0 + row_t + 16 * i) * D_ + kk + col_t);
            }
        }
        cp_commit();                                     // empty group in tail keeps counts

        LDM_BLK(fa0, fb0, sA, sB, 2);                    // prefetch ks2
        MMA_BLK(fa1, fb1);                               // ks1
        LDM_BLK(fa1, fb1, sA, sB, 3);                    // prefetch ks3
        MMA_BLK(fa0, fb0);                               // ks2
        MMA_BLK(fa1, fb1);                               // ks3

        st_c = (st_c + 1 == NSTG3) ? 0 : st_c + 1;
    }

    // epilogue: optional fused RoPE (acc pairs are exactly the (2i,2i+1) rope pairs)
    int tq = lane >> 2, tr = lane & 3;
#pragma unroll
    for (int mt = 0; mt < 4; mt++) {
#pragma unroll
        for (int nt = 0; nt < 8; nt++) {
            int m = m0 + wm * 64 + mt * 16 + tq;
            int n = n0 + wn * 64 + nt * 8 + tr * 2;
            float v0 = acc[mt][nt][0], v1 = acc[mt][nt][1];
            float v2 = acc[mt][nt][2], v3 = acc[mt][nt][3];
            if (rope_cos) {
                int i  = (n & 127) >> 1;
                int t1 = m & 4095, t2 = (m + 8) & 4095;
                float c1 = rope_cos[t1 * 64 + i], s1 = rope_sin[t1 * 64 + i];
                float c2 = rope_cos[t2 * 64 + i], s2 = rope_sin[t2 * 64 + i];
                float r0 = v0 * c1 - v1 * s1, r1 = v0 * s1 + v1 * c1;
                float r2 = v2 * c2 - v3 * s2, r3 = v2 * s2 + v3 * c2;
                v0 = r0; v1 = r1; v2 = r2; v3 = r3;
            }
            *(float2*)&C[(size_t)m * D_ + n]       = make_float2(v0, v1);
            *(float2*)&C[(size_t)(m + 8) * D_ + n] = make_float2(v2, v3);
        }
    }
}

// ---------------- fp32 -> bf16 hi/lo split ----------------
__global__ __launch_bounds__(256) void split_kernel(
    const float* __restrict__ a, __nv_bfloat16* __restrict__ hi, __nv_bfloat16* __restrict__ lo)
{
    size_t i = ((size_t)blockIdx.x * 256 + threadIdx.x) * 4;
    float4 v = *(const float4*)&a[i];
    __nv_bfloat16 h0 = __float2bfloat16(v.x), h1 = __float2bfloat16(v.y);
    __nv_bfloat16 h2 = __float2bfloat16(v.z), h3 = __float2bfloat16(v.w);
    __nv_bfloat16 l0 = __float2bfloat16(v.x - __bfloat162float(h0));
    __nv_bfloat16 l1 = __float2bfloat16(v.y - __bfloat162float(h1));
    __nv_bfloat16 l2 = __float2bfloat16(v.z - __bfloat162float(h2));
    __nv_bfloat16 l3 = __float2bfloat16(v.w - __bfloat162float(h3));
    __nv_bfloat162* hp = (__nv_bfloat162*)(hi + i);
    __nv_bfloat162* lp = (__nv_bfloat162*)(lo + i);
    hp[0] = __halves2bfloat162(h0, h1); hp[1] = __halves2bfloat162(h2, h3);
    lp[0] = __halves2bfloat162(l0, l1); lp[1] = __halves2bfloat162(l2, l3);
}

// ---------------- all 5 weights: W[K,N] -> Wt_hi/lo[N,K] transpose+split ----------------
__global__ __launch_bounds__(256) void wsplit_all(
    const float* __restrict__ W0, const float* __restrict__ W1,
    const float* __restrict__ W2, const float* __restrict__ W3,
    const float* __restrict__ W4,
    __nv_bfloat16* __restrict__ hi, __nv_bfloat16* __restrict__ lo)
{
    __shared__ float tile[32][33];
    int z = blockIdx.z;
    const float* W = (z == 0) ? W0 : (z == 1) ? W1 : (z == 2) ? W2 : (z == 3) ? W3 : W4;
    size_t off = (size_t)z * D_ * D_;
    int k0 = blockIdx.y * 32, n0 = blockIdx.x * 32;
    int tx = threadIdx.x & 31, ty = threadIdx.x >> 5;
#pragma unroll
    for (int i = 0; i < 32; i += 8)
        tile[ty + i][tx] = W[(size_t)(k0 + ty + i) * D_ + n0 + tx];
    __syncthreads();
#pragma unroll
    for (int i = 0; i < 32; i += 8) {
        float v = tile[tx][ty + i];
        __nv_bfloat16 h = __float2bfloat16(v);
        __nv_bfloat16 l = __float2bfloat16(v - __bfloat162float(h));
        size_t oi = off + (size_t)(n0 + ty + i) * D_ + k0 + tx;
        hi[oi] = h; lo[oi] = l;
    }
}

// ============================= retention =============================
__global__ __launch_bounds__(128) void gt_kernel(
    const float* __restrict__ x, const float* __restrict__ Wgt, float* __restrict__ gt)
{
    int row = blockIdx.x;
    int tid = threadIdx.x;
    const float* xr = x + (size_t)row * D_;
    float acc[16];
#pragma unroll
    for (int h = 0; h < 16; h++) acc[h] = 0.f;
    for (int kk = tid; kk < D_; kk += 128) {
        float xv = xr[kk];
        const float4* w4 = (const float4*)(Wgt + (size_t)kk * 16);
        float4 w0 = w4[0], w1 = w4[1], w2 = w4[2], w3 = w4[3];
        acc[0]  += xv * w0.x; acc[1]  += xv * w0.y; acc[2]  += xv * w0.z; acc[3]  += xv * w0.w;
        acc[4]  += xv * w1.x; acc[5]  += xv * w1.y; acc[6]  += xv * w1.z; acc[7]  += xv * w1.w;
        acc[8]  += xv * w2.x; acc[9]  += xv * w2.y; acc[10] += xv * w2.z; acc[11] += xv * w2.w;
        acc[12] += xv * w3.x; acc[13] += xv * w3.y; acc[14] += xv * w3.z; acc[15] += xv * w3.w;
    }
#pragma unroll
    for (int h = 0; h < 16; h++)
#pragma unroll
        for (int off = 16; off > 0; off >>= 1)
            acc[h] += __shfl_down_sync(0xffffffffu, acc[h], off);
    __shared__ float part[4][16];
    int warp = tid >> 5, lane = tid & 31;
    if (lane == 0)
#pragma unroll
        for (int h = 0; h < 16; h++) part[warp][h] = acc[h];
    __syncthreads();
    if (tid < 16) {
        float s = part[0][tid] + part[1][tid] + part[2][tid] + part[3][tid];
        int b = row >> 12, t = row & 4095;
        gt[((size_t)(b * H_ + tid)) * T_ + t] = log_sigmoidf(s) * (1.f / 16.f);
    }
}

__global__ __launch_bounds__(256) void cumsum_kernel(
    const float* __restrict__ gt, float* __restrict__ gc)
{
    int bh = blockIdx.x >> 4;
    int n  = blockIdx.x & 15;
    int tid = threadIdx.x, lane = tid & 31, warp = tid >> 5;
    size_t idx = (size_t)bh * T_ + n * CH_ + tid;
    float v = gt[idx];
#pragma unroll
    for (int off = 1; off < 32; off <<= 1) {
        float y = __shfl_up_sync(0xffffffffu, v, off);
        if (lane >= off) v += y;
    }
    __shared__ float ws[8];
    if (lane == 31) ws[warp] = v;
    __syncthreads();
    if (tid == 0) {
        float s = 0.f;
#pragma unroll
        for (int w = 0; w < 8; w++) { float t = ws[w]; ws[w] = s; s += t; }
    }
    __syncthreads();
    gc[idx] = v + ws[warp];
}

__global__ __launch_bounds__(256) void sin_kernel(
    const float* __restrict__ k, const float* __restrict__ v,
    const float* __restrict__ gc, float* __restrict__ Sin)
{
    __shared__ __align__(16) float Ks[32 * 128];
    __shared__ __align__(16) float Vs[32 * 128];
    __shared__ float kd[32];
    int blk = blockIdx.x;
    int n = blk & 15, h = (blk >> 4) & 15, b = blk >> 8;
    int tid = threadIdx.x;
    int trow = tid >> 4, tcol = tid & 15;
    const float* gcc = gc + ((size_t)(b * H_ + h)) * T_ + n * CH_;
    float gtot = gcc[CH_ - 1];

    float acc[8][8];
#pragma unroll
    for (int i = 0; i < 8; i++)
#pragma unroll
        for (int j = 0; j < 8; j++) acc[i][j] = 0.f;

    for (int s0 = 0; s0 < CH_; s0 += 32) {
        __syncthreads();
        if (tid < 32) kd[tid] = expf(gtot - gcc[s0 + tid]) * SCALE_;
        __syncthreads();
#pragma unroll
        for (int l = 0; l < 4; l++) {
            int li = tid + l * 256;
            int c = li >> 5, gcol = (li & 31) << 2;
            size_t gi = ((size_t)(b * T_ + n * CH_ + s0 + c)) * D_ + h * HD_ + gcol;
            float4 kv4 = *(const float4*)&k[gi];
            float sc = kd[c];
            kv4.x *= sc; kv4.y *= sc; kv4.z *= sc; kv4.w *= sc;
            *(float4*)&Ks[c * 128 + gcol] = kv4;
            *(float4*)&Vs[c * 128 + gcol] = *(const float4*)&v[gi];
        }
        __syncthreads();
#pragma unroll
        for (int c = 0; c < 32; c++) {
            float4 a0 = *(float4*)&Ks[c * 128 + trow * 8];
            float4 a1 = *(float4*)&Ks[c * 128 + trow * 8 + 4];
            float4 b0 = *(float4*)&Vs[c * 128 + tcol * 8];
            float4 b1 = *(float4*)&Vs[c * 128 + tcol * 8 + 4];
            float a[8] = {a0.x, a0.y, a0.z, a0.w, a1.x, a1.y, a1.z, a1.w};
            float bb[8] = {b0.x, b0.y, b0.z, b0.w, b1.x, b1.y, b1.z, b1.w};
#pragma unroll
            for (int i = 0; i < 8; i++)
#pragma unroll
                for (int j = 0; j < 8; j++) acc[i][j] += a[i] * bb[j];
        }
    }
    size_t base = (size_t)blk * (HD_ * HD_);
#pragma unroll
    for (int i = 0; i < 8; i++) {
        size_t oi = base + (size_t)(trow * 8 + i) * HD_ + tcol * 8;
        *(float4*)&Sin[oi]     = make_float4(acc[i][0], acc[i][1], acc[i][2], acc[i][3]);
        *(float4*)&Sin[oi + 4] = make_float4(acc[i][4], acc[i][5], acc[i][6], acc[i][7]);
    }
}

// parallel over (bh, 8 parts of the 16K state elements); serial only over 16 chunks
__global__ __launch_bounds__(256) void scan_kernel(
    const float* __restrict__ Sin, const float* __restrict__ gc, float* __restrict__ Spre)
{
    int blk = blockIdx.x;              // 256 = 32 bh x 8 parts
    int bh = blk >> 3, part = blk & 7;
    int e0 = part * 2048 + threadIdx.x;
    float S[8];
#pragma unroll
    for (int l = 0; l < 8; l++) S[l] = 0.f;
    for (int n = 0; n < NCH_; n++) {
        float cd = expf(gc[(size_t)bh * T_ + n * CH_ + (CH_ - 1)]);
        size_t base = ((size_t)(bh * NCH_ + n)) * (HD_ * HD_);
#pragma unroll
        for (int l = 0; l < 8; l++) {
            int idx = e0 + l * 256;
            Spre[base + idx] = S[l];
            S[l] = S[l] * cd + Sin[base + idx];
        }
    }
}

#define QS_OFF  0
#define BS_OFF  8192
#define SS_OFF  16384
#define GQ_OFF  20736
#define GK_OFF  20800
#define RED_OFF 20864
#define SMF_TOT 21888

__global__ __launch_bounds__(256) void out_kernel(
    const float* __restrict__ q, const float* __restrict__ k,
    const float* __restrict__ v, const float* __restrict__ g,
    const float* __restrict__ gc, const float* __restrict__ Spre,
    __nv_bfloat16* __restrict__ ohi, __nv_bfloat16* __restrict__ olo)
{
    extern __shared__ __align__(16) float sm[];
    float* Qs  = sm + QS_OFF;
    float* Bs  = sm + BS_OFF;
    float* Ss  = sm + SS_OFF;
    float* gq  = sm + GQ_OFF;
    float* gk  = sm + GK_OFF;
    float* red = sm + RED_OFF;

    int blk = blockIdx.x;
    int rt = blk & 3, n = (blk >> 2) & 15, h = (blk >> 6) & 15, b = blk >> 10;
    int tid = threadIdx.x, trow = tid >> 4, tcol = tid & 15;
    int trow4 = trow * 4;
    const float* gcc = gc + ((size_t)(b * H_ + h)) * T_ + n * CH_;
    int c0 = rt * 64;
    int rowbase = b * T_ + n * CH_;

#pragma unroll
    for (int l = 0; l < 8; l++) {
        int li = tid + l * 256;
        int c = li >> 5, gcol = (li & 31) << 2;
        size_t gi = ((size_t)(rowbase + c0 + c)) * D_ + h * HD_ + gcol;
        *(float4*)&Qs[c * 128 + gcol] = *(const float4*)&q[gi];
    }
    if (tid < 64) gq[tid] = gcc[c0 + tid];

    float oacc[4][8];
#pragma unroll
    for (int i = 0; i < 4; i++)
#pragma unroll
        for (int j = 0; j < 8; j++) oacc[i][j] = 0.f;
    __syncthreads();

    for (int st = 0; st <= rt; st++) {
        int s0 = st * 64;
#pragma unroll
        for (int l = 0; l < 8; l++) {
            int li = tid + l * 256;
            int c = li >> 5, gr = li & 31;
            size_t gi = ((size_t)(rowbase + s0 + c)) * D_ + h * HD_ + (gr << 2);
            *(float4*)&Bs[c * 128 + ((gr ^ (c & 7)) << 2)] = *(const float4*)&k[gi];
        }
        if (tid < 64) gk[tid] = gcc[s0 + tid];
        __syncthreads();

        float sacc[4][4];
#pragma unroll
        for (int i = 0; i < 4; i++)
#pragma unroll
            for (int j = 0; j < 4; j++) sacc[i][j] = 0.f;
#pragma unroll
        for (int gr = 0; gr < 32; gr++) {
            float4 a[4];
#pragma unroll
            for (int i = 0; i < 4; i++) a[i] = *(float4*)&Qs[(trow4 + i) * 128 + (gr << 2)];
#pragma unroll
            for (int j = 0; j < 4; j++) {
                int s = tcol * 4 + j;
                float4 bb = *(float4*)&Bs[s * 128 + ((gr ^ (s & 7)) << 2)];
#pragma unroll
                for (int i = 0; i < 4; i++)
                    sacc[i][j] += a[i].x * bb.x + a[i].y * bb.y + a[i].z * bb.z + a[i].w * bb.w;
            }
        }
#pragma unroll
        for (int i = 0; i < 4; i++) {
            int r = trow4 + i;
            float gqi = gq[r];
#pragma unroll
            for (int j = 0; j < 4; j++) {
                int s = tcol * 4 + j;
                float val = 0.f;
                if (s0 + s <= c0 + r) val = sacc[i][j] * SCALE_ * expf(gqi - gk[s]);
                Ss[r * 68 + s] = val;
            }
        }
        __syncthreads();

#pragma unroll
        for (int l = 0; l < 8; l++) {
            int li = tid + l * 256;
            int c = li >> 5, gr = li & 31;
            size_t gi = ((size_t)(rowbase + s0 + c)) * D_ + h * HD_ + (gr << 2);
            *(float4*)&Bs[c * 128 + ((gr ^ (c & 7)) << 2)] = *(const float4*)&v[gi];
        }
        __syncthreads();

#pragma unroll
        for (int s = 0; s < 64; s++) {
            float4 b0 = *(float4*)&Bs[s * 128 + (((2 * tcol)     ^ (s & 7)) << 2)];
            float4 b1 = *(float4*)&Bs[s * 128 + (((2 * tcol + 1) ^ (s & 7)) << 2)];
#pragma unroll
            for (int i = 0; i < 4; i++) {
                float a = Ss[(trow4 + i) * 68 + s];
                oacc[i][0] += a * b0.x; oacc[i][1] += a * b0.y;
                oacc[i][2] += a * b0.z; oacc[i][3] += a * b0.w;
                oacc[i][4] += a * b1.x; oacc[i][5] += a * b1.y;
                oacc[i][6] += a * b1.z; oacc[i][7] += a * b1.w;
            }
        }
        __syncthreads();
    }

    float qd[4];
#pragma unroll
    for (int i = 0; i < 4; i++) qd[i] = expf(gq[trow4 + i]);
    size_t sbase = ((size_t)(blk >> 2)) * (HD_ * HD_);
    for (int d0 = 0; d0 < 128; d0 += 64) {
#pragma unroll
        for (int l = 0; l < 8; l++) {
            int li = tid + l * 256;
            int dd = li >> 5, gr = li & 31;
            *(float4*)&Bs[dd * 128 + ((gr ^ (dd & 7)) << 2)] =
                *(const float4*)&Spre[sbase + (size_t)(d0 + dd) * 128 + (gr << 2)];
        }
        __syncthreads();
#pragma unroll
        for (int dd = 0; dd < 64; dd++) {
            float4 b0 = *(float4*)&Bs[dd * 128 + (((2 * tcol)     ^ (dd & 7)) << 2)];
            float4 b1 = *(float4*)&Bs[dd * 128 + (((2 * tcol + 1) ^ (dd & 7)) << 2)];
#pragma unroll
            for (int i = 0; i < 4; i++) {
                float a = Qs[(trow4 + i) * 128 + d0 + dd] * qd[i];
                oacc[i][0] += a * b0.x; oacc[i][1] += a * b0.y;
                oacc[i][2] += a * b0.z; oacc[i][3] += a * b0.w;
                oacc[i][4] += a * b1.x; oacc[i][5] += a * b1.y;
                oacc[i][6] += a * b1.z; oacc[i][7] += a * b1.w;
            }
        }
        __syncthreads();
    }

#pragma unroll
    for (int i = 0; i < 4; i++) {
        float ss = 0.f;
#pragma unroll
        for (int j = 0; j < 8; j++) ss += oacc[i][j] * oacc[i][j];
        red[(trow4 + i) * 16 + tcol] = ss;
    }
    __syncthreads();
#pragma unroll
    for (int i = 0; i < 4; i++) {
        int r = trow4 + i;
        float ss = 0.f;
#pragma unroll
        for (int t2 = 0; t2 < 16; t2++) ss += red[r * 16 + t2];
        float rn = rsqrtf(ss * (1.0f / 128.0f) + 1e-5f);
        size_t gi = ((size_t)(rowbase + c0 + r)) * D_ + h * HD_ + tcol * 8;
        float4 g0 = *(const float4*)&g[gi];
        float4 g1 = *(const float4*)&g[gi + 4];
        float ov[8];
        ov[0] = oacc[i][0] * rn * (g0.x / (1.f + expf(-g0.x)));
        ov[1] = oacc[i][1] * rn * (g0.y / (1.f + expf(-g0.y)));
        ov[2] = oacc[i][2] * rn * (g0.z / (1.f + expf(-g0.z)));
        ov[3] = oacc[i][3] * rn * (g0.w / (1.f + expf(-g0.w)));
        ov[4] = oacc[i][4] * rn * (g1.x / (1.f + expf(-g1.x)));
        ov[5] = oacc[i][5] * rn * (g1.y / (1.f + expf(-g1.y)));
        ov[6] = oacc[i][6] * rn * (g1.z / (1.f + expf(-g1.z)));
        ov[7] = oacc[i][7] * rn * (g1.w / (1.f + expf(-g1.w)));
        __nv_bfloat162 hv[4], lv[4];
#pragma unroll
        for (int j = 0; j < 4; j++) {
            __nv_bfloat16 h0 = __float2bfloat16(ov[2*j]);
            __nv_bfloat16 h1 = __float2bfloat16(ov[2*j+1]);
            __nv_bfloat16 l0 = __float2bfloat16(ov[2*j]   - __bfloat162float(h0));
            __nv_bfloat16 l1 = __float2bfloat16(ov[2*j+1] - __bfloat162float(h1));
            hv[j] = __halves2bfloat162(h0, h1);
            lv[j] = __halves2bfloat162(l0, l1);
        }
        *(uint4*)&ohi[gi] = *(uint4*)hv;
        *(uint4*)&olo[gi] = *(uint4*)lv;
    }
}

// ============================= launcher =============================
extern "C" void kernel_launch(void* const* d_in, const int* in_sizes, int n_in,
                              void* d_out, int out_size)
{
    const float* x    = (const float*)d_in[0];
    const float* cosb = (const float*)d_in[1];
    const float* sinb = (const float*)d_in[2];
    const float* Wq   = (const float*)d_in[3];
    const float* Wk   = (const float*)d_in[4];
    const float* Wv   = (const float*)d_in[5];
    const float* Wg   = (const float*)d_in[6];
    const float* Wgt  = (const float*)d_in[7];
    const float* Wout = (const float*)d_in[8];
    float* out = (float*)d_out;

    float *q, *k, *v, *g, *gt, *gc, *sbuf, *spre;
    __nv_bfloat16 *xhi, *xlo, *ohi, *olo, *wthi, *wtlo;
    cudaGetSymbolAddress((void**)&q,    g_q);
    cudaGetSymbolAddress((void**)&k,    g_k);
    cudaGetSymbolAddress((void**)&v,    g_v);
    cudaGetSymbolAddress((void**)&g,    g_g);
    cudaGetSymbolAddress((void**)&gt,   g_gt);
    cudaGetSymbolAddress((void**)&gc,   g_gc);
    cudaGetSymbolAddress((void**)&sbuf, g_sinbuf);
    cudaGetSymbolAddress((void**)&spre, g_sprebuf);
    cudaGetSymbolAddress((void**)&xhi,  g_xhi);
    cudaGetSymbolAddress((void**)&xlo,  g_xlo);
    cudaGetSymbolAddress((void**)&ohi,  g_ohi);
    cudaGetSymbolAddress((void**)&olo,  g_olo);
    cudaGetSymbolAddress((void**)&wthi, g_wthi);
    cudaGetSymbolAddress((void**)&wtlo, g_wtlo);

    cudaFuncSetAttribute(out_kernel, cudaFuncAttributeMaxDynamicSharedMemorySize,
                         SMF_TOT * sizeof(float));
    cudaFuncSetAttribute(tc_gemm, cudaFuncAttributeMaxDynamicSharedMemorySize, TCG_SMEM);

    const size_t WSZ = (size_t)D_ * D_;
    dim3 wgrid(D_ / 32, D_ / 32, 5);
    dim3 ggrid(D_ / 128, BT_ / 128);   // (16, 64)

    wsplit_all<<<wgrid, 256>>>(Wq, Wk, Wv, Wg, Wout, wthi, wtlo);        // 1
    split_kernel<<<(BT_ * (D_ / 4)) / 256, 256>>>(x, xhi, xlo);          // 2

    tc_gemm<<<ggrid, 128, TCG_SMEM>>>(xhi, xlo, wthi + 0 * WSZ, wtlo + 0 * WSZ, q, cosb, sinb); // 3
    tc_gemm<<<ggrid, 128, TCG_SMEM>>>(xhi, xlo, wthi + 1 * WSZ, wtlo + 1 * WSZ, k, cosb, sinb); // 4
    tc_gemm<<<ggrid, 128, TCG_SMEM>>>(xhi, xlo, wthi + 2 * WSZ, wtlo + 2 * WSZ, v, nullptr, nullptr); // 5
    tc_gemm<<<ggrid, 128, TCG_SMEM>>>(xhi, xlo, wthi + 3 * WSZ, wtlo + 3 * WSZ, g, nullptr, nullptr); // 6 <- ncu
    gt_kernel<<<BT_, 128>>>(x, Wgt, gt);
    cumsum_kernel<<<B_ * H_ * NCH_, 256>>>(gt, gc);
    sin_kernel<<<B_ * H_ * NCH_, 256>>>(k, v, gc, sbuf);
    scan_kernel<<<B_ * H_ * 8, 256>>>(sbuf, gc, spre);
    out_kernel<<<B_ * H_ * NCH_ * 4, 256, SMF_TOT * sizeof(float)>>>(q, k, v, g, gc, spre, ohi, olo);

    tc_gemm<<<ggrid, 128, TCG_SMEM>>>(ohi, olo, wthi + 4 * WSZ, wtlo + 4 * WSZ, out, nullptr, nullptr);
}

// round 10
// speedup vs baseline: 2.4692x; 1.0309x over previous
#include <cuda_runtime.h>
#include <cuda_bf16.h>
#include <cstdint>

#define B_   2
#define T_   4096
#define D_   2048
#define H_   16
#define HD_  128
#define CH_  256
#define NCH_ 16
#define BT_  (B_*T_)
#define SCALE_ 0.08838834764831845f

// ---------------- scratch ----------------
__device__ float g_q[(size_t)BT_*D_];
__device__ float g_k[(size_t)BT_*D_];
__device__ float g_v[(size_t)BT_*D_];
__device__ float g_g[(size_t)BT_*D_];
__device__ float g_gt[B_*H_*T_];
__device__ float g_gc[B_*H_*T_];
__device__ float g_sinbuf [(size_t)B_*H_*NCH_*HD_*HD_];
__device__ float g_sprebuf[(size_t)B_*H_*NCH_*HD_*HD_];
__device__ __nv_bfloat16 g_xhi[(size_t)BT_*D_];
__device__ __nv_bfloat16 g_xlo[(size_t)BT_*D_];
__device__ __nv_bfloat16 g_ohi[(size_t)BT_*D_];
__device__ __nv_bfloat16 g_olo[(size_t)BT_*D_];
__device__ __nv_bfloat16 g_wthi[5*(size_t)D_*D_];   // W^T [N,K]: q,k,v,g,out
__device__ __nv_bfloat16 g_wtlo[5*(size_t)D_*D_];

__device__ __forceinline__ float log_sigmoidf(float z) {
    return (z >= 0.f) ? -log1pf(expf(-z)) : (z - log1pf(expf(z)));
}

// ============================= MMA helpers =============================
__device__ __forceinline__ uint32_t smem_u32(const void* p) {
    uint32_t a;
    asm("{ .reg .u64 t; cvta.to.shared.u64 t, %1; cvt.u32.u64 %0, t; }" : "=r"(a) : "l"(p));
    return a;
}
__device__ __forceinline__ void cp_async16(uint32_t s, const void* g) {
    asm volatile("cp.async.cg.shared.global [%0], [%1], 16;" :: "r"(s), "l"(g));
}
__device__ __forceinline__ void cp_commit() { asm volatile("cp.async.commit_group;"); }
template<int N> __device__ __forceinline__ void cp_wait() {
    asm volatile("cp.async.wait_group %0;" :: "n"(N));
}
__device__ __forceinline__ void ldmat4(uint32_t* r, uint32_t a) {
    asm volatile("ldmatrix.sync.aligned.m8n8.x4.shared.b16 {%0,%1,%2,%3}, [%4];"
        : "=r"(r[0]), "=r"(r[1]), "=r"(r[2]), "=r"(r[3]) : "r"(a));
}
__device__ __forceinline__ void mma_bf16(float* d, const uint32_t* a, uint32_t b0, uint32_t b1) {
    asm volatile(
        "mma.sync.aligned.m16n8k16.row.col.f32.bf16.bf16.f32 "
        "{%0,%1,%2,%3}, {%4,%5,%6,%7}, {%8,%9}, {%0,%1,%2,%3};"
        : "+f"(d[0]), "+f"(d[1]), "+f"(d[2]), "+f"(d[3])
        : "r"(a[0]), "r"(a[1]), "r"(a[2]), "r"(a[3]), "r"(b0), "r"(b1));
}

// ============================= tensor-core GEMM =============================
// C[M,2048] = (Ahi+Alo)[M,2048] @ (Bhi+Blo)^T, B operands [N,K] row-major.
// blockIdx.z selects the weight slice + output pointer (merged multi-GEMM launch
// to kill tail-wave quantization: 4096 tiles / 296 CTA slots -> 98.9% balance).
// 128x128 CTA tile, BK=64, 4 warps (2x2), warp tile 64x64.
// 3-stage cp.async pipeline (issue distance 2), one __syncthreads per chunk,
// software-pipelined ldmatrix (double-buffered fragments).
// RoPE fused in epilogue for z<2 when rope pointers given (q and k projections).
#define LDS_ROW 72                      // bf16 per smem row (144 B; 4-bank row stride, 16B aligned)
#define STAGE_A (128 * LDS_ROW * 2)     // 18432 B
#define STAGE_T (2 * STAGE_A)           // 36864 B (A + B)
#define NSTG3   3
#define TCG_SMEM (NSTG3 * STAGE_T)      // 110592 B

__global__ void __launch_bounds__(128, 2) tc_gemm(
    const __nv_bfloat16* __restrict__ Ahi, const __nv_bfloat16* __restrict__ Alo,
    const __nv_bfloat16* __restrict__ BhiBase, const __nv_bfloat16* __restrict__ BloBase,
    float* __restrict__ C0, float* __restrict__ C1,
    float* __restrict__ C2, float* __restrict__ C3,
    const float* __restrict__ rope_cos, const float* __restrict__ rope_sin)
{
    extern __shared__ __align__(16) char smem[];
    const uint32_t smb = smem_u32(smem);

    int z = blockIdx.z;
    const __nv_bfloat16* Bhi = BhiBase + (size_t)z * D_ * D_;
    const __nv_bfloat16* Blo = BloBase + (size_t)z * D_ * D_;
    float* C = (z == 0) ? C0 : (z == 1) ? C1 : (z == 2) ? C2 : C3;
    bool use_rope = (rope_cos != nullptr) && (z < 2);

    int tid = threadIdx.x, lane = tid & 31, wid = tid >> 5;
    int wm = wid >> 1, wn = wid & 1;                     // 2 x 2 warp grid
    int m0 = blockIdx.y * 128, n0 = blockIdx.x * 128;

    // global loads: 128 rows x 64 bf16 per operand per chunk = 1024 vec16; 8/thread/operand
    int row_t = tid >> 3;                                // 0..15
    int col_t = (tid & 7) << 3;                          // bf16 col 0..56
    uint32_t so_[8];
#pragma unroll
    for (int i = 0; i < 8; i++)
        so_[i] = (uint32_t)((row_t + 16 * i) * (LDS_ROW * 2) + col_t * 2);

    uint32_t aoff[4];
#pragma unroll
    for (int mt = 0; mt < 4; mt++)
        aoff[mt] = (uint32_t)(((wm * 64 + mt * 16 + (lane & 15)) * LDS_ROW + ((lane >> 4) << 3)) * 2);
    uint32_t boff[4];
    {
        int q = lane >> 3, r = lane & 7;
#pragma unroll
        for (int np = 0; np < 4; np++) {
            int n = wn * 64 + np * 16 + ((q >> 1) << 3) + r;
            int kc = (q & 1) << 3;
            boff[np] = (uint32_t)((n * LDS_ROW + kc) * 2);
        }
    }

    float acc[4][8][4];
#pragma unroll
    for (int i = 0; i < 4; i++)
#pragma unroll
        for (int j = 0; j < 8; j++)
#pragma unroll
            for (int e = 0; e < 4; e++) acc[i][j][e] = 0.f;

    const int NCHUNK = 96;                               // 3 passes x 32 (BK=64)

    // prologue: issue chunks 0,1 (pass 0 => Ahi/Bhi)
#pragma unroll
    for (int pc = 0; pc < 2; pc++) {
        int kk = pc << 6;
        uint32_t st = smb + pc * STAGE_T;
#pragma unroll
        for (int i = 0; i < 8; i++) {
            cp_async16(st + so_[i],           Ahi + (size_t)(m0 + row_t + 16 * i) * D_ + kk + col_t);
            cp_async16(st + STAGE_A + so_[i], Bhi + (size_t)(n0 + row_t + 16 * i) * D_ + kk + col_t);
        }
        cp_commit();
    }

    uint32_t fa0[4][4], fb0[4][4], fa1[4][4], fb1[4][4];

#define LDM_BLK(fa, fb, sA, sB, ks) do { \
    _Pragma("unroll") for (int mt = 0; mt < 4; mt++) ldmat4((fa)[mt], (sA) + aoff[mt] + (ks) * 32); \
    _Pragma("unroll") for (int np = 0; np < 4; np++) ldmat4((fb)[np], (sB) + boff[np] + (ks) * 32); \
} while (0)
#define MMA_BLK(fa, fb) do { \
    _Pragma("unroll") for (int mt = 0; mt < 4; mt++) \
        _Pragma("unroll") for (int nt = 0; nt < 8; nt++) \
            mma_bf16(acc[mt][nt], (fa)[mt], (fb)[nt >> 1][(nt & 1) * 2], (fb)[nt >> 1][(nt & 1) * 2 + 1]); \
} while (0)

    int st_c = 0;                                        // stage of chunk c
    for (int c = 0; c < NCHUNK; c++) {
        cp_wait<1>();                                    // chunk c resident (this thread)
        __syncthreads();                                 // visible; stage (c-1)%3 compute done

        uint32_t sA = smb + st_c * STAGE_T;
        uint32_t sB = sA + STAGE_A;

        LDM_BLK(fa0, fb0, sA, sB, 0);                    // frags ks0
        LDM_BLK(fa1, fb1, sA, sB, 1);                    // prefetch ks1
        MMA_BLK(fa0, fb0);                               // tensor starts immediately

        // issue next-next chunk loads while tensor pipe crunches ks0
        int cn = c + 2;
        if (cn < NCHUNK) {
            int pass = cn >> 5;
            int kk = (cn & 31) << 6;
            const __nv_bfloat16* As = (pass == 1) ? Alo : Ahi;
            const __nv_bfloat16* Bs = (pass == 2) ? Blo : Bhi;
            int stn = st_c + 2; if (stn >= NSTG3) stn -= NSTG3;   // == (c-1)%3
            uint32_t st = smb + stn * STAGE_T;
#pragma unroll
            for (int i = 0; i < 8; i++) {
                cp_async16(st + so_[i],           As + (size_t)(m0 + row_t + 16 * i) * D_ + kk + col_t);
                cp_async16(st + STAGE_A + so_[i], Bs + (size_t)(n0 + row_t + 16 * i) * D_ + kk + col_t);
            }
        }
        cp_commit();                                     // empty group in tail keeps counts

        LDM_BLK(fa0, fb0, sA, sB, 2);                    // prefetch ks2
        MMA_BLK(fa1, fb1);                               // ks1
        LDM_BLK(fa1, fb1, sA, sB, 3);                    // prefetch ks3
        MMA_BLK(fa0, fb0);                               // ks2
        MMA_BLK(fa1, fb1);                               // ks3

        st_c = (st_c + 1 == NSTG3) ? 0 : st_c + 1;
    }

    // epilogue: optional fused RoPE (acc pairs are exactly the (2i,2i+1) rope pairs)
    int tq = lane >> 2, tr = lane & 3;
#pragma unroll
    for (int mt = 0; mt < 4; mt++) {
#pragma unroll
        for (int nt = 0; nt < 8; nt++) {
            int m = m0 + wm * 64 + mt * 16 + tq;
            int n = n0 + wn * 64 + nt * 8 + tr * 2;
            float v0 = acc[mt][nt][0], v1 = acc[mt][nt][1];
            float v2 = acc[mt][nt][2], v3 = acc[mt][nt][3];
            if (use_rope) {
                int i  = (n & 127) >> 1;
                int t1 = m & 4095, t2 = (m + 8) & 4095;
                float c1 = rope_cos[t1 * 64 + i], s1 = rope_sin[t1 * 64 + i];
                float c2 = rope_cos[t2 * 64 + i], s2 = rope_sin[t2 * 64 + i];
                float r0 = v0 * c1 - v1 * s1, r1 = v0 * s1 + v1 * c1;
                float r2 = v2 * c2 - v3 * s2, r3 = v2 * s2 + v3 * c2;
                v0 = r0; v1 = r1; v2 = r2; v3 = r3;
            }
            *(float2*)&C[(size_t)m * D_ + n]       = make_float2(v0, v1);
            *(float2*)&C[(size_t)(m + 8) * D_ + n] = make_float2(v2, v3);
        }
    }
}

// ---------------- fp32 -> bf16 hi/lo split ----------------
__global__ __launch_bounds__(256) void split_kernel(
    const float* __restrict__ a, __nv_bfloat16* __restrict__ hi, __nv_bfloat16* __restrict__ lo)
{
    size_t i = ((size_t)blockIdx.x * 256 + threadIdx.x) * 4;
    float4 v = *(const float4*)&a[i];
    __nv_bfloat16 h0 = __float2bfloat16(v.x), h1 = __float2bfloat16(v.y);
    __nv_bfloat16 h2 = __float2bfloat16(v.z), h3 = __float2bfloat16(v.w);
    __nv_bfloat16 l0 = __float2bfloat16(v.x - __bfloat162float(h0));
    __nv_bfloat16 l1 = __float2bfloat16(v.y - __bfloat162float(h1));
    __nv_bfloat16 l2 = __float2bfloat16(v.z - __bfloat162float(h2));
    __nv_bfloat16 l3 = __float2bfloat16(v.w - __bfloat162float(h3));
    __nv_bfloat162* hp = (__nv_bfloat162*)(hi + i);
    __nv_bfloat162* lp = (__nv_bfloat162*)(lo + i);
    hp[0] = __halves2bfloat162(h0, h1); hp[1] = __halves2bfloat162(h2, h3);
    lp[0] = __halves2bfloat162(l0, l1); lp[1] = __halves2bfloat162(l2, l3);
}

// ---------------- all 5 weights: W[K,N] -> Wt_hi/lo[N,K] transpose+split ----------------
__global__ __launch_bounds__(256) void wsplit_all(
    const float* __restrict__ W0, const float* __restrict__ W1,
    const float* __restrict__ W2, const float* __restrict__ W3,
    const float* __restrict__ W4,
    __nv_bfloat16* __restrict__ hi, __nv_bfloat16* __restrict__ lo)
{
    __shared__ float tile[32][33];
    int z = blockIdx.z;
    const float* W = (z == 0) ? W0 : (z == 1) ? W1 : (z == 2) ? W2 : (z == 3) ? W3 : W4;
    size_t off = (size_t)z * D_ * D_;
    int k0 = blockIdx.y * 32, n0 = blockIdx.x * 32;
    int tx = threadIdx.x & 31, ty = threadIdx.x >> 5;
#pragma unroll
    for (int i = 0; i < 32; i += 8)
        tile[ty + i][tx] = W[(size_t)(k0 + ty + i) * D_ + n0 + tx];
    __syncthreads();
#pragma unroll
    for (int i = 0; i < 32; i += 8) {
        float v = tile[tx][ty + i];
        __nv_bfloat16 h = __float2bfloat16(v);
        __nv_bfloat16 l = __float2bfloat16(v - __bfloat162float(h));
        size_t oi = off + (size_t)(n0 + ty + i) * D_ + k0 + tx;
        hi[oi] = h; lo[oi] = l;
    }
}

// ============================= retention =============================
__global__ __launch_bounds__(128) void gt_kernel(
    const float* __restrict__ x, const float* __restrict__ Wgt, float* __restrict__ gt)
{
    int row = blockIdx.x;
    int tid = threadIdx.x;
    const float* xr = x + (size_t)row * D_;
    float acc[16];
#pragma unroll
    for (int h = 0; h < 16; h++) acc[h] = 0.f;
    for (int kk = tid; kk < D_; kk += 128) {
        float xv = xr[kk];
        const float4* w4 = (const float4*)(Wgt + (size_t)kk * 16);
        float4 w0 = w4[0], w1 = w4[1], w2 = w4[2], w3 = w4[3];
        acc[0]  += xv * w0.x; acc[1]  += xv * w0.y; acc[2]  += xv * w0.z; acc[3]  += xv * w0.w;
        acc[4]  += xv * w1.x; acc[5]  += xv * w1.y; acc[6]  += xv * w1.z; acc[7]  += xv * w1.w;
        acc[8]  += xv * w2.x; acc[9]  += xv * w2.y; acc[10] += xv * w2.z; acc[11] += xv * w2.w;
        acc[12] += xv * w3.x; acc[13] += xv * w3.y; acc[14] += xv * w3.z; acc[15] += xv * w3.w;
    }
#pragma unroll
    for (int h = 0; h < 16; h++)
#pragma unroll
        for (int off = 16; off > 0; off >>= 1)
            acc[h] += __shfl_down_sync(0xffffffffu, acc[h], off);
    __shared__ float part[4][16];
    int warp = tid >> 5, lane = tid & 31;
    if (lane == 0)
#pragma unroll
        for (int h = 0; h < 16; h++) part[warp][h] = acc[h];
    __syncthreads();
    if (tid < 16) {
        float s = part[0][tid] + part[1][tid] + part[2][tid] + part[3][tid];
        int b = row >> 12, t = row & 4095;
        gt[((size_t)(b * H_ + tid)) * T_ + t] = log_sigmoidf(s) * (1.f / 16.f);
    }
}

__global__ __launch_bounds__(256) void cumsum_kernel(
    const float* __restrict__ gt, float* __restrict__ gc)
{
    int bh = blockIdx.x >> 4;
    int n  = blockIdx.x & 15;
    int tid = threadIdx.x, lane = tid & 31, warp = tid >> 5;
    size_t idx = (size_t)bh * T_ + n * CH_ + tid;
    float v = gt[idx];
#pragma unroll
    for (int off = 1; off < 32; off <<= 1) {
        float y = __shfl_up_sync(0xffffffffu, v, off);
        if (lane >= off) v += y;
    }
    __shared__ float ws[8];
    if (lane == 31) ws[warp] = v;
    __syncthreads();
    if (tid == 0) {
        float s = 0.f;
#pragma unroll
        for (int w = 0; w < 8; w++) { float t = ws[w]; ws[w] = s; s += t; }
    }
    __syncthreads();
    gc[idx] = v + ws[warp];
}

__global__ __launch_bounds__(256) void sin_kernel(
    const float* __restrict__ k, const float* __restrict__ v,
    const float* __restrict__ gc, float* __restrict__ Sin)
{
    __shared__ __align__(16) float Ks[32 * 128];
    __shared__ __align__(16) float Vs[32 * 128];
    __shared__ float kd[32];
    int blk = blockIdx.x;
    int n = blk & 15, h = (blk >> 4) & 15, b = blk >> 8;
    int tid = threadIdx.x;
    int trow = tid >> 4, tcol = tid & 15;
    const float* gcc = gc + ((size_t)(b * H_ + h)) * T_ + n * CH_;
    float gtot = gcc[CH_ - 1];

    float acc[8][8];
#pragma unroll
    for (int i = 0; i < 8; i++)
#pragma unroll
        for (int j = 0; j < 8; j++) acc[i][j] = 0.f;

    for (int s0 = 0; s0 < CH_; s0 += 32) {
        __syncthreads();
        if (tid < 32) kd[tid] = expf(gtot - gcc[s0 + tid]) * SCALE_;
        __syncthreads();
#pragma unroll
        for (int l = 0; l < 4; l++) {
            int li = tid + l * 256;
            int c = li >> 5, gcol = (li & 31) << 2;
            size_t gi = ((size_t)(b * T_ + n * CH_ + s0 + c)) * D_ + h * HD_ + gcol;
            float4 kv4 = *(const float4*)&k[gi];
            float sc = kd[c];
            kv4.x *= sc; kv4.y *= sc; kv4.z *= sc; kv4.w *= sc;
            *(float4*)&Ks[c * 128 + gcol] = kv4;
            *(float4*)&Vs[c * 128 + gcol] = *(const float4*)&v[gi];
        }
        __syncthreads();
#pragma unroll
        for (int c = 0; c < 32; c++) {
            float4 a0 = *(float4*)&Ks[c * 128 + trow * 8];
            float4 a1 = *(float4*)&Ks[c * 128 + trow * 8 + 4];
            float4 b0 = *(float4*)&Vs[c * 128 + tcol * 8];
            float4 b1 = *(float4*)&Vs[c * 128 + tcol * 8 + 4];
            float a[8] = {a0.x, a0.y, a0.z, a0.w, a1.x, a1.y, a1.z, a1.w};
            float bb[8] = {b0.x, b0.y, b0.z, b0.w, b1.x, b1.y, b1.z, b1.w};
#pragma unroll
            for (int i = 0; i < 8; i++)
#pragma unroll
                for (int j = 0; j < 8; j++) acc[i][j] += a[i] * bb[j];
        }
    }
    size_t base = (size_t)blk * (HD_ * HD_);
#pragma unroll
    for (int i = 0; i < 8; i++) {
        size_t oi = base + (size_t)(trow * 8 + i) * HD_ + tcol * 8;
        *(float4*)&Sin[oi]     = make_float4(acc[i][0], acc[i][1], acc[i][2], acc[i][3]);
        *(float4*)&Sin[oi + 4] = make_float4(acc[i][4], acc[i][5], acc[i][6], acc[i][7]);
    }
}

// parallel over (bh, 8 parts of the 16K state elements); serial only over 16 chunks
__global__ __launch_bounds__(256) void scan_kernel(
    const float* __restrict__ Sin, const float* __restrict__ gc, float* __restrict__ Spre)
{
    int blk = blockIdx.x;              // 256 = 32 bh x 8 parts
    int bh = blk >> 3, part = blk & 7;
    int e0 = part * 2048 + threadIdx.x;
    float S[8];
#pragma unroll
    for (int l = 0; l < 8; l++) S[l] = 0.f;
    for (int n = 0; n < NCH_; n++) {
        float cd = expf(gc[(size_t)bh * T_ + n * CH_ + (CH_ - 1)]);
        size_t base = ((size_t)(bh * NCH_ + n)) * (HD_ * HD_);
#pragma unroll
        for (int l = 0; l < 8; l++) {
            int idx = e0 + l * 256;
            Spre[base + idx] = S[l];
            S[l] = S[l] * cd + Sin[base + idx];
        }
    }
}

#define QS_OFF  0
#define BS_OFF  8192
#define SS_OFF  16384
#define GQ_OFF  20736
#define GK_OFF  20800
#define RED_OFF 20864
#define SMF_TOT 21888

__global__ __launch_bounds__(256) void out_kernel(
    const float* __restrict__ q, const float* __restrict__ k,
    const float* __restrict__ v, const float* __restrict__ g,
    const float* __restrict__ gc, const float* __restrict__ Spre,
    __nv_bfloat16* __restrict__ ohi, __nv_bfloat16* __restrict__ olo)
{
    extern __shared__ __align__(16) float sm[];
    float* Qs  = sm + QS_OFF;
    float* Bs  = sm + BS_OFF;
    float* Ss  = sm + SS_OFF;
    float* gq  = sm + GQ_OFF;
    float* gk  = sm + GK_OFF;
    float* red = sm + RED_OFF;

    int blk = blockIdx.x;
    int rt = blk & 3, n = (blk >> 2) & 15, h = (blk >> 6) & 15, b = blk >> 10;
    int tid = threadIdx.x, trow = tid >> 4, tcol = tid & 15;
    int trow4 = trow * 4;
    const float* gcc = gc + ((size_t)(b * H_ + h)) * T_ + n * CH_;
    int c0 = rt * 64;
    int rowbase = b * T_ + n * CH_;

#pragma unroll
    for (int l = 0; l < 8; l++) {
        int li = tid + l * 256;
        int c = li >> 5, gcol = (li & 31) << 2;
        size_t gi = ((size_t)(rowbase + c0 + c)) * D_ + h * HD_ + gcol;
        *(float4*)&Qs[c * 128 + gcol] = *(const float4*)&q[gi];
    }
    if (tid < 64) gq[tid] = gcc[c0 + tid];

    float oacc[4][8];
#pragma unroll
    for (int i = 0; i < 4; i++)
#pragma unroll
        for (int j = 0; j < 8; j++) oacc[i][j] = 0.f;
    __syncthreads();

    for (int st = 0; st <= rt; st++) {
        int s0 = st * 64;
#pragma unroll
        for (int l = 0; l < 8; l++) {
            int li = tid + l * 256;
            int c = li >> 5, gr = li & 31;
            size_t gi = ((size_t)(rowbase + s0 + c)) * D_ + h * HD_ + (gr << 2);
            *(float4*)&Bs[c * 128 + ((gr ^ (c & 7)) << 2)] = *(const float4*)&k[gi];
        }
        if (tid < 64) gk[tid] = gcc[s0 + tid];
        __syncthreads();

        float sacc[4][4];
#pragma unroll
        for (int i = 0; i < 4; i++)
#pragma unroll
            for (int j = 0; j < 4; j++) sacc[i][j] = 0.f;
#pragma unroll
        for (int gr = 0; gr < 32; gr++) {
            float4 a[4];
#pragma unroll
            for (int i = 0; i < 4; i++) a[i] = *(float4*)&Qs[(trow4 + i) * 128 + (gr << 2)];
#pragma unroll
            for (int j = 0; j < 4; j++) {
                int s = tcol * 4 + j;
                float4 bb = *(float4*)&Bs[s * 128 + ((gr ^ (s & 7)) << 2)];
#pragma unroll
                for (int i = 0; i < 4; i++)
                    sacc[i][j] += a[i].x * bb.x + a[i].y * bb.y + a[i].z * bb.z + a[i].w * bb.w;
            }
        }
#pragma unroll
        for (int i = 0; i < 4; i++) {
            int r = trow4 + i;
            float gqi = gq[r];
#pragma unroll
            for (int j = 0; j < 4; j++) {
                int s = tcol * 4 + j;
                float val = 0.f;
                if (s0 + s <= c0 + r) val = sacc[i][j] * SCALE_ * expf(gqi - gk[s]);
                Ss[r * 68 + s] = val;
            }
        }
        __syncthreads();

#pragma unroll
        for (int l = 0; l < 8; l++) {
            int li = tid + l * 256;
            int c = li >> 5, gr = li & 31;
            size_t gi = ((size_t)(rowbase + s0 + c)) * D_ + h * HD_ + (gr << 2);
            *(float4*)&Bs[c * 128 + ((gr ^ (c & 7)) << 2)] = *(const float4*)&v[gi];
        }
        __syncthreads();

#pragma unroll
        for (int s = 0; s < 64; s++) {
            float4 b0 = *(float4*)&Bs[s * 128 + (((2 * tcol)     ^ (s & 7)) << 2)];
            float4 b1 = *(float4*)&Bs[s * 128 + (((2 * tcol + 1) ^ (s & 7)) << 2)];
#pragma unroll
            for (int i = 0; i < 4; i++) {
                float a = Ss[(trow4 + i) * 68 + s];
                oacc[i][0] += a * b0.x; oacc[i][1] += a * b0.y;
                oacc[i][2] += a * b0.z; oacc[i][3] += a * b0.w;
                oacc[i][4] += a * b1.x; oacc[i][5] += a * b1.y;
                oacc[i][6] += a * b1.z; oacc[i][7] += a * b1.w;
            }
        }
        __syncthreads();
    }

    float qd[4];
#pragma unroll
    for (int i = 0; i < 4; i++) qd[i] = expf(gq[trow4 + i]);
    size_t sbase = ((size_t)(blk >> 2)) * (HD_ * HD_);
    for (int d0 = 0; d0 < 128; d0 += 64) {
#pragma unroll
        for (int l = 0; l < 8; l++) {
            int li = tid + l * 256;
            int dd = li >> 5, gr = li & 31;
            *(float4*)&Bs[dd * 128 + ((gr ^ (dd & 7)) << 2)] =
                *(const float4*)&Spre[sbase + (size_t)(d0 + dd) * 128 + (gr << 2)];
        }
        __syncthreads();
#pragma unroll
        for (int dd = 0; dd < 64; dd++) {
            float4 b0 = *(float4*)&Bs[dd * 128 + (((2 * tcol)     ^ (dd & 7)) << 2)];
            float4 b1 = *(float4*)&Bs[dd * 128 + (((2 * tcol + 1) ^ (dd & 7)) << 2)];
#pragma unroll
            for (int i = 0; i < 4; i++) {
                float a = Qs[(trow4 + i) * 128 + d0 + dd] * qd[i];
                oacc[i][0] += a * b0.x; oacc[i][1] += a * b0.y;
                oacc[i][2] += a * b0.z; oacc[i][3] += a * b0.w;
                oacc[i][4] += a * b1.x; oacc[i][5] += a * b1.y;
                oacc[i][6] += a * b1.z; oacc[i][7] += a * b1.w;
            }
        }
        __syncthreads();
    }

#pragma unroll
    for (int i = 0; i < 4; i++) {
        float ss = 0.f;
#pragma unroll
        for (int j = 0; j < 8; j++) ss += oacc[i][j] * oacc[i][j];
        red[(trow4 + i) * 16 + tcol] = ss;
    }
    __syncthreads();
#pragma unroll
    for (int i = 0; i < 4; i++) {
        int r = trow4 + i;
        float ss = 0.f;
#pragma unroll
        for (int t2 = 0; t2 < 16; t2++) ss += red[r * 16 + t2];
        float rn = rsqrtf(ss * (1.0f / 128.0f) + 1e-5f);
        size_t gi = ((size_t)(rowbase + c0 + r)) * D_ + h * HD_ + tcol * 8;
        float4 g0 = *(const float4*)&g[gi];
        float4 g1 = *(const float4*)&g[gi + 4];
        float ov[8];
        ov[0] = oacc[i][0] * rn * (g0.x / (1.f + expf(-g0.x)));
        ov[1] = oacc[i][1] * rn * (g0.y / (1.f + expf(-g0.y)));
        ov[2] = oacc[i][2] * rn * (g0.z / (1.f + expf(-g0.z)));
        ov[3] = oacc[i][3] * rn * (g0.w / (1.f + expf(-g0.w)));
        ov[4] = oacc[i][4] * rn * (g1.x / (1.f + expf(-g1.x)));
        ov[5] = oacc[i][5] * rn * (g1.y / (1.f + expf(-g1.y)));
        ov[6] = oacc[i][6] * rn * (g1.z / (1.f + expf(-g1.z)));
        ov[7] = oacc[i][7] * rn * (g1.w / (1.f + expf(-g1.w)));
        __nv_bfloat162 hv[4], lv[4];
#pragma unroll
        for (int j = 0; j < 4; j++) {
            __nv_bfloat16 h0 = __float2bfloat16(ov[2*j]);
            __nv_bfloat16 h1 = __float2bfloat16(ov[2*j+1]);
            __nv_bfloat16 l0 = __float2bfloat16(ov[2*j]   - __bfloat162float(h0));
            __nv_bfloat16 l1 = __float2bfloat16(ov[2*j+1] - __bfloat162float(h1));
            hv[j] = __halves2bfloat162(h0, h1);
            lv[j] = __halves2bfloat162(l0, l1);
        }
        *(uint4*)&ohi[gi] = *(uint4*)hv;
        *(uint4*)&olo[gi] = *(uint4*)lv;
    }
}

// ============================= launcher =============================
extern "C" void kernel_launch(void* const* d_in, const int* in_sizes, int n_in,
                              void* d_out, int out_size)
{
    const float* x    = (const float*)d_in[0];
    const float* cosb = (const float*)d_in[1];
    const float* sinb = (const float*)d_in[2];
    const float* Wq   = (const float*)d_in[3];
    const float* Wk   = (const float*)d_in[4];
    const float* Wv   = (const float*)d_in[5];
    const float* Wg   = (const float*)d_in[6];
    const float* Wgt  = (const float*)d_in[7];
    const float* Wout = (const float*)d_in[8];
    float* out = (float*)d_out;

    float *q, *k, *v, *g, *gt, *gc, *sbuf, *spre;
    __nv_bfloat16 *xhi, *xlo, *ohi, *olo, *wthi, *wtlo;
    cudaGetSymbolAddress((void**)&q,    g_q);
    cudaGetSymbolAddress((void**)&k,    g_k);
    cudaGetSymbolAddress((void**)&v,    g_v);
    cudaGetSymbolAddress((void**)&g,    g_g);
    cudaGetSymbolAddress((void**)&gt,   g_gt);
    cudaGetSymbolAddress((void**)&gc,   g_gc);
    cudaGetSymbolAddress((void**)&sbuf, g_sinbuf);
    cudaGetSymbolAddress((void**)&spre, g_sprebuf);
    cudaGetSymbolAddress((void**)&xhi,  g_xhi);
    cudaGetSymbolAddress((void**)&xlo,  g_xlo);
    cudaGetSymbolAddress((void**)&ohi,  g_ohi);
    cudaGetSymbolAddress((void**)&olo,  g_olo);
    cudaGetSymbolAddress((void**)&wthi, g_wthi);
    cudaGetSymbolAddress((void**)&wtlo, g_wtlo);

    cudaFuncSetAttribute(out_kernel, cudaFuncAttributeMaxDynamicSharedMemorySize,
                         SMF_TOT * sizeof(float));
    cudaFuncSetAttribute(tc_gemm, cudaFuncAttributeMaxDynamicSharedMemorySize, TCG_SMEM);

    const size_t WSZ = (size_t)D_ * D_;
    dim3 wgrid(D_ / 32, D_ / 32, 5);
    dim3 ggrid4(D_ / 128, BT_ / 128, 4);   // merged q,k,v,g projections (4096 CTAs)
    dim3 ggrid1(D_ / 128, BT_ / 128, 1);   // output projection

    wsplit_all<<<wgrid, 256>>>(Wq, Wk, Wv, Wg, Wout, wthi, wtlo);
    split_kernel<<<(BT_ * (D_ / 4)) / 256, 256>>>(x, xhi, xlo);

    // one merged launch: z=0..3 -> q(rope), k(rope), v, g
    tc_gemm<<<ggrid4, 128, TCG_SMEM>>>(xhi, xlo, wthi, wtlo, q, k, v, g, cosb, sinb);

    gt_kernel<<<BT_, 128>>>(x, Wgt, gt);
    cumsum_kernel<<<B_ * H_ * NCH_, 256>>>(gt, gc);
    sin_kernel<<<B_ * H_ * NCH_, 256>>>(k, v, gc, sbuf);
    scan_kernel<<<B_ * H_ * 8, 256>>>(sbuf, gc, spre);
    out_kernel<<<B_ * H_ * NCH_ * 4, 256, SMF_TOT * sizeof(float)>>>(q, k, v, g, gc, spre, ohi, olo);

    // output projection (weight slice 4 via base offset; z=0, no rope)
    tc_gemm<<<ggrid1, 128, TCG_SMEM>>>(ohi, olo, wthi + 4 * WSZ, wtlo + 4 * WSZ,
                                       out, out, out, out, nullptr, nullptr);
}

// round 13
// speedup vs baseline: 2.5293x; 1.0243x over previous
#include <cuda_runtime.h>
#include <cuda_bf16.h>
#include <cstdint>

#define B_   2
#define T_   4096
#define D_   2048
#define H_   16
#define HD_  128
#define CH_  256
#define NCH_ 16
#define BT_  (B_*T_)
#define SCALE_ 0.08838834764831845f

// ---------------- scratch ----------------
__device__ float g_q[(size_t)BT_*D_];
__device__ float g_k[(size_t)BT_*D_];
__device__ float g_v[(size_t)BT_*D_];
__device__ float g_g[(size_t)BT_*D_];
__device__ float g_gt[B_*H_*T_];
__device__ float g_gc[B_*H_*T_];
__device__ float g_sinbuf [(size_t)B_*H_*NCH_*HD_*HD_];
__device__ float g_sprebuf[(size_t)B_*H_*NCH_*HD_*HD_];
__device__ __nv_bfloat16 g_xhi[(size_t)BT_*D_];
__device__ __nv_bfloat16 g_xlo[(size_t)BT_*D_];
__device__ __nv_bfloat16 g_ohi[(size_t)BT_*D_];
__device__ __nv_bfloat16 g_olo[(size_t)BT_*D_];
__device__ __nv_bfloat16 g_wthi[5*(size_t)D_*D_];   // W^T [N,K]: q,k,v,g,out
__device__ __nv_bfloat16 g_wtlo[5*(size_t)D_*D_];

__device__ __forceinline__ float log_sigmoidf(float z) {
    return (z >= 0.f) ? -log1pf(expf(-z)) : (z - log1pf(expf(z)));
}

// ============================= MMA helpers =============================
__device__ __forceinline__ uint32_t smem_u32(const void* p) {
    uint32_t a;
    asm("{ .reg .u64 t; cvta.to.shared.u64 t, %1; cvt.u32.u64 %0, t; }" : "=r"(a) : "l"(p));
    return a;
}
__device__ __forceinline__ void cp_async16(uint32_t s, const void* g) {
    asm volatile("cp.async.cg.shared.global [%0], [%1], 16;" :: "r"(s), "l"(g));
}
__device__ __forceinline__ void cp_commit() { asm volatile("cp.async.commit_group;"); }
template<int N> __device__ __forceinline__ void cp_wait() {
    asm volatile("cp.async.wait_group %0;" :: "n"(N));
}
__device__ __forceinline__ void ldmat4(uint32_t* r, uint32_t a) {
    asm volatile("ldmatrix.sync.aligned.m8n8.x4.shared.b16 {%0,%1,%2,%3}, [%4];"
        : "=r"(r[0]), "=r"(r[1]), "=r"(r[2]), "=r"(r[3]) : "r"(a));
}
__device__ __forceinline__ void mma_bf16(float* d, const uint32_t* a, uint32_t b0, uint32_t b1) {
    asm volatile(
        "mma.sync.aligned.m16n8k16.row.col.f32.bf16.bf16.f32 "
        "{%0,%1,%2,%3}, {%4,%5,%6,%7}, {%8,%9}, {%0,%1,%2,%3};"
        : "+f"(d[0]), "+f"(d[1]), "+f"(d[2]), "+f"(d[3])
        : "r"(a[0]), "r"(a[1]), "r"(a[2]), "r"(a[3]), "r"(b0), "r"(b1));
}

// ============================= tensor-core GEMM =============================
// C[M,2048] = (Ahi+Alo)[M,2048] @ (Bhi+Blo)^T, B operands [N,K] row-major.
// blockIdx.z selects the weight slice + output pointer (merged multi-GEMM launch).
// 128x128 CTA tile, BK=64, 4 warps (2x2), warp tile 64x64.
// 3-stage cp.async pipeline (issue distance 2), one __syncthreads per chunk,
// software-pipelined ldmatrix (double-buffered fragments).
// RoPE fused in epilogue for z<2 when rope pointers given (q and k projections).
#define LDS_ROW 72                      // bf16 per smem row (144 B; 4-bank row stride, 16B aligned)
#define STAGE_A (128 * LDS_ROW * 2)     // 18432 B
#define STAGE_T (2 * STAGE_A)           // 36864 B (A + B)
#define NSTG3   3
#define TCG_SMEM (NSTG3 * STAGE_T)      // 110592 B

__global__ void __launch_bounds__(128, 2) tc_gemm(
    const __nv_bfloat16* __restrict__ Ahi, const __nv_bfloat16* __restrict__ Alo,
    const __nv_bfloat16* __restrict__ BhiBase, const __nv_bfloat16* __restrict__ BloBase,
    float* __restrict__ C0, float* __restrict__ C1,
    float* __restrict__ C2, float* __restrict__ C3,
    const float* __restrict__ rope_cos, const float* __restrict__ rope_sin)
{
    extern __shared__ __align__(16) char smem[];
    const uint32_t smb = smem_u32(smem);

    int z = blockIdx.z;
    const __nv_bfloat16* Bhi = BhiBase + (size_t)z * D_ * D_;
    const __nv_bfloat16* Blo = BloBase + (size_t)z * D_ * D_;
    float* C = (z == 0) ? C0 : (z == 1) ? C1 : (z == 2) ? C2 : C3;
    bool use_rope = (rope_cos != nullptr) && (z < 2);

    int tid = threadIdx.x, lane = tid & 31, wid = tid >> 5;
    int wm = wid >> 1, wn = wid & 1;                     // 2 x 2 warp grid
    int m0 = blockIdx.y * 128, n0 = blockIdx.x * 128;

    int row_t = tid >> 3;                                // 0..15
    int col_t = (tid & 7) << 3;                          // bf16 col 0..56
    uint32_t so_[8];
#pragma unroll
    for (int i = 0; i < 8; i++)
        so_[i] = (uint32_t)((row_t + 16 * i) * (LDS_ROW * 2) + col_t * 2);

    uint32_t aoff[4];
#pragma unroll
    for (int mt = 0; mt < 4; mt++)
        aoff[mt] = (uint32_t)(((wm * 64 + mt * 16 + (lane & 15)) * LDS_ROW + ((lane >> 4) << 3)) * 2);
    uint32_t boff[4];
    {
        int q = lane >> 3, r = lane & 7;
#pragma unroll
        for (int np = 0; np < 4; np++) {
            int n = wn * 64 + np * 16 + ((q >> 1) << 3) + r;
            int kc = (q & 1) << 3;
            boff[np] = (uint32_t)((n * LDS_ROW + kc) * 2);
        }
    }

    float acc[4][8][4];
#pragma unroll
    for (int i = 0; i < 4; i++)
#pragma unroll
        for (int j = 0; j < 8; j++)
#pragma unroll
            for (int e = 0; e < 4; e++) acc[i][j][e] = 0.f;

    const int NCHUNK = 96;                               // 3 passes x 32 (BK=64)

#pragma unroll
    for (int pc = 0; pc < 2; pc++) {
        int kk = pc << 6;
        uint32_t st = smb + pc * STAGE_T;
#pragma unroll
        for (int i = 0; i < 8; i++) {
            cp_async16(st + so_[i],           Ahi + (size_t)(m0 + row_t + 16 * i) * D_ + kk + col_t);
            cp_async16(st + STAGE_A + so_[i], Bhi + (size_t)(n0 + row_t + 16 * i) * D_ + kk + col_t);
        }
        cp_commit();
    }

    uint32_t fa0[4][4], fb0[4][4], fa1[4][4], fb1[4][4];

#define LDM_BLK(fa, fb, sA, sB, ks) do { \
    _Pragma("unroll") for (int mt = 0; mt < 4; mt++) ldmat4((fa)[mt], (sA) + aoff[mt] + (ks) * 32); \
    _Pragma("unroll") for (int np = 0; np < 4; np++) ldmat4((fb)[np], (sB) + boff[np] + (ks) * 32); \
} while (0)
#define MMA_BLK(fa, fb) do { \
    _Pragma("unroll") for (int mt = 0; mt < 4; mt++) \
        _Pragma("unroll") for (int nt = 0; nt < 8; nt++) \
            mma_bf16(acc[mt][nt], (fa)[mt], (fb)[nt >> 1][(nt & 1) * 2], (fb)[nt >> 1][(nt & 1) * 2 + 1]); \
} while (0)

    int st_c = 0;
    for (int c = 0; c < NCHUNK; c++) {
        cp_wait<1>();
        __syncthreads();

        uint32_t sA = smb + st_c * STAGE_T;
        uint32_t sB = sA + STAGE_A;

        LDM_BLK(fa0, fb0, sA, sB, 0);
        LDM_BLK(fa1, fb1, sA, sB, 1);
        MMA_BLK(fa0, fb0);

        int cn = c + 2;
        if (cn < NCHUNK) {
            int pass = cn >> 5;
            int kk = (cn & 31) << 6;
            const __nv_bfloat16* As = (pass == 1) ? Alo : Ahi;
            const __nv_bfloat16* Bs = (pass == 2) ? Blo : Bhi;
            int stn = st_c + 2; if (stn >= NSTG3) stn -= NSTG3;
            uint32_t st = smb + stn * STAGE_T;
#pragma unroll
            for (int i = 0; i < 8; i++) {
                cp_async16(st + so_[i],           As + (size_t)(m0 + row_t + 16 * i) * D_ + kk + col_t);
                cp_async16(st + STAGE_A + so_[i], Bs + (size_t)(n0 + row_t + 16 * i) * D_ + kk + col_t);
            }
        }
        cp_commit();

        LDM_BLK(fa0, fb0, sA, sB, 2);
        MMA_BLK(fa1, fb1);
        LDM_BLK(fa1, fb1, sA, sB, 3);
        MMA_BLK(fa0, fb0);
        MMA_BLK(fa1, fb1);

        st_c = (st_c + 1 == NSTG3) ? 0 : st_c + 1;
    }

    int tq = lane >> 2, tr = lane & 3;
#pragma unroll
    for (int mt = 0; mt < 4; mt++) {
#pragma unroll
        for (int nt = 0; nt < 8; nt++) {
            int m = m0 + wm * 64 + mt * 16 + tq;
            int n = n0 + wn * 64 + nt * 8 + tr * 2;
            float v0 = acc[mt][nt][0], v1 = acc[mt][nt][1];
            float v2 = acc[mt][nt][2], v3 = acc[mt][nt][3];
            if (use_rope) {
                int i  = (n & 127) >> 1;
                int t1 = m & 4095, t2 = (m + 8) & 4095;
                float c1 = rope_cos[t1 * 64 + i], s1 = rope_sin[t1 * 64 + i];
                float c2 = rope_cos[t2 * 64 + i], s2 = rope_sin[t2 * 64 + i];
                float r0 = v0 * c1 - v1 * s1, r1 = v0 * s1 + v1 * c1;
                float r2 = v2 * c2 - v3 * s2, r3 = v2 * s2 + v3 * c2;
                v0 = r0; v1 = r1; v2 = r2; v3 = r3;
            }
            *(float2*)&C[(size_t)m * D_ + n]       = make_float2(v0, v1);
            *(float2*)&C[(size_t)(m + 8) * D_ + n] = make_float2(v2, v3);
        }
    }
}

// ---------------- fp32 -> bf16 hi/lo split ----------------
__global__ __launch_bounds__(256) void split_kernel(
    const float* __restrict__ a, __nv_bfloat16* __restrict__ hi, __nv_bfloat16* __restrict__ lo)
{
    size_t i = ((size_t)blockIdx.x * 256 + threadIdx.x) * 4;
    float4 v = *(const float4*)&a[i];
    __nv_bfloat16 h0 = __float2bfloat16(v.x), h1 = __float2bfloat16(v.y);
    __nv_bfloat16 h2 = __float2bfloat16(v.z), h3 = __float2bfloat16(v.w);
    __nv_bfloat16 l0 = __float2bfloat16(v.x - __bfloat162float(h0));
    __nv_bfloat16 l1 = __float2bfloat16(v.y - __bfloat162float(h1));
    __nv_bfloat16 l2 = __float2bfloat16(v.z - __bfloat162float(h2));
    __nv_bfloat16 l3 = __float2bfloat16(v.w - __bfloat162float(h3));
    __nv_bfloat162* hp = (__nv_bfloat162*)(hi + i);
    __nv_bfloat162* lp = (__nv_bfloat162*)(lo + i);
    hp[0] = __halves2bfloat162(h0, h1); hp[1] = __halves2bfloat162(h2, h3);
    lp[0] = __halves2bfloat162(l0, l1); lp[1] = __halves2bfloat162(l2, l3);
}

// ---------------- all 5 weights: W[K,N] -> Wt_hi/lo[N,K] transpose+split ----------------
__global__ __launch_bounds__(256) void wsplit_all(
    const float* __restrict__ W0, const float* __restrict__ W1,
    const float* __restrict__ W2, const float* __restrict__ W3,
    const float* __restrict__ W4,
    __nv_bfloat16* __restrict__ hi, __nv_bfloat16* __restrict__ lo)
{
    __shared__ float tile[32][33];
    int z = blockIdx.z;
    const float* W = (z == 0) ? W0 : (z == 1) ? W1 : (z == 2) ? W2 : (z == 3) ? W3 : W4;
    size_t off = (size_t)z * D_ * D_;
    int k0 = blockIdx.y * 32, n0 = blockIdx.x * 32;
    int tx = threadIdx.x & 31, ty = threadIdx.x >> 5;
#pragma unroll
    for (int i = 0; i < 32; i += 8)
        tile[ty + i][tx] = W[(size_t)(k0 + ty + i) * D_ + n0 + tx];
    __syncthreads();
#pragma unroll
    for (int i = 0; i < 32; i += 8) {
        float v = tile[tx][ty + i];
        __nv_bfloat16 h = __float2bfloat16(v);
        __nv_bfloat16 l = __float2bfloat16(v - __bfloat162float(h));
        size_t oi = off + (size_t)(n0 + ty + i) * D_ + k0 + tx;
        hi[oi] = h; lo[oi] = l;
    }
}

// ============================= retention =============================
// gt = log_sigmoid(x @ Wgt)/GLN, stored [B,H,T].
// 4 rows per block, Wgt register-cached per thread; smem-transpose reduction
// (no giant unrolled shuffle tree -> small codegen).
__global__ __launch_bounds__(128) void gt_kernel(
    const float* __restrict__ x, const float* __restrict__ Wgt, float* __restrict__ gt)
{
    __shared__ float red[64][33];        // [r*16+h][thread-group]
    int row0 = blockIdx.x * 4;
    int tid = threadIdx.x;
    float acc[4][16];
#pragma unroll
    for (int r = 0; r < 4; r++)
#pragma unroll
        for (int h = 0; h < 16; h++) acc[r][h] = 0.f;

    for (int kk = tid; kk < D_; kk += 128) {
        const float4* w4 = (const float4*)(Wgt + (size_t)kk * 16);
        float4 w0 = w4[0], w1 = w4[1], w2 = w4[2], w3 = w4[3];
        float w[16] = {w0.x, w0.y, w0.z, w0.w, w1.x, w1.y, w1.z, w1.w,
                       w2.x, w2.y, w2.z, w2.w, w3.x, w3.y, w3.z, w3.w};
#pragma unroll
        for (int r = 0; r < 4; r++) {
            float xv = x[(size_t)(row0 + r) * D_ + kk];
#pragma unroll
            for (int h = 0; h < 16; h++) acc[r][h] += xv * w[h];
        }
    }
    // reduce 128 threads -> 1 per (r,h) via smem: 4 sweeps of 32 lanes
    int grp = tid >> 2, sub = tid & 3;   // 32 groups x 4
#pragma unroll
    for (int r = 0; r < 4; r++) {
#pragma unroll
        for (int h = 0; h < 16; h++) {
            // thread tid holds partial for (r,h); fold 128 partials in smem
        }
    }
    // simple two-phase: each thread writes its 64 partials spread over 2 sweeps
#pragma unroll
    for (int half = 0; half < 2; half++) {
        __syncthreads();
#pragma unroll
        for (int r = 0; r < 2; r++) {
            int rr = half * 2 + r;
#pragma unroll
            for (int h = 0; h < 16; h++) {
                // accumulate into red[rr*16+h][tid>>2] with 4-way conflict-free adds
                if (sub == 0) red[(r << 4) + h][grp] = acc[rr][h];
            }
        }
        __syncthreads();
#pragma unroll
        for (int r = 0; r < 2; r++) {
            int rr = half * 2 + r;
#pragma unroll
            for (int h = 0; h < 16; h++) {
                if (sub == 1) red[(r << 4) + h][grp] += acc[rr][h];
            }
        }
        __syncthreads();
#pragma unroll
        for (int r = 0; r < 2; r++) {
            int rr = half * 2 + r;
#pragma unroll
            for (int h = 0; h < 16; h++) {
                if (sub == 2) red[(r << 4) + h][grp] += acc[rr][h];
            }
        }
        __syncthreads();
#pragma unroll
        for (int r = 0; r < 2; r++) {
            int rr = half * 2 + r;
#pragma unroll
            for (int h = 0; h < 16; h++) {
                if (sub == 3) red[(r << 4) + h][grp] += acc[rr][h];
            }
        }
        __syncthreads();
        // now red[(r<<4)+h][0..31] holds 32 partials; reduce with 32 threads each
        if (tid < 32) {
#pragma unroll
            for (int rh = 0; rh < 32; rh++) {
                // each of 32 threads handles one (r,h) pair via rh == its index? no:
            }
        }
        // final: 32 (r,h) pairs this half; thread t<32 reduces pair t
        if (tid < 32) {
            float s = 0.f;
#pragma unroll
            for (int c = 0; c < 32; c++) s += red[tid][c];
            int rr = half * 2 + (tid >> 4);
            int h = tid & 15;
            int row = row0 + rr;
            int b = row >> 12, t = row & 4095;
            gt[((size_t)(b * H_ + h)) * T_ + t] = log_sigmoidf(s) * (1.f / 16.f);
        }
    }
}

__global__ __launch_bounds__(256) void cumsum_kernel(
    const float* __restrict__ gt, float* __restrict__ gc)
{
    int bh = blockIdx.x >> 4;
    int n  = blockIdx.x & 15;
    int tid = threadIdx.x, lane = tid & 31, warp = tid >> 5;
    size_t idx = (size_t)bh * T_ + n * CH_ + tid;
    float v = gt[idx];
#pragma unroll
    for (int off = 1; off < 32; off <<= 1) {
        float y = __shfl_up_sync(0xffffffffu, v, off);
        if (lane >= off) v += y;
    }
    __shared__ float ws[8];
    if (lane == 31) ws[warp] = v;
    __syncthreads();
    if (tid == 0) {
        float s = 0.f;
#pragma unroll
        for (int w = 0; w < 8; w++) { float t = ws[w]; ws[w] = s; s += t; }
    }
    __syncthreads();
    gc[idx] = v + ws[warp];
}

__global__ __launch_bounds__(256) void sin_kernel(
    const float* __restrict__ k, const float* __restrict__ v,
    const float* __restrict__ gc, float* __restrict__ Sin)
{
    __shared__ __align__(16) float Ks[32 * 128];
    __shared__ __align__(16) float Vs[32 * 128];
    __shared__ float kd[32];
    int blk = blockIdx.x;
    int n = blk & 15, h = (blk >> 4) & 15, b = blk >> 8;
    int tid = threadIdx.x;
    int trow = tid >> 4, tcol = tid & 15;
    const float* gcc = gc + ((size_t)(b * H_ + h)) * T_ + n * CH_;
    float gtot = gcc[CH_ - 1];

    float acc[8][8];
#pragma unroll
    for (int i = 0; i < 8; i++)
#pragma unroll
        for (int j = 0; j < 8; j++) acc[i][j] = 0.f;

    for (int s0 = 0; s0 < CH_; s0 += 32) {
        __syncthreads();
        if (tid < 32) kd[tid] = expf(gtot - gcc[s0 + tid]) * SCALE_;
        __syncthreads();
#pragma unroll
        for (int l = 0; l < 4; l++) {
            int li = tid + l * 256;
            int c = li >> 5, gcol = (li & 31) << 2;
            size_t gi = ((size_t)(b * T_ + n * CH_ + s0 + c)) * D_ + h * HD_ + gcol;
            float4 kv4 = *(const float4*)&k[gi];
            float sc = kd[c];
            kv4.x *= sc; kv4.y *= sc; kv4.z *= sc; kv4.w *= sc;
            *(float4*)&Ks[c * 128 + gcol] = kv4;
            *(float4*)&Vs[c * 128 + gcol] = *(const float4*)&v[gi];
        }
        __syncthreads();
#pragma unroll
        for (int c = 0; c < 32; c++) {
            float4 a0 = *(float4*)&Ks[c * 128 + trow * 8];
            float4 a1 = *(float4*)&Ks[c * 128 + trow * 8 + 4];
            float4 b0 = *(float4*)&Vs[c * 128 + tcol * 8];
            float4 b1 = *(float4*)&Vs[c * 128 + tcol * 8 + 4];
            float a[8] = {a0.x, a0.y, a0.z, a0.w, a1.x, a1.y, a1.z, a1.w};
            float bb[8] = {b0.x, b0.y, b0.z, b0.w, b1.x, b1.y, b1.z, b1.w};
#pragma unroll
            for (int i = 0; i < 8; i++)
#pragma unroll
                for (int j = 0; j < 8; j++) acc[i][j] += a[i] * bb[j];
        }
    }
    size_t base = (size_t)blk * (HD_ * HD_);
#pragma unroll
    for (int i = 0; i < 8; i++) {
        size_t oi = base + (size_t)(trow * 8 + i) * HD_ + tcol * 8;
        *(float4*)&Sin[oi]     = make_float4(acc[i][0], acc[i][1], acc[i][2], acc[i][3]);
        *(float4*)&Sin[oi + 4] = make_float4(acc[i][4], acc[i][5], acc[i][6], acc[i][7]);
    }
}

// parallel over (bh, 8 parts of the 16K state elements); serial only over 16 chunks
__global__ __launch_bounds__(256) void scan_kernel(
    const float* __restrict__ Sin, const float* __restrict__ gc, float* __restrict__ Spre)
{
    int blk = blockIdx.x;              // 256 = 32 bh x 8 parts
    int bh = blk >> 3, part = blk & 7;
    int e0 = part * 2048 + threadIdx.x;
    float S[8];
#pragma unroll
    for (int l = 0; l < 8; l++) S[l] = 0.f;
    for (int n = 0; n < NCH_; n++) {
        float cd = expf(gc[(size_t)bh * T_ + n * CH_ + (CH_ - 1)]);
        size_t base = ((size_t)(bh * NCH_ + n)) * (HD_ * HD_);
#pragma unroll
        for (int l = 0; l < 8; l++) {
            int idx = e0 + l * 256;
            Spre[base + idx] = S[l];
            S[l] = S[l] * cd + Sin[base + idx];
        }
    }
}

#define QS_OFF  0
#define BS_OFF  8192
#define SS_OFF  16384
#define GQ_OFF  20736
#define GK_OFF  20800
#define RED_OFF 20864
#define SMF_TOT 21888

__global__ __launch_bounds__(256) void out_kernel(
    const float* __restrict__ q, const float* __restrict__ k,
    const float* __restrict__ v, const float* __restrict__ g,
    const float* __restrict__ gc, const float* __restrict__ Spre,
    __nv_bfloat16* __restrict__ ohi, __nv_bfloat16* __restrict__ olo)
{
    extern __shared__ __align__(16) float sm[];
    float* Qs  = sm + QS_OFF;
    float* Bs  = sm + BS_OFF;
    float* Ss  = sm + SS_OFF;
    float* gq  = sm + GQ_OFF;
    float* gk  = sm + GK_OFF;
    float* red = sm + RED_OFF;

    int blk = blockIdx.x;
    int rt = blk & 3, n = (blk >> 2) & 15, h = (blk >> 6) & 15, b = blk >> 10;
    int tid = threadIdx.x, trow = tid >> 4, tcol = tid & 15;
    int trow4 = trow * 4;
    const float* gcc = gc + ((size_t)(b * H_ + h)) * T_ + n * CH_;
    int c0 = rt * 64;
    int rowbase = b * T_ + n * CH_;

#pragma unroll
    for (int l = 0; l < 8; l++) {
        int li = tid + l * 256;
        int c = li >> 5, gcol = (li & 31) << 2;
        size_t gi = ((size_t)(rowbase + c0 + c)) * D_ + h * HD_ + gcol;
        *(float4*)&Qs[c * 128 + gcol] = *(const float4*)&q[gi];
    }
    if (tid < 64) gq[tid] = gcc[c0 + tid];

    float oacc[4][8];
#pragma unroll
    for (int i = 0; i < 4; i++)
#pragma unroll
        for (int j = 0; j < 8; j++) oacc[i][j] = 0.f;
    __syncthreads();

    for (int st = 0; st <= rt; st++) {
        int s0 = st * 64;
#pragma unroll
        for (int l = 0; l < 8; l++) {
            int li = tid + l * 256;
            int c = li >> 5, gr = li & 31;
            size_t gi = ((size_t)(rowbase + s0 + c)) * D_ + h * HD_ + (gr << 2);
            *(float4*)&Bs[c * 128 + ((gr ^ (c & 7)) << 2)] = *(const float4*)&k[gi];
        }
        if (tid < 64) gk[tid] = gcc[s0 + tid];
        __syncthreads();

        float sacc[4][4];
#pragma unroll
        for (int i = 0; i < 4; i++)
#pragma unroll
            for (int j = 0; j < 4; j++) sacc[i][j] = 0.f;
#pragma unroll
        for (int gr = 0; gr < 32; gr++) {
            float4 a[4];
#pragma unroll
            for (int i = 0; i < 4; i++) a[i] = *(float4*)&Qs[(trow4 + i) * 128 + (gr << 2)];
#pragma unroll
            for (int j = 0; j < 4; j++) {
                int s = tcol * 4 + j;
                float4 bb = *(float4*)&Bs[s * 128 + ((gr ^ (s & 7)) << 2)];
#pragma unroll
                for (int i = 0; i < 4; i++)
                    sacc[i][j] += a[i].x * bb.x + a[i].y * bb.y + a[i].z * bb.z + a[i].w * bb.w;
            }
        }
#pragma unroll
        for (int i = 0; i < 4; i++) {
            int r = trow4 + i;
            float gqi = gq[r];
#pragma unroll
            for (int j = 0; j < 4; j++) {
                int s = tcol * 4 + j;
                float val = 0.f;
                if (s0 + s <= c0 + r) val = sacc[i][j] * SCALE_ * expf(gqi - gk[s]);
                Ss[r * 68 + s] = val;
            }
        }
        __syncthreads();

#pragma unroll
        for (int l = 0; l < 8; l++) {
            int li = tid + l * 256;
            int c = li >> 5, gr = li & 31;
            size_t gi = ((size_t)(rowbase + s0 + c)) * D_ + h * HD_ + (gr << 2);
            *(float4*)&Bs[c * 128 + ((gr ^ (c & 7)) << 2)] = *(const float4*)&v[gi];
        }
        __syncthreads();

#pragma unroll
        for (int s = 0; s < 64; s++) {
            float4 b0 = *(float4*)&Bs[s * 128 + (((2 * tcol)     ^ (s & 7)) << 2)];
            float4 b1 = *(float4*)&Bs[s * 128 + (((2 * tcol + 1) ^ (s & 7)) << 2)];
#pragma unroll
            for (int i = 0; i < 4; i++) {
                float a = Ss[(trow4 + i) * 68 + s];
                oacc[i][0] += a * b0.x; oacc[i][1] += a * b0.y;
                oacc[i][2] += a * b0.z; oacc[i][3] += a * b0.w;
                oacc[i][4] += a * b1.x; oacc[i][5] += a * b1.y;
                oacc[i][6] += a * b1.z; oacc[i][7] += a * b1.w;
            }
        }
        __syncthreads();
    }

    float qd[4];
#pragma unroll
    for (int i = 0; i < 4; i++) qd[i] = expf(gq[trow4 + i]);
    size_t sbase = ((size_t)(blk >> 2)) * (HD_ * HD_);
    for (int d0 = 0; d0 < 128; d0 += 64) {
#pragma unroll
        for (int l = 0; l < 8; l++) {
            int li = tid + l * 256;
            int dd = li >> 5, gr = li & 31;
            *(float4*)&Bs[dd * 128 + ((gr ^ (dd & 7)) << 2)] =
                *(const float4*)&Spre[sbase + (size_t)(d0 + dd) * 128 + (gr << 2)];
        }
        __syncthreads();
#pragma unroll
        for (int dd = 0; dd < 64; dd++) {
            float4 b0 = *(float4*)&Bs[dd * 128 + (((2 * tcol)     ^ (dd & 7)) << 2)];
            float4 b1 = *(float4*)&Bs[dd * 128 + (((2 * tcol + 1) ^ (dd & 7)) << 2)];
#pragma unroll
            for (int i = 0; i < 4; i++) {
                float a = Qs[(trow4 + i) * 128 + d0 + dd] * qd[i];
                oacc[i][0] += a * b0.x; oacc[i][1] += a * b0.y;
                oacc[i][2] += a * b0.z; oacc[i][3] += a * b0.w;
                oacc[i][4] += a * b1.x; oacc[i][5] += a * b1.y;
                oacc[i][6] += a * b1.z; oacc[i][7] += a * b1.w;
            }
        }
        __syncthreads();
    }

#pragma unroll
    for (int i = 0; i < 4; i++) {
        float ss = 0.f;
#pragma unroll
        for (int j = 0; j < 8; j++) ss += oacc[i][j] * oacc[i][j];
        red[(trow4 + i) * 16 + tcol] = ss;
    }
    __syncthreads();
#pragma unroll
    for (int i = 0; i < 4; i++) {
        int r = trow4 + i;
        float ss = 0.f;
#pragma unroll
        for (int t2 = 0; t2 < 16; t2++) ss += red[r * 16 + t2];
        float rn = rsqrtf(ss * (1.0f / 128.0f) + 1e-5f);
        size_t gi = ((size_t)(rowbase + c0 + r)) * D_ + h * HD_ + tcol * 8;
        float4 g0 = *(const float4*)&g[gi];
        float4 g1 = *(const float4*)&g[gi + 4];
        float ov[8];
        ov[0] = oacc[i][0] * rn * (g0.x / (1.f + expf(-g0.x)));
        ov[1] = oacc[i][1] * rn * (g0.y / (1.f + expf(-g0.y)));
        ov[2] = oacc[i][2] * rn * (g0.z / (1.f + expf(-g0.z)));
        ov[3] = oacc[i][3] * rn * (g0.w / (1.f + expf(-g0.w)));
        ov[4] = oacc[i][4] * rn * (g1.x / (1.f + expf(-g1.x)));
        ov[5] = oacc[i][5] * rn * (g1.y / (1.f + expf(-g1.y)));
        ov[6] = oacc[i][6] * rn * (g1.z / (1.f + expf(-g1.z)));
        ov[7] = oacc[i][7] * rn * (g1.w / (1.f + expf(-g1.w)));
        __nv_bfloat162 hv[4], lv[4];
#pragma unroll
        for (int j = 0; j < 4; j++) {
            __nv_bfloat16 h0 = __float2bfloat16(ov[2*j]);
            __nv_bfloat16 h1 = __float2bfloat16(ov[2*j+1]);
            __nv_bfloat16 l0 = __float2bfloat16(ov[2*j]   - __bfloat162float(h0));
            __nv_bfloat16 l1 = __float2bfloat16(ov[2*j+1] - __bfloat162float(h1));
            hv[j] = __halves2bfloat162(h0, h1);
            lv[j] = __halves2bfloat162(l0, l1);
        }
        *(uint4*)&ohi[gi] = *(uint4*)hv;
        *(uint4*)&olo[gi] = *(uint4*)lv;
    }
}

// ============================= launcher =============================
extern "C" void kernel_launch(void* const* d_in, const int* in_sizes, int n_in,
                              void* d_out, int out_size)
{
    const float* x    = (const float*)d_in[0];
    const float* cosb = (const float*)d_in[1];
    const float* sinb = (const float*)d_in[2];
    const float* Wq   = (const float*)d_in[3];
    const float* Wk   = (const float*)d_in[4];
    const float* Wv   = (const float*)d_in[5];
    const float* Wg   = (const float*)d_in[6];
    const float* Wgt  = (const float*)d_in[7];
    const float* Wout = (const float*)d_in[8];
    float* out = (float*)d_out;

    float *q, *k, *v, *g, *gt, *gc, *sbuf, *spre;
    __nv_bfloat16 *xhi, *xlo, *ohi, *olo, *wthi, *wtlo;
    cudaGetSymbolAddress((void**)&q,    g_q);
    cudaGetSymbolAddress((void**)&k,    g_k);
    cudaGetSymbolAddress((void**)&v,    g_v);
    cudaGetSymbolAddress((void**)&g,    g_g);
    cudaGetSymbolAddress((void**)&gt,   g_gt);
    cudaGetSymbolAddress((void**)&gc,   g_gc);
    cudaGetSymbolAddress((void**)&sbuf, g_sinbuf);
    cudaGetSymbolAddress((void**)&spre, g_sprebuf);
    cudaGetSymbolAddress((void**)&xhi,  g_xhi);
    cudaGetSymbolAddress((void**)&xlo,  g_xlo);
    cudaGetSymbolAddress((void**)&ohi,  g_ohi);
    cudaGetSymbolAddress((void**)&olo,  g_olo);
    cudaGetSymbolAddress((void**)&wthi, g_wthi);
    cudaGetSymbolAddress((void**)&wtlo, g_wtlo);

    cudaFuncSetAttribute(out_kernel, cudaFuncAttributeMaxDynamicSharedMemorySize,
                         SMF_TOT * sizeof(float));
    cudaFuncSetAttribute(tc_gemm, cudaFuncAttributeMaxDynamicSharedMemorySize, TCG_SMEM);

    const size_t WSZ = (size_t)D_ * D_;
    dim3 wgrid(D_ / 32, D_ / 32, 5);
    dim3 ggrid4(D_ / 128, BT_ / 128, 4);   // merged q,k,v,g projections
    dim3 ggrid1(D_ / 128, BT_ / 128, 1);   // output projection

    // order: x-only kernels first so launch #6 (ncu window) = sin_kernel
    wsplit_all<<<wgrid, 256>>>(Wq, Wk, Wv, Wg, Wout, wthi, wtlo);        // 1
    split_kernel<<<(BT_ * (D_ / 4)) / 256, 256>>>(x, xhi, xlo);          // 2
    gt_kernel<<<BT_ / 4, 128>>>(x, Wgt, gt);                             // 3
    cumsum_kernel<<<B_ * H_ * NCH_, 256>>>(gt, gc);                      // 4
    tc_gemm<<<ggrid4, 128, TCG_SMEM>>>(xhi, xlo, wthi, wtlo, q, k, v, g, cosb, sinb); // 5
    sin_kernel<<<B_ * H_ * NCH_, 256>>>(k, v, gc, sbuf);                 // 6 <- ncu
    scan_kernel<<<B_ * H_ * 8, 256>>>(sbuf, gc, spre);
    out_kernel<<<B_ * H_ * NCH_ * 4, 256, SMF_TOT * sizeof(float)>>>(q, k, v, g, gc, spre, ohi, olo);
    tc_gemm<<<ggrid1, 128, TCG_SMEM>>>(ohi, olo, wthi + 4 * WSZ, wtlo + 4 * WSZ,
                                       out, out, out, out, nullptr, nullptr);
}